// round 4
// baseline (speedup 1.0000x reference)
#include <cuda_runtime.h>
#include <math.h>
#include <float.h>

#define B_   2
#define S_   2048
#define D_   1024
#define H_   16
#define DK_  64
#define MTOK (B_*S_)   // 4096

// Scratch (allocation-free rule: __device__ globals)
__device__ float g_q[MTOK * D_];
__device__ float g_k[MTOK * D_];
__device__ float g_v[MTOK * D_];
__device__ float g_ctx[MTOK * D_];
__device__ float g_p[B_ * H_ * S_ * S_];   // 512 MB scores/probs

// ---------------------------------------------------------------------------
// C[M,N] = A[M,K] @ W[N,K]^T + bias[N]
// 64x64 block tile, 256 threads, 4x4 per-thread micro-tile, k-tiles of 16.
// ---------------------------------------------------------------------------
__global__ __launch_bounds__(256) void gemm_bias_kernel(
    const float* __restrict__ A, const float* __restrict__ W,
    const float* __restrict__ bias, float* __restrict__ C,
    int M, int N, int K)
{
    __shared__ float As[64][17];
    __shared__ float Bs[16][65];
    const int tid = threadIdx.x;
    const int tx = tid & 15, ty = tid >> 4;
    const int m0 = blockIdx.y << 6, n0 = blockIdx.x << 6;

    float acc[4][4] = {};
    for (int kt = 0; kt < K; kt += 16) {
#pragma unroll
        for (int l = 0; l < 4; ++l) {
            int idx = tid + l * 256;
            int i = idx >> 4, kk = idx & 15;
            As[i][kk] = A[(size_t)(m0 + i) * K + kt + kk];
            Bs[kk][i] = W[(size_t)(n0 + i) * K + kt + kk];
        }
        __syncthreads();
#pragma unroll
        for (int kk = 0; kk < 16; ++kk) {
            float a[4], b[4];
#pragma unroll
            for (int r = 0; r < 4; ++r) a[r] = As[ty * 4 + r][kk];
#pragma unroll
            for (int c = 0; c < 4; ++c) b[c] = Bs[kk][tx * 4 + c];
#pragma unroll
            for (int r = 0; r < 4; ++r)
#pragma unroll
                for (int c = 0; c < 4; ++c)
                    acc[r][c] = fmaf(a[r], b[c], acc[r][c]);
        }
        __syncthreads();
    }
#pragma unroll
    for (int r = 0; r < 4; ++r) {
        int m = m0 + ty * 4 + r;
#pragma unroll
        for (int c = 0; c < 4; ++c) {
            int n = n0 + tx * 4 + c;
            C[(size_t)m * N + n] = acc[r][c] + bias[n];
        }
    }
}

// ---------------------------------------------------------------------------
// scores[bh][q][k] = (Q_h[q,:] . K_h[k,:]) * 1/8, masked to -10000 where mask==0
// grid: (S/64 key-tiles, S/64 query-tiles, B*H)
// ---------------------------------------------------------------------------
__global__ __launch_bounds__(256) void scores_kernel(const int* __restrict__ mask)
{
    const int k0 = blockIdx.x << 6, q0 = blockIdx.y << 6, bh = blockIdx.z;
    const int b = bh >> 4, h = bh & 15;
    const float* Qh = g_q + (size_t)b * S_ * D_ + h * DK_;
    const float* Kh = g_k + (size_t)b * S_ * D_ + h * DK_;
    float* P = g_p + (size_t)bh * S_ * S_;

    __shared__ float As[64][17];
    __shared__ float Bs[16][65];
    const int tid = threadIdx.x;
    const int tx = tid & 15, ty = tid >> 4;

    float acc[4][4] = {};
    for (int kd = 0; kd < DK_; kd += 16) {
#pragma unroll
        for (int l = 0; l < 4; ++l) {
            int idx = tid + l * 256;
            int i = idx >> 4, kk = idx & 15;
            As[i][kk] = Qh[(size_t)(q0 + i) * D_ + kd + kk];
            Bs[kk][i] = Kh[(size_t)(k0 + i) * D_ + kd + kk];
        }
        __syncthreads();
#pragma unroll
        for (int kk = 0; kk < 16; ++kk) {
            float a[4], bb[4];
#pragma unroll
            for (int r = 0; r < 4; ++r) a[r] = As[ty * 4 + r][kk];
#pragma unroll
            for (int c = 0; c < 4; ++c) bb[c] = Bs[kk][tx * 4 + c];
#pragma unroll
            for (int r = 0; r < 4; ++r)
#pragma unroll
                for (int c = 0; c < 4; ++c)
                    acc[r][c] = fmaf(a[r], bb[c], acc[r][c]);
        }
        __syncthreads();
    }
#pragma unroll
    for (int r = 0; r < 4; ++r) {
        int q = q0 + ty * 4 + r;
#pragma unroll
        for (int c = 0; c < 4; ++c) {
            int k = k0 + tx * 4 + c;
            float s = acc[r][c] * 0.125f;       // 1/sqrt(64)
            if (mask[b * S_ + k] == 0) s = -10000.0f;
            P[(size_t)q * S_ + k] = s;
        }
    }
}

// ---------------------------------------------------------------------------
// Row softmax over the key dim (S=2048). One block per (bh, q) row.
// ---------------------------------------------------------------------------
__global__ __launch_bounds__(256) void softmax_kernel()
{
    float* row = g_p + (size_t)blockIdx.x * S_;
    const int tid = threadIdx.x;
    __shared__ float red[256];

    float v[8];
    float m = -FLT_MAX;
#pragma unroll
    for (int j = 0; j < 8; ++j) {
        v[j] = row[tid + j * 256];
        m = fmaxf(m, v[j]);
    }
    red[tid] = m; __syncthreads();
    for (int s = 128; s > 0; s >>= 1) {
        if (tid < s) red[tid] = fmaxf(red[tid], red[tid + s]);
        __syncthreads();
    }
    m = red[0]; __syncthreads();

    float sum = 0.0f;
#pragma unroll
    for (int j = 0; j < 8; ++j) {
        v[j] = __expf(v[j] - m);
        sum += v[j];
    }
    red[tid] = sum; __syncthreads();
    for (int s = 128; s > 0; s >>= 1) {
        if (tid < s) red[tid] += red[tid + s];
        __syncthreads();
    }
    float inv = 1.0f / red[0];
#pragma unroll
    for (int j = 0; j < 8; ++j) row[tid + j * 256] = v[j] * inv;
}

// ---------------------------------------------------------------------------
// ctx[b,q,h*64+d] = sum_k P[bh][q][k] * V_h[k][d]
// grid: (S/64 query-tiles, B*H)
// ---------------------------------------------------------------------------
__global__ __launch_bounds__(256) void attnv_kernel()
{
    const int q0 = blockIdx.x << 6, bh = blockIdx.y;
    const int b = bh >> 4, h = bh & 15;
    const float* P  = g_p + (size_t)bh * S_ * S_;
    const float* Vh = g_v   + (size_t)b * S_ * D_ + h * DK_;
    float*       O  = g_ctx + (size_t)b * S_ * D_ + h * DK_;

    __shared__ float As[64][17];
    __shared__ float Bs[16][65];
    const int tid = threadIdx.x;
    const int tx = tid & 15, ty = tid >> 4;

    float acc[4][4] = {};
    for (int kt = 0; kt < S_; kt += 16) {
#pragma unroll
        for (int l = 0; l < 4; ++l) {
            int idx = tid + l * 256;
            int i = idx >> 4, kk = idx & 15;
            As[i][kk] = P[(size_t)(q0 + i) * S_ + kt + kk];
            int kv = idx >> 6, j = idx & 63;
            Bs[kv][j] = Vh[(size_t)(kt + kv) * D_ + j];
        }
        __syncthreads();
#pragma unroll
        for (int kk = 0; kk < 16; ++kk) {
            float a[4], bb[4];
#pragma unroll
            for (int r = 0; r < 4; ++r) a[r] = As[ty * 4 + r][kk];
#pragma unroll
            for (int c = 0; c < 4; ++c) bb[c] = Bs[kk][tx * 4 + c];
#pragma unroll
            for (int r = 0; r < 4; ++r)
#pragma unroll
                for (int c = 0; c < 4; ++c)
                    acc[r][c] = fmaf(a[r], bb[c], acc[r][c]);
        }
        __syncthreads();
    }
#pragma unroll
    for (int r = 0; r < 4; ++r) {
        int q = q0 + ty * 4 + r;
#pragma unroll
        for (int c = 0; c < 4; ++c)
            O[(size_t)q * D_ + tx * 4 + c] = acc[r][c];
    }
}

// ---------------------------------------------------------------------------
extern "C" void kernel_launch(void* const* d_in, const int* in_sizes, int n_in,
                              void* d_out, int out_size)
{
    const float* query = (const float*)d_in[0];
    const float* key   = (const float*)d_in[1];
    const float* value = (const float*)d_in[2];
    const int*   mask  = (const int*)d_in[3];
    const float* Wq = (const float*)d_in[4];  const float* bq = (const float*)d_in[5];
    const float* Wk = (const float*)d_in[6];  const float* bk = (const float*)d_in[7];
    const float* Wv = (const float*)d_in[8];  const float* bv = (const float*)d_in[9];
    const float* Wo = (const float*)d_in[10]; const float* bo = (const float*)d_in[11];
    float* out = (float*)d_out;

    float *gq, *gk, *gv, *gctx;
    cudaGetSymbolAddress((void**)&gq,   g_q);
    cudaGetSymbolAddress((void**)&gk,   g_k);
    cudaGetSymbolAddress((void**)&gv,   g_v);
    cudaGetSymbolAddress((void**)&gctx, g_ctx);

    dim3 gproj(D_ / 64, MTOK / 64);   // (16, 64)
    gemm_bias_kernel<<<gproj, 256>>>(query, Wq, bq, gq, MTOK, D_, D_);
    gemm_bias_kernel<<<gproj, 256>>>(key,   Wk, bk, gk, MTOK, D_, D_);
    gemm_bias_kernel<<<gproj, 256>>>(value, Wv, bv, gv, MTOK, D_, D_);

    scores_kernel<<<dim3(S_ / 64, S_ / 64, B_ * H_), 256>>>(mask);
    softmax_kernel<<<B_ * H_ * S_, 256>>>();
    attnv_kernel<<<dim3(S_ / 64, B_ * H_), 256>>>();

    gemm_bias_kernel<<<gproj, 256>>>(gctx, Wo, bo, out, MTOK, D_, D_);
}

// round 5
// speedup vs baseline: 2.3728x; 2.3728x over previous
#include <cuda_runtime.h>
#include <cuda_bf16.h>
#include <stdint.h>
#include <math.h>

#define B_   2
#define S_   2048
#define D_   1024
#define H_   16
#define DK_  64
#define MTOK (B_*S_)      // 4096
#define BH_  (B_*H_)      // 32
#define BKP  40           // padded smem k-stride (bf16): 80B rows, conflict-free frags

typedef __nv_bfloat16 bf16;

// ------------------------- scratch (__device__ globals) ---------------------
__device__ bf16 g_tq_hi[MTOK*D_], g_tq_lo[MTOK*D_];
__device__ bf16 g_tk_hi[MTOK*D_], g_tk_lo[MTOK*D_];
__device__ bf16 g_tv_hi[MTOK*D_], g_tv_lo[MTOK*D_];
__device__ bf16 g_wq_hi[D_*D_],  g_wq_lo[D_*D_];
__device__ bf16 g_wk_hi[D_*D_],  g_wk_lo[D_*D_];
__device__ bf16 g_wv_hi[D_*D_],  g_wv_lo[D_*D_];
__device__ bf16 g_wo_hi[D_*D_],  g_wo_lo[D_*D_];
__device__ bf16 g_q_hi[MTOK*D_], g_q_lo[MTOK*D_];   // Q proj, pre-scaled 1/8
__device__ bf16 g_k_hi[MTOK*D_], g_k_lo[MTOK*D_];
__device__ bf16 g_vt_hi[MTOK*D_], g_vt_lo[MTOK*D_]; // V proj, [bh][d][s]
__device__ bf16 g_c_hi[MTOK*D_], g_c_lo[MTOK*D_];   // context
__device__ bf16 g_p_hi[134217728];                  // BH*S*S unnormalized probs
__device__ bf16 g_p_lo[134217728];
__device__ float g_lpart[64 * BH_ * S_];
__device__ float g_l[BH_ * S_];

// ------------------------------- helpers ------------------------------------
__device__ __forceinline__ void cp16(void* smem, const void* g) {
    uint32_t s = (uint32_t)__cvta_generic_to_shared(smem);
    asm volatile("cp.async.cg.shared.global [%0], [%1], 16;\n" :: "r"(s), "l"(g));
}
#define CP_COMMIT asm volatile("cp.async.commit_group;\n")
#define CP_WAIT0  asm volatile("cp.async.wait_group 0;\n")

__device__ __forceinline__ void mma_bf16(float c[4],
    const uint32_t a[4], const uint32_t b[2])
{
    asm volatile(
        "mma.sync.aligned.m16n8k16.row.col.f32.bf16.bf16.f32 "
        "{%0,%1,%2,%3}, {%4,%5,%6,%7}, {%8,%9}, {%0,%1,%2,%3};\n"
        : "+f"(c[0]), "+f"(c[1]), "+f"(c[2]), "+f"(c[3])
        : "r"(a[0]), "r"(a[1]), "r"(a[2]), "r"(a[3]), "r"(b[0]), "r"(b[1]));
}

__device__ __forceinline__ void split_store(float v, bf16* hi, bf16* lo, size_t i)
{
    bf16 h = __float2bfloat16(v);
    hi[i] = h;
    lo[i] = __float2bfloat16(v - __bfloat162float(h));
}

// stage a 128-row x 32-k hi/lo tile (256 threads)
__device__ __forceinline__ void stage128(bf16* dh, bf16* dl,
    const bf16* Sh, const bf16* Sl, size_t stride, int r0, int kt, int srow, int sch)
{
    size_t a0 = (size_t)(r0 + srow)      * stride + kt + sch;
    size_t a1 = (size_t)(r0 + srow + 64) * stride + kt + sch;
    cp16(dh +  srow      * BKP + sch, Sh + a0);
    cp16(dh + (srow + 64) * BKP + sch, Sh + a1);
    cp16(dl +  srow      * BKP + sch, Sl + a0);
    cp16(dl + (srow + 64) * BKP + sch, Sl + a1);
}
// stage a 64-row x 32-k hi/lo tile
__device__ __forceinline__ void stage64(bf16* dh, bf16* dl,
    const bf16* Sh, const bf16* Sl, size_t stride, int r0, int kt, int srow, int sch)
{
    size_t a0 = (size_t)(r0 + srow) * stride + kt + sch;
    cp16(dh + srow * BKP + sch, Sh + a0);
    cp16(dl + srow * BKP + sch, Sl + a0);
}

// 32-deep k step: MT m-frags x 4 n-frags, 3-pass split mma
template<int MT>
__device__ __forceinline__ void mma_tile(const bf16* ah, const bf16* al,
    const bf16* bh, const bf16* bl, int wm, int wn, int g, int t,
    float (*acc)[4][4])
{
    #pragma unroll
    for (int kk = 0; kk < 32; kk += 16) {
        uint32_t aH[MT][4], aL[MT][4], bH[4][2], bL[4][2];
        #pragma unroll
        for (int mt = 0; mt < MT; ++mt) {
            int base = (wm + mt*16 + g) * BKP + kk + 2*t;
            aH[mt][0] = *(const uint32_t*)(ah + base);
            aH[mt][1] = *(const uint32_t*)(ah + base + 8*BKP);
            aH[mt][2] = *(const uint32_t*)(ah + base + 8);
            aH[mt][3] = *(const uint32_t*)(ah + base + 8*BKP + 8);
            aL[mt][0] = *(const uint32_t*)(al + base);
            aL[mt][1] = *(const uint32_t*)(al + base + 8*BKP);
            aL[mt][2] = *(const uint32_t*)(al + base + 8);
            aL[mt][3] = *(const uint32_t*)(al + base + 8*BKP + 8);
        }
        #pragma unroll
        for (int nt = 0; nt < 4; ++nt) {
            int base = (wn + nt*8 + g) * BKP + kk + 2*t;
            bH[nt][0] = *(const uint32_t*)(bh + base);
            bH[nt][1] = *(const uint32_t*)(bh + base + 8);
            bL[nt][0] = *(const uint32_t*)(bl + base);
            bL[nt][1] = *(const uint32_t*)(bl + base + 8);
        }
        #pragma unroll
        for (int mt = 0; mt < MT; ++mt)
            #pragma unroll
            for (int nt = 0; nt < 4; ++nt) {
                mma_bf16(acc[mt][nt], aH[mt], bH[nt]);
                mma_bf16(acc[mt][nt], aH[mt], bL[nt]);
                mma_bf16(acc[mt][nt], aL[mt], bH[nt]);
            }
    }
}

// ------------------------------- kernels ------------------------------------
__global__ __launch_bounds__(256) void split_kernel(
    const float* __restrict__ x, bf16* __restrict__ hi, bf16* __restrict__ lo, int n)
{
    int i = blockIdx.x * 256 + threadIdx.x;
    if (i < n) {
        float v = x[i];
        bf16 h = __float2bfloat16(v);
        hi[i] = h;
        lo[i] = __float2bfloat16(v - __bfloat162float(h));
    }
}

// C[4096,1024] = A @ W^T + bias.  mode 0: split bf16 (scaled); 1: fp32; 2: split V-transposed
__global__ __launch_bounds__(256) void proj_kernel(
    const bf16* __restrict__ Ahi, const bf16* __restrict__ Alo,
    const bf16* __restrict__ Whi, const bf16* __restrict__ Wlo,
    const float* __restrict__ bias, const float scale, const int mode,
    bf16* __restrict__ Ohi, bf16* __restrict__ Olo, float* __restrict__ Of)
{
    extern __shared__ bf16 sm[];
    #define TA(buf,hl) (sm + ((buf)*2 + (hl)) * (128*BKP))
    #define TB(buf,hl) (sm + (4 + (buf)*2 + (hl)) * (128*BKP))
    const int tid = threadIdx.x, lane = tid & 31, wid = tid >> 5;
    const int g = lane >> 2, t = lane & 3;
    const int wm = (wid >> 2) * 64, wn = (wid & 3) * 32;
    const int m0 = blockIdx.y * 128, n0 = blockIdx.x * 128;
    const int srow = tid >> 2, sch = (tid & 3) * 8;

    float acc[4][4][4] = {};
    stage128(TA(0,0), TA(0,1), Ahi, Alo, D_, m0, 0, srow, sch);
    stage128(TB(0,0), TB(0,1), Whi, Wlo, D_, n0, 0, srow, sch);
    CP_COMMIT;

    for (int kt = 0; kt < D_; kt += 32) {
        const int cur = (kt >> 5) & 1;
        CP_WAIT0; __syncthreads();
        if (kt + 32 < D_) {
            stage128(TA(cur^1,0), TA(cur^1,1), Ahi, Alo, D_, m0, kt + 32, srow, sch);
            stage128(TB(cur^1,0), TB(cur^1,1), Whi, Wlo, D_, n0, kt + 32, srow, sch);
            CP_COMMIT;
        }
        mma_tile<4>(TA(cur,0), TA(cur,1), TB(cur,0), TB(cur,1), wm, wn, g, t, acc);
    }

    #pragma unroll
    for (int mt = 0; mt < 4; ++mt) {
        int row0 = m0 + wm + mt*16 + g;
        #pragma unroll
        for (int nt = 0; nt < 4; ++nt) {
            int col = n0 + wn + nt*8 + 2*t;
            float v[4];
            v[0] = (acc[mt][nt][0] + bias[col])   * scale;
            v[1] = (acc[mt][nt][1] + bias[col+1]) * scale;
            v[2] = (acc[mt][nt][2] + bias[col])   * scale;
            v[3] = (acc[mt][nt][3] + bias[col+1]) * scale;
            if (mode == 0) {
                size_t i0 = (size_t)row0 * D_ + col, i1 = (size_t)(row0+8) * D_ + col;
                split_store(v[0], Ohi, Olo, i0);   split_store(v[1], Ohi, Olo, i0+1);
                split_store(v[2], Ohi, Olo, i1);   split_store(v[3], Ohi, Olo, i1+1);
            } else if (mode == 1) {
                size_t i0 = (size_t)row0 * D_ + col, i1 = (size_t)(row0+8) * D_ + col;
                Of[i0] = v[0]; Of[i0+1] = v[1]; Of[i1] = v[2]; Of[i1+1] = v[3];
            } else {  // V transposed: [bh][d][s], bh = (row>>11)*16 + col>>6
                #pragma unroll
                for (int e = 0; e < 4; ++e) {
                    int row = row0 + (e >> 1) * 8, c = col + (e & 1);
                    size_t i = (((size_t)(row >> 11) * 16 + (c >> 6)) * 64 + (c & 63)) * S_
                             + (row & (S_-1));
                    split_store(v[e], Ohi, Olo, i);
                }
            }
        }
    }
    #undef TA
    #undef TB
}

// P'[bh][q][k] = exp(Qs.K) masked->0, split store + partial row sums
__global__ __launch_bounds__(256) void scores_kernel(const int* __restrict__ mask)
{
    extern __shared__ bf16 sm[];
    #define TA(buf,hl) (sm + ((buf)*2 + (hl)) * (128*BKP))
    #define TB(buf,hl) (sm + (4 + (buf)*2 + (hl)) * (128*BKP))
    const int bh = blockIdx.z, b = bh >> 4, h = bh & 15;
    const size_t head = (size_t)b * S_ * D_ + (size_t)h * DK_;
    const bf16 *Ahi = g_q_hi + head, *Alo = g_q_lo + head;
    const bf16 *Bhi = g_k_hi + head, *Blo = g_k_lo + head;
    const int tid = threadIdx.x, lane = tid & 31, wid = tid >> 5;
    const int g = lane >> 2, t = lane & 3;
    const int wm = (wid >> 2) * 64, wn = (wid & 3) * 32;
    const int m0 = blockIdx.y * 128, n0 = blockIdx.x * 128;
    const int srow = tid >> 2, sch = (tid & 3) * 8;

    float acc[4][4][4] = {};
    stage128(TA(0,0), TA(0,1), Ahi, Alo, D_, m0, 0, srow, sch);
    stage128(TB(0,0), TB(0,1), Bhi, Blo, D_, n0, 0, srow, sch);
    CP_COMMIT;
    for (int kt = 0; kt < DK_; kt += 32) {
        const int cur = (kt >> 5) & 1;
        CP_WAIT0; __syncthreads();
        if (kt + 32 < DK_) {
            stage128(TA(cur^1,0), TA(cur^1,1), Ahi, Alo, D_, m0, kt + 32, srow, sch);
            stage128(TB(cur^1,0), TB(cur^1,1), Bhi, Blo, D_, n0, kt + 32, srow, sch);
            CP_COMMIT;
        }
        mma_tile<4>(TA(cur,0), TA(cur,1), TB(cur,0), TB(cur,1), wm, wn, g, t, acc);
    }

    bf16* Phi = g_p_hi + (size_t)bh * S_ * S_;
    bf16* Plo = g_p_lo + (size_t)bh * S_ * S_;
    const int slice = blockIdx.x * 4 + (wid & 3);
    #pragma unroll
    for (int mt = 0; mt < 4; ++mt) {
        int row0 = m0 + wm + mt*16 + g;
        float sum0 = 0.f, sum1 = 0.f;
        #pragma unroll
        for (int nt = 0; nt < 4; ++nt) {
            int col = n0 + wn + nt*8 + 2*t;
            bool mk0 = mask[b * S_ + col] != 0, mk1 = mask[b * S_ + col + 1] != 0;
            float p00 = mk0 ? __expf(acc[mt][nt][0]) : 0.f;
            float p01 = mk1 ? __expf(acc[mt][nt][1]) : 0.f;
            float p10 = mk0 ? __expf(acc[mt][nt][2]) : 0.f;
            float p11 = mk1 ? __expf(acc[mt][nt][3]) : 0.f;
            sum0 += p00 + p01;  sum1 += p10 + p11;
            size_t i0 = (size_t)row0 * S_ + col, i1 = (size_t)(row0+8) * S_ + col;
            split_store(p00, Phi, Plo, i0);   split_store(p01, Phi, Plo, i0+1);
            split_store(p10, Phi, Plo, i1);   split_store(p11, Phi, Plo, i1+1);
        }
        sum0 += __shfl_xor_sync(~0u, sum0, 1);  sum0 += __shfl_xor_sync(~0u, sum0, 2);
        sum1 += __shfl_xor_sync(~0u, sum1, 1);  sum1 += __shfl_xor_sync(~0u, sum1, 2);
        if (t == 0) {
            g_lpart[(size_t)slice * (BH_*S_) + bh * S_ + row0]     = sum0;
            g_lpart[(size_t)slice * (BH_*S_) + bh * S_ + row0 + 8] = sum1;
        }
    }
    #undef TA
    #undef TB
}

__global__ __launch_bounds__(256) void reduce_l_kernel()
{
    int i = blockIdx.x * 256 + threadIdx.x;
    float s = 0.f;
    #pragma unroll
    for (int j = 0; j < 64; ++j) s += g_lpart[(size_t)j * (BH_*S_) + i];
    g_l[i] = s;
}

// ctx = (P' @ V) / l  via transposed V.  128x64 tile, warps 4m x 2n.
__global__ __launch_bounds__(256) void attnv_kernel()
{
    extern __shared__ bf16 sm[];
    #define TA(buf,hl) (sm + ((buf)*2 + (hl)) * (128*BKP))
    #define TB(buf,hl) (sm + 4*(128*BKP) + ((buf)*2 + (hl)) * (64*BKP))
    const int bh = blockIdx.y, b = bh >> 4, h = bh & 15;
    const int m0 = blockIdx.x * 128;
    const bf16 *Phi = g_p_hi + (size_t)bh * S_ * S_, *Plo = g_p_lo + (size_t)bh * S_ * S_;
    const bf16 *Vhi = g_vt_hi + (size_t)bh * 64 * S_, *Vlo = g_vt_lo + (size_t)bh * 64 * S_;
    const int tid = threadIdx.x, lane = tid & 31, wid = tid >> 5;
    const int g = lane >> 2, t = lane & 3;
    const int wm = (wid >> 1) * 32, wn = (wid & 1) * 32;
    const int srow = tid >> 2, sch = (tid & 3) * 8;

    float acc[2][4][4] = {};
    stage128(TA(0,0), TA(0,1), Phi, Plo, S_, m0, 0, srow, sch);
    if (srow < 64) stage64(TB(0,0), TB(0,1), Vhi, Vlo, S_, 0, 0, srow, sch);
    CP_COMMIT;
    for (int kt = 0; kt < S_; kt += 32) {
        const int cur = (kt >> 5) & 1;
        CP_WAIT0; __syncthreads();
        if (kt + 32 < S_) {
            stage128(TA(cur^1,0), TA(cur^1,1), Phi, Plo, S_, m0, kt + 32, srow, sch);
            if (srow < 64) stage64(TB(cur^1,0), TB(cur^1,1), Vhi, Vlo, S_, 0, kt + 32, srow, sch);
            CP_COMMIT;
        }
        mma_tile<2>(TA(cur,0), TA(cur,1), TB(cur,0), TB(cur,1), wm, wn, g, t, acc);
    }

    #pragma unroll
    for (int mt = 0; mt < 2; ++mt) {
        int row0 = m0 + wm + mt*16 + g;
        float inv0 = 1.f / g_l[bh * S_ + row0];
        float inv1 = 1.f / g_l[bh * S_ + row0 + 8];
        #pragma unroll
        for (int nt = 0; nt < 4; ++nt) {
            int d = wn + nt*8 + 2*t;
            size_t i0 = (size_t)(b * S_ + row0)     * D_ + h * DK_ + d;
            size_t i1 = (size_t)(b * S_ + row0 + 8) * D_ + h * DK_ + d;
            split_store(acc[mt][nt][0] * inv0, g_c_hi, g_c_lo, i0);
            split_store(acc[mt][nt][1] * inv0, g_c_hi, g_c_lo, i0+1);
            split_store(acc[mt][nt][2] * inv1, g_c_hi, g_c_lo, i1);
            split_store(acc[mt][nt][3] * inv1, g_c_hi, g_c_lo, i1+1);
        }
    }
    #undef TA
    #undef TB
}

// ------------------------------- launch -------------------------------------
extern "C" void kernel_launch(void* const* d_in, const int* in_sizes, int n_in,
                              void* d_out, int out_size)
{
    const float* query = (const float*)d_in[0];
    const float* key   = (const float*)d_in[1];
    const float* value = (const float*)d_in[2];
    const int*   mask  = (const int*)d_in[3];
    const float* Wq = (const float*)d_in[4];  const float* bq = (const float*)d_in[5];
    const float* Wk = (const float*)d_in[6];  const float* bk = (const float*)d_in[7];
    const float* Wv = (const float*)d_in[8];  const float* bv = (const float*)d_in[9];
    const float* Wo = (const float*)d_in[10]; const float* bo = (const float*)d_in[11];
    float* out = (float*)d_out;

    const int GEMM_SMEM  = 8 * 128 * BKP * 2;                    // 81920 B
    const int ATTNV_SMEM = (4*128*BKP + 4*64*BKP) * 2;           // 61440 B
    static int done = 0;
    cudaFuncSetAttribute(proj_kernel,   cudaFuncAttributeMaxDynamicSharedMemorySize, GEMM_SMEM);
    cudaFuncSetAttribute(scores_kernel, cudaFuncAttributeMaxDynamicSharedMemorySize, GEMM_SMEM);
    cudaFuncSetAttribute(attnv_kernel,  cudaFuncAttributeMaxDynamicSharedMemorySize, ATTNV_SMEM);
    (void)done;

    bf16 *tqh,*tql,*tkh,*tkl,*tvh,*tvl,*wqh,*wql,*wkh,*wkl,*wvh,*wvl,*woh,*wol;
    bf16 *qh,*ql,*kh,*kl,*vth,*vtl,*ch,*cl;
    cudaGetSymbolAddress((void**)&tqh, g_tq_hi); cudaGetSymbolAddress((void**)&tql, g_tq_lo);
    cudaGetSymbolAddress((void**)&tkh, g_tk_hi); cudaGetSymbolAddress((void**)&tkl, g_tk_lo);
    cudaGetSymbolAddress((void**)&tvh, g_tv_hi); cudaGetSymbolAddress((void**)&tvl, g_tv_lo);
    cudaGetSymbolAddress((void**)&wqh, g_wq_hi); cudaGetSymbolAddress((void**)&wql, g_wq_lo);
    cudaGetSymbolAddress((void**)&wkh, g_wk_hi); cudaGetSymbolAddress((void**)&wkl, g_wk_lo);
    cudaGetSymbolAddress((void**)&wvh, g_wv_hi); cudaGetSymbolAddress((void**)&wvl, g_wv_lo);
    cudaGetSymbolAddress((void**)&woh, g_wo_hi); cudaGetSymbolAddress((void**)&wol, g_wo_lo);
    cudaGetSymbolAddress((void**)&qh,  g_q_hi);  cudaGetSymbolAddress((void**)&ql,  g_q_lo);
    cudaGetSymbolAddress((void**)&kh,  g_k_hi);  cudaGetSymbolAddress((void**)&kl,  g_k_lo);
    cudaGetSymbolAddress((void**)&vth, g_vt_hi); cudaGetSymbolAddress((void**)&vtl, g_vt_lo);
    cudaGetSymbolAddress((void**)&ch,  g_c_hi);  cudaGetSymbolAddress((void**)&cl,  g_c_lo);

    const int NT = MTOK * D_, NW = D_ * D_;
    split_kernel<<<NT/256, 256>>>(query, tqh, tql, NT);
    split_kernel<<<NT/256, 256>>>(key,   tkh, tkl, NT);
    split_kernel<<<NT/256, 256>>>(value, tvh, tvl, NT);
    split_kernel<<<NW/256, 256>>>(Wq, wqh, wql, NW);
    split_kernel<<<NW/256, 256>>>(Wk, wkh, wkl, NW);
    split_kernel<<<NW/256, 256>>>(Wv, wvh, wvl, NW);
    split_kernel<<<NW/256, 256>>>(Wo, woh, wol, NW);

    dim3 gproj(D_/128, MTOK/128);   // (8, 32)
    proj_kernel<<<gproj, 256, GEMM_SMEM>>>(tqh, tql, wqh, wql, bq, 0.125f, 0, qh,  ql,  nullptr);
    proj_kernel<<<gproj, 256, GEMM_SMEM>>>(tkh, tkl, wkh, wkl, bk, 1.0f,   0, kh,  kl,  nullptr);
    proj_kernel<<<gproj, 256, GEMM_SMEM>>>(tvh, tvl, wvh, wvl, bv, 1.0f,   2, vth, vtl, nullptr);

    scores_kernel<<<dim3(S_/128, S_/128, BH_), 256, GEMM_SMEM>>>(mask);
    reduce_l_kernel<<<BH_*S_/256, 256>>>();
    attnv_kernel<<<dim3(S_/128, BH_), 256, ATTNV_SMEM>>>();

    proj_kernel<<<gproj, 256, GEMM_SMEM>>>(ch, cl, woh, wol, bo, 1.0f, 1, nullptr, nullptr, out);
}

// round 7
// speedup vs baseline: 3.4487x; 1.4534x over previous
#include <cuda_runtime.h>
#include <cuda_bf16.h>
#include <stdint.h>
#include <math.h>

#define B_   2
#define S_   2048
#define D_   1024
#define H_   16
#define DK_  64
#define MTOK (B_*S_)      // 4096
#define BH_  (B_*H_)      // 32
#define BKP  40           // proj smem k-stride

typedef __nv_bfloat16 bf16;

// ------------------------- scratch -------------------------
__device__ bf16 g_tq_hi[MTOK*D_], g_tq_lo[MTOK*D_];
__device__ bf16 g_tk_hi[MTOK*D_], g_tk_lo[MTOK*D_];
__device__ bf16 g_tv_hi[MTOK*D_], g_tv_lo[MTOK*D_];
__device__ bf16 g_wq_hi[D_*D_],  g_wq_lo[D_*D_];
__device__ bf16 g_wk_hi[D_*D_],  g_wk_lo[D_*D_];
__device__ bf16 g_wv_hi[D_*D_],  g_wv_lo[D_*D_];
__device__ bf16 g_wo_hi[D_*D_],  g_wo_lo[D_*D_];
__device__ bf16 g_q_hi[MTOK*D_], g_q_lo[MTOK*D_];   // Q proj, pre-scaled 1/8
__device__ bf16 g_k_hi[MTOK*D_], g_k_lo[MTOK*D_];
__device__ bf16 g_vt_hi[MTOK*D_], g_vt_lo[MTOK*D_]; // V proj, [bh][d][s]
__device__ bf16 g_c_hi[MTOK*D_], g_c_lo[MTOK*D_];   // context

// ------------------------- helpers -------------------------
__device__ __forceinline__ void cp16(void* smem, const void* g) {
    uint32_t s = (uint32_t)__cvta_generic_to_shared(smem);
    asm volatile("cp.async.cg.shared.global [%0], [%1], 16;\n" :: "r"(s), "l"(g));
}
#define CP_COMMIT asm volatile("cp.async.commit_group;\n")

__device__ __forceinline__ void mma_bf16(float c[4], const uint32_t a[4], const uint32_t b[2])
{
    asm volatile(
        "mma.sync.aligned.m16n8k16.row.col.f32.bf16.bf16.f32 "
        "{%0,%1,%2,%3}, {%4,%5,%6,%7}, {%8,%9}, {%0,%1,%2,%3};\n"
        : "+f"(c[0]), "+f"(c[1]), "+f"(c[2]), "+f"(c[3])
        : "r"(a[0]), "r"(a[1]), "r"(a[2]), "r"(a[3]), "r"(b[0]), "r"(b[1]));
}

__device__ __forceinline__ void split_store(float v, bf16* hi, bf16* lo, size_t i)
{
    bf16 h = __float2bfloat16(v);
    hi[i] = h;
    lo[i] = __float2bfloat16(v - __bfloat162float(h));
}

__device__ __forceinline__ void split2(float f0, float f1, uint32_t& hi, uint32_t& lo)
{
    __nv_bfloat162 hh, ll;
    hh.x = __float2bfloat16(f0);  hh.y = __float2bfloat16(f1);
    ll.x = __float2bfloat16(f0 - __bfloat162float(hh.x));
    ll.y = __float2bfloat16(f1 - __bfloat162float(hh.y));
    hi = *(uint32_t*)&hh;  lo = *(uint32_t*)&ll;
}

// proj staging: 128-row x 32-k hi/lo tile
__device__ __forceinline__ void stage128(bf16* dh, bf16* dl,
    const bf16* Sh, const bf16* Sl, size_t stride, int r0, int kt, int srow, int sch)
{
    size_t a0 = (size_t)(r0 + srow)      * stride + kt + sch;
    size_t a1 = (size_t)(r0 + srow + 64) * stride + kt + sch;
    cp16(dh +  srow      * BKP + sch, Sh + a0);
    cp16(dh + (srow + 64) * BKP + sch, Sh + a1);
    cp16(dl +  srow      * BKP + sch, Sl + a0);
    cp16(dl + (srow + 64) * BKP + sch, Sl + a1);
}

__device__ __forceinline__ void mma_tile4(const bf16* ah, const bf16* al,
    const bf16* bh, const bf16* bl, int wm, int wn, int g, int t, float (*acc)[4][4])
{
    #pragma unroll
    for (int kk = 0; kk < 32; kk += 16) {
        uint32_t aH[4][4], aL[4][4], bH[4][2], bL[4][2];
        #pragma unroll
        for (int mt = 0; mt < 4; ++mt) {
            int base = (wm + mt*16 + g) * BKP + kk + 2*t;
            aH[mt][0] = *(const uint32_t*)(ah + base);
            aH[mt][1] = *(const uint32_t*)(ah + base + 8*BKP);
            aH[mt][2] = *(const uint32_t*)(ah + base + 8);
            aH[mt][3] = *(const uint32_t*)(ah + base + 8*BKP + 8);
            aL[mt][0] = *(const uint32_t*)(al + base);
            aL[mt][1] = *(const uint32_t*)(al + base + 8*BKP);
            aL[mt][2] = *(const uint32_t*)(al + base + 8);
            aL[mt][3] = *(const uint32_t*)(al + base + 8*BKP + 8);
        }
        #pragma unroll
        for (int nt = 0; nt < 4; ++nt) {
            int base = (wn + nt*8 + g) * BKP + kk + 2*t;
            bH[nt][0] = *(const uint32_t*)(bh + base);
            bH[nt][1] = *(const uint32_t*)(bh + base + 8);
            bL[nt][0] = *(const uint32_t*)(bl + base);
            bL[nt][1] = *(const uint32_t*)(bl + base + 8);
        }
        #pragma unroll
        for (int mt = 0; mt < 4; ++mt)
            #pragma unroll
            for (int nt = 0; nt < 4; ++nt) {
                mma_bf16(acc[mt][nt], aH[mt], bH[nt]);
                mma_bf16(acc[mt][nt], aH[mt], bL[nt]);
                mma_bf16(acc[mt][nt], aL[mt], bH[nt]);
            }
    }
}

// ------------------------- kernels -------------------------
__global__ __launch_bounds__(256) void split_kernel(
    const float* __restrict__ x, bf16* __restrict__ hi, bf16* __restrict__ lo, int n)
{
    int i = blockIdx.x * 256 + threadIdx.x;
    if (i < n) {
        float v = x[i];
        bf16 h = __float2bfloat16(v);
        hi[i] = h;
        lo[i] = __float2bfloat16(v - __bfloat162float(h));
    }
}

// C[4096,1024] = A @ W^T + bias.  mode 0: split bf16 (scaled); 1: fp32 out; 2: split V-transposed
__global__ __launch_bounds__(256) void proj_kernel(
    const bf16* __restrict__ Ahi, const bf16* __restrict__ Alo,
    const bf16* __restrict__ Whi, const bf16* __restrict__ Wlo,
    const float* __restrict__ bias, const float scale, const int mode,
    bf16* __restrict__ Ohi, bf16* __restrict__ Olo, float* __restrict__ Of)
{
    extern __shared__ bf16 sm[];
    #define TA(buf,hl) (sm + ((buf)*2 + (hl)) * (128*BKP))
    #define TB(buf,hl) (sm + (4 + (buf)*2 + (hl)) * (128*BKP))
    const int tid = threadIdx.x, lane = tid & 31, wid = tid >> 5;
    const int g = lane >> 2, t = lane & 3;
    const int wm = (wid >> 2) * 64, wn = (wid & 3) * 32;
    const int m0 = blockIdx.y * 128, n0 = blockIdx.x * 128;
    const int srow = tid >> 2, sch = (tid & 3) * 8;

    float acc[4][4][4] = {};
    stage128(TA(0,0), TA(0,1), Ahi, Alo, D_, m0, 0, srow, sch);
    stage128(TB(0,0), TB(0,1), Whi, Wlo, D_, n0, 0, srow, sch);
    CP_COMMIT;

    for (int kt = 0; kt < D_; kt += 32) {
        const int cur = (kt >> 5) & 1;
        asm volatile("cp.async.wait_group 0;\n");
        __syncthreads();
        if (kt + 32 < D_) {
            stage128(TA(cur^1,0), TA(cur^1,1), Ahi, Alo, D_, m0, kt + 32, srow, sch);
            stage128(TB(cur^1,0), TB(cur^1,1), Whi, Wlo, D_, n0, kt + 32, srow, sch);
            CP_COMMIT;
        }
        mma_tile4(TA(cur,0), TA(cur,1), TB(cur,0), TB(cur,1), wm, wn, g, t, acc);
    }

    #pragma unroll
    for (int mt = 0; mt < 4; ++mt) {
        int row0 = m0 + wm + mt*16 + g;
        #pragma unroll
        for (int nt = 0; nt < 4; ++nt) {
            int col = n0 + wn + nt*8 + 2*t;
            float v[4];
            v[0] = (acc[mt][nt][0] + bias[col])   * scale;
            v[1] = (acc[mt][nt][1] + bias[col+1]) * scale;
            v[2] = (acc[mt][nt][2] + bias[col])   * scale;
            v[3] = (acc[mt][nt][3] + bias[col+1]) * scale;
            if (mode == 0) {
                size_t i0 = (size_t)row0 * D_ + col, i1 = (size_t)(row0+8) * D_ + col;
                split_store(v[0], Ohi, Olo, i0);   split_store(v[1], Ohi, Olo, i0+1);
                split_store(v[2], Ohi, Olo, i1);   split_store(v[3], Ohi, Olo, i1+1);
            } else if (mode == 1) {
                size_t i0 = (size_t)row0 * D_ + col, i1 = (size_t)(row0+8) * D_ + col;
                Of[i0] = v[0]; Of[i0+1] = v[1]; Of[i1] = v[2]; Of[i1+1] = v[3];
            } else {  // V transposed: [bh][d][s]
                #pragma unroll
                for (int e = 0; e < 4; ++e) {
                    int row = row0 + (e >> 1) * 8, c = col + (e & 1);
                    size_t i = (((size_t)(row >> 11) * 16 + (c >> 6)) * 64 + (c & 63)) * S_
                             + (row & (S_-1));
                    split_store(v[e], Ohi, Olo, i);
                }
            }
        }
    }
    #undef TA
    #undef TB
}

// ------------------------- flash attention -------------------------
// q-tile 64 rows per CTA; k streamed in 128-token chunks.
// smem bytes: Qs 18432 | Ks 73728 | Vs 69632 | mask 8192  = 169984
#define QHL  (64*72)
#define KHL  (128*72)
#define VHL  (64*136)
#define FLASH_SMEM 169984

__device__ __forceinline__ void stage_k(bf16* Ks, int buf, int b, int h, int kt, int kr, int kc)
{
    size_t gk = ((size_t)(b*S_ + kt + kr))*D_ + h*64 + kc;
    bf16* d = Ks + buf*(2*KHL) + kr*72 + kc;
    #pragma unroll
    for (int i = 0; i < 4; ++i) cp16(d + i*8, g_k_hi + gk + i*8);
    d += KHL;
    #pragma unroll
    for (int i = 0; i < 4; ++i) cp16(d + i*8, g_k_lo + gk + i*8);
}
__device__ __forceinline__ void stage_v(bf16* Vs, int buf, int bh, int kt, int vr, int vc)
{
    size_t gv = ((size_t)(bh*64 + vr))*S_ + kt + vc;
    bf16* d = Vs + buf*(2*VHL) + vr*136 + vc;
    #pragma unroll
    for (int i = 0; i < 4; ++i) cp16(d + i*8, g_vt_hi + gv + i*8);
    d += VHL;
    #pragma unroll
    for (int i = 0; i < 4; ++i) cp16(d + i*8, g_vt_lo + gv + i*8);
}

__global__ __launch_bounds__(256) void flash_kernel(const int* __restrict__ mask)
{
    extern __shared__ char smc[];
    bf16* Qs = (bf16*)smc;                 // [hl][64][72]
    bf16* Ks = (bf16*)(smc + 18432);       // [buf][hl][128][72]
    bf16* Vs = (bf16*)(smc + 92160);       // [buf][hl][64][136]
    int*  Ms = (int*)(smc + 161792);       // [2048]
    float* red   = (float*)smc;            // [4][64][68]  (post-loop reuse)
    float* lpart = (float*)(smc + 69632);  // [4][64]

    const int bh = blockIdx.y, b = bh >> 4, h = bh & 15;
    const int q0 = blockIdx.x * 64;
    const int tid = threadIdx.x, lane = tid & 31, wid = tid >> 5;
    const int g = lane >> 2, t = lane & 3;
    const int wm = (wid >> 2) * 32;     // 2 m-halves of 32 rows
    const int j  = wid & 3;             // k-slice owner (scores n-warp)
    const int wn = j * 32;

    const int qr = tid >> 2, qc = (tid & 3) * 16;
    const int kr = tid >> 1, kc = (tid & 1) * 32;
    const int vr = tid >> 2, vc = (tid & 3) * 32;

    // prologue: Q, K0, V0, mask
    {
        size_t gq = ((size_t)(b*S_ + q0 + qr))*D_ + h*64 + qc;
        cp16(Qs +       qr*72 + qc,     g_q_hi + gq);
        cp16(Qs +       qr*72 + qc + 8, g_q_hi + gq + 8);
        cp16(Qs + QHL + qr*72 + qc,     g_q_lo + gq);
        cp16(Qs + QHL + qr*72 + qc + 8, g_q_lo + gq + 8);
        stage_k(Ks, 0, b, h, 0, kr, kc);
        stage_v(Vs, 0, bh, 0, vr, vc);
        cp16(Ms + tid*8,     mask + b*S_ + tid*8);
        cp16(Ms + tid*8 + 4, mask + b*S_ + tid*8 + 4);
        CP_COMMIT;
    }

    float acc_o[2][8][4] = {};
    float ls[2][2] = {};

    for (int it = 0; it < 16; ++it) {
        const int cur = it & 1;
        if (it < 15) {
            stage_k(Ks, cur^1, b, h, (it+1)*128, kr, kc);
            stage_v(Vs, cur^1, bh, (it+1)*128, vr, vc);
            CP_COMMIT;
            asm volatile("cp.async.wait_group 1;\n");
        } else {
            asm volatile("cp.async.wait_group 0;\n");
        }
        __syncthreads();

        // ---- scores: Q[64x64] . K_chunk[128x64]^T, warp slice 32q x 32k ----
        float accs[2][4][4] = {};
        const bf16* kb = Ks + cur*(2*KHL);
        #pragma unroll
        for (int kk = 0; kk < 64; kk += 16) {
            uint32_t aH[2][4], aL[2][4], bH[4][2], bL[4][2];
            #pragma unroll
            for (int mt = 0; mt < 2; ++mt) {
                int base = (wm + mt*16 + g)*72 + kk + 2*t;
                aH[mt][0] = *(const uint32_t*)(Qs + base);
                aH[mt][1] = *(const uint32_t*)(Qs + base + 8*72);
                aH[mt][2] = *(const uint32_t*)(Qs + base + 8);
                aH[mt][3] = *(const uint32_t*)(Qs + base + 8*72 + 8);
                aL[mt][0] = *(const uint32_t*)(Qs + QHL + base);
                aL[mt][1] = *(const uint32_t*)(Qs + QHL + base + 8*72);
                aL[mt][2] = *(const uint32_t*)(Qs + QHL + base + 8);
                aL[mt][3] = *(const uint32_t*)(Qs + QHL + base + 8*72 + 8);
            }
            #pragma unroll
            for (int nt = 0; nt < 4; ++nt) {
                int bb = (wn + nt*8 + g)*72 + kk + 2*t;
                bH[nt][0] = *(const uint32_t*)(kb + bb);
                bH[nt][1] = *(const uint32_t*)(kb + bb + 8);
                bL[nt][0] = *(const uint32_t*)(kb + KHL + bb);
                bL[nt][1] = *(const uint32_t*)(kb + KHL + bb + 8);
            }
            #pragma unroll
            for (int mt = 0; mt < 2; ++mt)
                #pragma unroll
                for (int nt = 0; nt < 4; ++nt) {
                    mma_bf16(accs[mt][nt], aH[mt], bH[nt]);
                    mma_bf16(accs[mt][nt], aH[mt], bL[nt]);
                    mma_bf16(accs[mt][nt], aL[mt], bH[nt]);
                }
        }

        // ---- mask + exp + pack P acc -> A-frags ----
        uint32_t pH[2][2][4], pL[2][2][4];
        #pragma unroll
        for (int mt = 0; mt < 2; ++mt) {
            #pragma unroll
            for (int nt = 0; nt < 4; ++nt) {
                int c0 = it*128 + wn + nt*8 + 2*t;
                bool m0 = Ms[c0] != 0, m1 = Ms[c0+1] != 0;
                float p0 = m0 ? __expf(accs[mt][nt][0]) : 0.f;
                float p1 = m1 ? __expf(accs[mt][nt][1]) : 0.f;
                float p2 = m0 ? __expf(accs[mt][nt][2]) : 0.f;
                float p3 = m1 ? __expf(accs[mt][nt][3]) : 0.f;
                ls[mt][0] += p0 + p1;
                ls[mt][1] += p2 + p3;
                int jj = nt >> 1, hf = (nt & 1) * 2;
                split2(p0, p1, pH[mt][jj][hf],   pL[mt][jj][hf]);
                split2(p2, p3, pH[mt][jj][hf+1], pL[mt][jj][hf+1]);
            }
        }

        // ---- P_slice[32q x 32k] . V_chunk[32k x 64d] ----
        const bf16* vb = Vs + cur*(2*VHL);
        #pragma unroll
        for (int jj = 0; jj < 2; ++jj) {
            uint32_t bH[8][2], bL[8][2];
            #pragma unroll
            for (int dt = 0; dt < 8; ++dt) {
                int bb = (dt*8 + g)*136 + wn + jj*16 + 2*t;
                bH[dt][0] = *(const uint32_t*)(vb + bb);
                bH[dt][1] = *(const uint32_t*)(vb + bb + 8);
                bL[dt][0] = *(const uint32_t*)(vb + VHL + bb);
                bL[dt][1] = *(const uint32_t*)(vb + VHL + bb + 8);
            }
            #pragma unroll
            for (int mt = 0; mt < 2; ++mt)
                #pragma unroll
                for (int dt = 0; dt < 8; ++dt) {
                    mma_bf16(acc_o[mt][dt], pH[mt][jj], bH[dt]);
                    mma_bf16(acc_o[mt][dt], pH[mt][jj], bL[dt]);
                    mma_bf16(acc_o[mt][dt], pL[mt][jj], bH[dt]);
                }
        }
        __syncthreads();
    }

    // ---- cross-warp reduction over the 4 k-slices ----
    #pragma unroll
    for (int mt = 0; mt < 2; ++mt) {
        int r0 = wm + mt*16 + g;
        #pragma unroll
        for (int dt = 0; dt < 8; ++dt) {
            int c = dt*8 + 2*t;
            red[(j*64 + r0)*68 + c]       = acc_o[mt][dt][0];
            red[(j*64 + r0)*68 + c + 1]   = acc_o[mt][dt][1];
            red[(j*64 + r0+8)*68 + c]     = acc_o[mt][dt][2];
            red[(j*64 + r0+8)*68 + c + 1] = acc_o[mt][dt][3];
        }
        #pragma unroll
        for (int rr = 0; rr < 2; ++rr) {
            float s = ls[mt][rr];
            s += __shfl_xor_sync(~0u, s, 1);
            s += __shfl_xor_sync(~0u, s, 2);
            if (t == 0) lpart[j*64 + r0 + rr*8] = s;
        }
    }
    __syncthreads();

    #pragma unroll
    for (int i = 0; i < 16; ++i) {
        int e = i*256 + tid;
        int row = e >> 6, col = e & 63;
        float s = red[row*68 + col] + red[(64+row)*68 + col]
                + red[(128+row)*68 + col] + red[(192+row)*68 + col];
        float l = lpart[row] + lpart[64+row] + lpart[128+row] + lpart[192+row];
        float v = s / l;
        size_t o = ((size_t)(b*S_ + q0 + row))*D_ + h*64 + col;
        split_store(v, g_c_hi, g_c_lo, o);
    }
}

// ------------------------- launch -------------------------
extern "C" void kernel_launch(void* const* d_in, const int* in_sizes, int n_in,
                              void* d_out, int out_size)
{
    const float* query = (const float*)d_in[0];
    const float* key   = (const float*)d_in[1];
    const float* value = (const float*)d_in[2];
    const int*   mask  = (const int*)d_in[3];
    const float* Wq = (const float*)d_in[4];  const float* bq = (const float*)d_in[5];
    const float* Wk = (const float*)d_in[6];  const float* bk = (const float*)d_in[7];
    const float* Wv = (const float*)d_in[8];  const float* bv = (const float*)d_in[9];
    const float* Wo = (const float*)d_in[10]; const float* bo = (const float*)d_in[11];
    float* out = (float*)d_out;

    const int GEMM_SMEM = 8 * 128 * BKP * 2;   // 81920 B
    cudaFuncSetAttribute(proj_kernel,  cudaFuncAttributeMaxDynamicSharedMemorySize, GEMM_SMEM);
    cudaFuncSetAttribute(flash_kernel, cudaFuncAttributeMaxDynamicSharedMemorySize, FLASH_SMEM);

    bf16 *tqh,*tql,*tkh,*tkl,*tvh,*tvl,*wqh,*wql,*wkh,*wkl,*wvh,*wvl,*woh,*wol;
    bf16 *qh,*ql,*kh,*kl,*vth,*vtl,*ch,*cl;
    cudaGetSymbolAddress((void**)&tqh, g_tq_hi); cudaGetSymbolAddress((void**)&tql, g_tq_lo);
    cudaGetSymbolAddress((void**)&tkh, g_tk_hi); cudaGetSymbolAddress((void**)&tkl, g_tk_lo);
    cudaGetSymbolAddress((void**)&tvh, g_tv_hi); cudaGetSymbolAddress((void**)&tvl, g_tv_lo);
    cudaGetSymbolAddress((void**)&wqh, g_wq_hi); cudaGetSymbolAddress((void**)&wql, g_wq_lo);
    cudaGetSymbolAddress((void**)&wkh, g_wk_hi); cudaGetSymbolAddress((void**)&wkl, g_wk_lo);
    cudaGetSymbolAddress((void**)&wvh, g_wv_hi); cudaGetSymbolAddress((void**)&wvl, g_wv_lo);
    cudaGetSymbolAddress((void**)&woh, g_wo_hi); cudaGetSymbolAddress((void**)&wol, g_wo_lo);
    cudaGetSymbolAddress((void**)&qh,  g_q_hi);  cudaGetSymbolAddress((void**)&ql,  g_q_lo);
    cudaGetSymbolAddress((void**)&kh,  g_k_hi);  cudaGetSymbolAddress((void**)&kl,  g_k_lo);
    cudaGetSymbolAddress((void**)&vth, g_vt_hi); cudaGetSymbolAddress((void**)&vtl, g_vt_lo);
    cudaGetSymbolAddress((void**)&ch,  g_c_hi);  cudaGetSymbolAddress((void**)&cl,  g_c_lo);

    const int NT = MTOK * D_, NW = D_ * D_;
    split_kernel<<<NT/256, 256>>>(query, tqh, tql, NT);
    split_kernel<<<NT/256, 256>>>(key,   tkh, tkl, NT);
    split_kernel<<<NT/256, 256>>>(value, tvh, tvl, NT);
    split_kernel<<<NW/256, 256>>>(Wq, wqh, wql, NW);
    split_kernel<<<NW/256, 256>>>(Wk, wkh, wkl, NW);
    split_kernel<<<NW/256, 256>>>(Wv, wvh, wvl, NW);
    split_kernel<<<NW/256, 256>>>(Wo, woh, wol, NW);

    dim3 gproj(D_/128, MTOK/128);   // (8, 32)
    proj_kernel<<<gproj, 256, GEMM_SMEM>>>(tqh, tql, wqh, wql, bq, 0.125f, 0, qh,  ql,  nullptr);
    proj_kernel<<<gproj, 256, GEMM_SMEM>>>(tkh, tkl, wkh, wkl, bk, 1.0f,   0, kh,  kl,  nullptr);
    proj_kernel<<<gproj, 256, GEMM_SMEM>>>(tvh, tvl, wvh, wvl, bv, 1.0f,   2, vth, vtl, nullptr);

    flash_kernel<<<dim3(S_/64, BH_), 256, FLASH_SMEM>>>(mask);

    proj_kernel<<<gproj, 256, GEMM_SMEM>>>(ch, cl, woh, wol, bo, 1.0f, 1, nullptr, nullptr, out);
}

// round 8
// speedup vs baseline: 3.5388x; 1.0261x over previous
#include <cuda_runtime.h>
#include <cuda_bf16.h>
#include <stdint.h>

#define B_   2
#define S_   2048
#define D_   1024
#define MTOK 4096
#define BH_  32
#define BKP  40

typedef __nv_bfloat16 bf16;

// ------------------------- scratch -------------------------
__device__ bf16 g_tq_hi[MTOK*D_], g_tq_lo[MTOK*D_];
__device__ bf16 g_tk_hi[MTOK*D_], g_tk_lo[MTOK*D_];
__device__ bf16 g_tv_hi[MTOK*D_], g_tv_lo[MTOK*D_];
__device__ bf16 g_wq_hi[D_*D_],  g_wq_lo[D_*D_];
__device__ bf16 g_wk_hi[D_*D_],  g_wk_lo[D_*D_];
__device__ bf16 g_wv_hi[D_*D_],  g_wv_lo[D_*D_];
__device__ bf16 g_wo_hi[D_*D_],  g_wo_lo[D_*D_];
__device__ bf16 g_q_hi[MTOK*D_], g_q_lo[MTOK*D_];   // Q proj, pre-scaled 1/8
__device__ bf16 g_k_hi[MTOK*D_], g_k_lo[MTOK*D_];
__device__ bf16 g_vt_hi[MTOK*D_], g_vt_lo[MTOK*D_]; // V proj, [bh][d][s]
__device__ bf16 g_c_hi[MTOK*D_], g_c_lo[MTOK*D_];   // context

// ------------------------- helpers -------------------------
__device__ __forceinline__ uint32_t sptr(const void* p) {
    return (uint32_t)__cvta_generic_to_shared(p);
}
__device__ __forceinline__ void cp16(void* smem, const void* g) {
    asm volatile("cp.async.cg.shared.global [%0], [%1], 16;\n" :: "r"(sptr(smem)), "l"(g));
}
#define CP_COMMIT asm volatile("cp.async.commit_group;\n")

__device__ __forceinline__ void ldsm4(uint32_t* r, uint32_t a) {
    asm volatile("ldmatrix.sync.aligned.m8n8.x4.shared.b16 {%0,%1,%2,%3}, [%4];\n"
        : "=r"(r[0]), "=r"(r[1]), "=r"(r[2]), "=r"(r[3]) : "r"(a));
}
__device__ __forceinline__ void ldsm2(uint32_t* r, uint32_t a) {
    asm volatile("ldmatrix.sync.aligned.m8n8.x2.shared.b16 {%0,%1}, [%2];\n"
        : "=r"(r[0]), "=r"(r[1]) : "r"(a));
}

__device__ __forceinline__ void mma_bf16(float c[4], const uint32_t a[4], const uint32_t b[2])
{
    asm volatile(
        "mma.sync.aligned.m16n8k16.row.col.f32.bf16.bf16.f32 "
        "{%0,%1,%2,%3}, {%4,%5,%6,%7}, {%8,%9}, {%0,%1,%2,%3};\n"
        : "+f"(c[0]), "+f"(c[1]), "+f"(c[2]), "+f"(c[3])
        : "r"(a[0]), "r"(a[1]), "r"(a[2]), "r"(a[3]), "r"(b[0]), "r"(b[1]));
}

__device__ __forceinline__ void split_store(float v, bf16* hi, bf16* lo, size_t i)
{
    bf16 h = __float2bfloat16(v);
    hi[i] = h;
    lo[i] = __float2bfloat16(v - __bfloat162float(h));
}

__device__ __forceinline__ void split2(float f0, float f1, uint32_t& hi, uint32_t& lo)
{
    __nv_bfloat162 hh, ll;
    hh.x = __float2bfloat16(f0);  hh.y = __float2bfloat16(f1);
    ll.x = __float2bfloat16(f0 - __bfloat162float(hh.x));
    ll.y = __float2bfloat16(f1 - __bfloat162float(hh.y));
    hi = *(uint32_t*)&hh;  lo = *(uint32_t*)&ll;
}

// proj staging: 128-row x 32-k hi/lo tile
__device__ __forceinline__ void stage128(bf16* dh, bf16* dl,
    const bf16* Sh, const bf16* Sl, size_t stride, int r0, int kt, int srow, int sch)
{
    size_t a0 = (size_t)(r0 + srow)      * stride + kt + sch;
    size_t a1 = (size_t)(r0 + srow + 64) * stride + kt + sch;
    cp16(dh +  srow      * BKP + sch, Sh + a0);
    cp16(dh + (srow + 64) * BKP + sch, Sh + a1);
    cp16(dl +  srow      * BKP + sch, Sl + a0);
    cp16(dl + (srow + 64) * BKP + sch, Sl + a1);
}

// 32-deep k step via ldmatrix, MT m-frags x 4 n-frags, 3-pass split mma
template<int MT>
__device__ __forceinline__ void mma_tileN(uint32_t ah, uint32_t al, uint32_t bh, uint32_t bl,
    int wm, int wn, int lane, float (*acc)[4][4])
{
    const uint32_t aoff = (uint32_t)((lane & 15) * BKP * 2 + (lane >> 4) * 16);
    const uint32_t boff = (uint32_t)((lane & 7) * BKP * 2 + ((lane >> 3) & 1) * 16);
    #pragma unroll
    for (int kk = 0; kk < 32; kk += 16) {
        uint32_t aH[MT][4], aL[MT][4], bH[4][2], bL[4][2];
        #pragma unroll
        for (int mt = 0; mt < MT; ++mt) {
            uint32_t base = (uint32_t)(((wm + mt*16)*BKP + kk) * 2);
            ldsm4(aH[mt], ah + base + aoff);
            ldsm4(aL[mt], al + base + aoff);
        }
        #pragma unroll
        for (int nt = 0; nt < 4; ++nt) {
            uint32_t base = (uint32_t)(((wn + nt*8)*BKP + kk) * 2);
            ldsm2(bH[nt], bh + base + boff);
            ldsm2(bL[nt], bl + base + boff);
        }
        #pragma unroll
        for (int mt = 0; mt < MT; ++mt)
            #pragma unroll
            for (int nt = 0; nt < 4; ++nt) {
                mma_bf16(acc[mt][nt], aH[mt], bH[nt]);
                mma_bf16(acc[mt][nt], aH[mt], bL[nt]);
                mma_bf16(acc[mt][nt], aL[mt], bH[nt]);
            }
    }
}

// ------------------------- split (all 7 tensors, one launch) ----------------
struct SplitArgs {
    const float* src[7];
    bf16* hi[7];
    bf16* lo[7];
};
#define NT (MTOK*D_)
#define NW (D_*D_)

__global__ __launch_bounds__(256) void split_all_kernel(SplitArgs a)
{
    int bid = blockIdx.x;
    int z, base;
    if (bid < 3 * (NT/256)) { z = bid / (NT/256); base = (bid % (NT/256)) * 256; }
    else { int r = bid - 3*(NT/256); z = 3 + r / (NW/256); base = (r % (NW/256)) * 256; }
    int i = base + threadIdx.x;
    float v = a.src[z][i];
    bf16 h = __float2bfloat16(v);
    a.hi[z][i] = h;
    a.lo[z][i] = __float2bfloat16(v - __bfloat162float(h));
}

// ------------------------- projection GEMM ----------------------------------
// C[4096,1024] = A @ W^T + bias.  mode 0: split bf16 (scaled); 1: fp32 out; 2: split V-transposed
__device__ __forceinline__ void proj_body(
    const bf16* __restrict__ Ahi, const bf16* __restrict__ Alo,
    const bf16* __restrict__ Whi, const bf16* __restrict__ Wlo,
    const float* __restrict__ bias, const float scale, const int mode,
    bf16* __restrict__ Ohi, bf16* __restrict__ Olo, float* __restrict__ Of)
{
    extern __shared__ bf16 sm[];
    #define TA(buf,hl) (sm + ((buf)*2 + (hl)) * (128*BKP))
    #define TB(buf,hl) (sm + (4 + (buf)*2 + (hl)) * (128*BKP))
    const int tid = threadIdx.x, lane = tid & 31, wid = tid >> 5;
    const int g = lane >> 2, t = lane & 3;
    const int wm = (wid >> 2) * 64, wn = (wid & 3) * 32;
    const int m0 = blockIdx.y * 128, n0 = blockIdx.x * 128;
    const int srow = tid >> 2, sch = (tid & 3) * 8;

    float acc[4][4][4] = {};
    stage128(TA(0,0), TA(0,1), Ahi, Alo, D_, m0, 0, srow, sch);
    stage128(TB(0,0), TB(0,1), Whi, Wlo, D_, n0, 0, srow, sch);
    CP_COMMIT;

    for (int kt = 0; kt < D_; kt += 32) {
        const int cur = (kt >> 5) & 1;
        asm volatile("cp.async.wait_group 0;\n");
        __syncthreads();
        if (kt + 32 < D_) {
            stage128(TA(cur^1,0), TA(cur^1,1), Ahi, Alo, D_, m0, kt + 32, srow, sch);
            stage128(TB(cur^1,0), TB(cur^1,1), Whi, Wlo, D_, n0, kt + 32, srow, sch);
            CP_COMMIT;
        }
        mma_tileN<4>(sptr(TA(cur,0)), sptr(TA(cur,1)), sptr(TB(cur,0)), sptr(TB(cur,1)),
                     wm, wn, lane, acc);
        __syncthreads();
    }

    #pragma unroll
    for (int mt = 0; mt < 4; ++mt) {
        int row0 = m0 + wm + mt*16 + g;
        #pragma unroll
        for (int nt = 0; nt < 4; ++nt) {
            int col = n0 + wn + nt*8 + 2*t;
            float v[4];
            v[0] = (acc[mt][nt][0] + bias[col])   * scale;
            v[1] = (acc[mt][nt][1] + bias[col+1]) * scale;
            v[2] = (acc[mt][nt][2] + bias[col])   * scale;
            v[3] = (acc[mt][nt][3] + bias[col+1]) * scale;
            if (mode == 0) {
                size_t i0 = (size_t)row0 * D_ + col, i1 = (size_t)(row0+8) * D_ + col;
                split_store(v[0], Ohi, Olo, i0);   split_store(v[1], Ohi, Olo, i0+1);
                split_store(v[2], Ohi, Olo, i1);   split_store(v[3], Ohi, Olo, i1+1);
            } else if (mode == 1) {
                size_t i0 = (size_t)row0 * D_ + col, i1 = (size_t)(row0+8) * D_ + col;
                Of[i0] = v[0]; Of[i0+1] = v[1]; Of[i1] = v[2]; Of[i1+1] = v[3];
            } else {  // V transposed: [bh][d][s]
                #pragma unroll
                for (int e = 0; e < 4; ++e) {
                    int row = row0 + (e >> 1) * 8, c = col + (e & 1);
                    size_t i = (((size_t)(row >> 11) * 16 + (c >> 6)) * 64 + (c & 63)) * S_
                             + (row & (S_-1));
                    split_store(v[e], Ohi, Olo, i);
                }
            }
        }
    }
    #undef TA
    #undef TB
}

struct ProjArgs {
    const bf16 *Ah[3], *Al[3], *Wh[3], *Wl[3];
    const float* bias[3];
    bf16 *Oh[3], *Ol[3];
};

__global__ __launch_bounds__(256) void proj_qkv_kernel(ProjArgs p)
{
    int z = blockIdx.z;
    proj_body(p.Ah[z], p.Al[z], p.Wh[z], p.Wl[z], p.bias[z],
              z == 0 ? 0.125f : 1.0f, z == 2 ? 2 : 0,
              p.Oh[z], p.Ol[z], nullptr);
}

__global__ __launch_bounds__(256) void proj_o_kernel(
    const bf16* Ahi, const bf16* Alo, const bf16* Whi, const bf16* Wlo,
    const float* bias, float* Of)
{
    proj_body(Ahi, Alo, Whi, Wlo, bias, 1.0f, 1, nullptr, nullptr, Of);
}

// ------------------------- flash attention -------------------------
// q-tile 64 rows per CTA; k streamed in 128-token chunks.
#define QHL  (64*72)
#define KHL  (128*72)
#define VHL  (64*136)
#define FLASH_SMEM 169984

__device__ __forceinline__ void stage_k(bf16* Ks, int buf, int b, int h, int kt, int kr, int kc)
{
    size_t gk = ((size_t)(b*S_ + kt + kr))*D_ + h*64 + kc;
    bf16* d = Ks + buf*(2*KHL) + kr*72 + kc;
    #pragma unroll
    for (int i = 0; i < 4; ++i) cp16(d + i*8, g_k_hi + gk + i*8);
    d += KHL;
    #pragma unroll
    for (int i = 0; i < 4; ++i) cp16(d + i*8, g_k_lo + gk + i*8);
}
__device__ __forceinline__ void stage_v(bf16* Vs, int buf, int bh, int kt, int vr, int vc)
{
    size_t gv = ((size_t)(bh*64 + vr))*S_ + kt + vc;
    bf16* d = Vs + buf*(2*VHL) + vr*136 + vc;
    #pragma unroll
    for (int i = 0; i < 4; ++i) cp16(d + i*8, g_vt_hi + gv + i*8);
    d += VHL;
    #pragma unroll
    for (int i = 0; i < 4; ++i) cp16(d + i*8, g_vt_lo + gv + i*8);
}

__global__ __launch_bounds__(256) void flash_kernel(const int* __restrict__ mask)
{
    extern __shared__ char smc[];
    bf16* Qs = (bf16*)smc;                 // [hl][64][72]
    bf16* Ks = (bf16*)(smc + 18432);       // [buf][hl][128][72]
    bf16* Vs = (bf16*)(smc + 92160);       // [buf][hl][64][136]
    int*  Ms = (int*)(smc + 161792);       // [2048]
    float* red   = (float*)smc;            // [4][64][68]  (post-loop reuse)
    float* lpart = (float*)(smc + 69632);  // [4][64]

    const int bh = blockIdx.y, b = bh >> 4, h = bh & 15;
    const int q0 = blockIdx.x * 64;
    const int tid = threadIdx.x, lane = tid & 31, wid = tid >> 5;
    const int g = lane >> 2, t = lane & 3;
    const int wm = (wid >> 2) * 32;     // 2 m-halves of 32 rows
    const int j  = wid & 3;             // k-slice owner
    const int wn = j * 32;

    const int qr = tid >> 2, qc = (tid & 3) * 16;
    const int kr = tid >> 1, kc = (tid & 1) * 32;
    const int vr = tid >> 2, vc = (tid & 3) * 32;

    // ldmatrix lane offsets (strides 72 and 136)
    const uint32_t aoff72  = (uint32_t)((lane & 15) * 72 * 2 + (lane >> 4) * 16);
    const uint32_t boff72  = (uint32_t)((lane & 7) * 72 * 2 + ((lane >> 3) & 1) * 16);
    const uint32_t boff136 = (uint32_t)((lane & 7) * 136 * 2 + ((lane >> 3) & 1) * 16);
    const uint32_t qs_base = sptr(Qs);

    // prologue: Q, K0, V0, mask
    {
        size_t gq = ((size_t)(b*S_ + q0 + qr))*D_ + h*64 + qc;
        cp16(Qs +       qr*72 + qc,     g_q_hi + gq);
        cp16(Qs +       qr*72 + qc + 8, g_q_hi + gq + 8);
        cp16(Qs + QHL + qr*72 + qc,     g_q_lo + gq);
        cp16(Qs + QHL + qr*72 + qc + 8, g_q_lo + gq + 8);
        stage_k(Ks, 0, b, h, 0, kr, kc);
        stage_v(Vs, 0, bh, 0, vr, vc);
        cp16(Ms + tid*8,     mask + b*S_ + tid*8);
        cp16(Ms + tid*8 + 4, mask + b*S_ + tid*8 + 4);
        CP_COMMIT;
    }

    float acc_o[2][8][4] = {};
    float ls[2][2] = {};

    for (int it = 0; it < 16; ++it) {
        const int cur = it & 1;
        if (it < 15) {
            stage_k(Ks, cur^1, b, h, (it+1)*128, kr, kc);
            stage_v(Vs, cur^1, bh, (it+1)*128, vr, vc);
            CP_COMMIT;
            asm volatile("cp.async.wait_group 1;\n");
        } else {
            asm volatile("cp.async.wait_group 0;\n");
        }
        __syncthreads();

        // ---- scores: Q[64x64] . K_chunk[128x64]^T, warp slice 32q x 32k ----
        float accs[2][4][4] = {};
        const uint32_t kb  = sptr(Ks + cur*(2*KHL));
        const uint32_t kbl = kb + KHL*2;   // lo plane (bytes)
        #pragma unroll
        for (int kk = 0; kk < 64; kk += 16) {
            uint32_t aH[2][4], aL[2][4], bH[4][2], bL[4][2];
            #pragma unroll
            for (int mt = 0; mt < 2; ++mt) {
                uint32_t base = (uint32_t)(((wm + mt*16)*72 + kk) * 2);
                ldsm4(aH[mt], qs_base + base + aoff72);
                ldsm4(aL[mt], qs_base + QHL*2 + base + aoff72);
            }
            #pragma unroll
            for (int nt = 0; nt < 4; ++nt) {
                uint32_t base = (uint32_t)(((wn + nt*8)*72 + kk) * 2);
                ldsm2(bH[nt], kb  + base + boff72);
                ldsm2(bL[nt], kbl + base + boff72);
            }
            #pragma unroll
            for (int mt = 0; mt < 2; ++mt)
                #pragma unroll
                for (int nt = 0; nt < 4; ++nt) {
                    mma_bf16(accs[mt][nt], aH[mt], bH[nt]);
                    mma_bf16(accs[mt][nt], aH[mt], bL[nt]);
                    mma_bf16(accs[mt][nt], aL[mt], bH[nt]);
                }
        }

        // ---- mask + exp + pack P acc -> A-frags ----
        uint32_t pH[2][2][4], pL[2][2][4];
        #pragma unroll
        for (int mt = 0; mt < 2; ++mt) {
            #pragma unroll
            for (int nt = 0; nt < 4; ++nt) {
                int c0 = it*128 + wn + nt*8 + 2*t;
                bool m0 = Ms[c0] != 0, m1 = Ms[c0+1] != 0;
                float p0 = m0 ? __expf(accs[mt][nt][0]) : 0.f;
                float p1 = m1 ? __expf(accs[mt][nt][1]) : 0.f;
                float p2 = m0 ? __expf(accs[mt][nt][2]) : 0.f;
                float p3 = m1 ? __expf(accs[mt][nt][3]) : 0.f;
                ls[mt][0] += p0 + p1;
                ls[mt][1] += p2 + p3;
                int jj = nt >> 1, hf = (nt & 1) * 2;
                split2(p0, p1, pH[mt][jj][hf],   pL[mt][jj][hf]);
                split2(p2, p3, pH[mt][jj][hf+1], pL[mt][jj][hf+1]);
            }
        }

        // ---- P_slice[32q x 32k] . V_chunk[32k x 64d] ----
        const uint32_t vb  = sptr(Vs + cur*(2*VHL));
        const uint32_t vbl = vb + VHL*2;
        #pragma unroll
        for (int jj = 0; jj < 2; ++jj) {
            uint32_t bH[8][2], bL[8][2];
            #pragma unroll
            for (int dt = 0; dt < 8; ++dt) {
                uint32_t base = (uint32_t)(((dt*8)*136 + wn + jj*16) * 2);
                ldsm2(bH[dt], vb  + base + boff136);
                ldsm2(bL[dt], vbl + base + boff136);
            }
            #pragma unroll
            for (int mt = 0; mt < 2; ++mt)
                #pragma unroll
                for (int dt = 0; dt < 8; ++dt) {
                    mma_bf16(acc_o[mt][dt], pH[mt][jj], bH[dt]);
                    mma_bf16(acc_o[mt][dt], pH[mt][jj], bL[dt]);
                    mma_bf16(acc_o[mt][dt], pL[mt][jj], bH[dt]);
                }
        }
        __syncthreads();
    }

    // ---- cross-warp reduction over the 4 k-slices ----
    #pragma unroll
    for (int mt = 0; mt < 2; ++mt) {
        int r0 = wm + mt*16 + g;
        #pragma unroll
        for (int dt = 0; dt < 8; ++dt) {
            int c = dt*8 + 2*t;
            red[(j*64 + r0)*68 + c]       = acc_o[mt][dt][0];
            red[(j*64 + r0)*68 + c + 1]   = acc_o[mt][dt][1];
            red[(j*64 + r0+8)*68 + c]     = acc_o[mt][dt][2];
            red[(j*64 + r0+8)*68 + c + 1] = acc_o[mt][dt][3];
        }
        #pragma unroll
        for (int rr = 0; rr < 2; ++rr) {
            float s = ls[mt][rr];
            s += __shfl_xor_sync(~0u, s, 1);
            s += __shfl_xor_sync(~0u, s, 2);
            if (t == 0) lpart[j*64 + r0 + rr*8] = s;
        }
    }
    __syncthreads();

    #pragma unroll
    for (int i = 0; i < 16; ++i) {
        int e = i*256 + tid;
        int row = e >> 6, col = e & 63;
        float s = red[row*68 + col] + red[(64+row)*68 + col]
                + red[(128+row)*68 + col] + red[(192+row)*68 + col];
        float l = lpart[row] + lpart[64+row] + lpart[128+row] + lpart[192+row];
        float v = s / l;
        size_t o = ((size_t)(b*S_ + q0 + row))*D_ + h*64 + col;
        split_store(v, g_c_hi, g_c_lo, o);
    }
}

// ------------------------- launch -------------------------
extern "C" void kernel_launch(void* const* d_in, const int* in_sizes, int n_in,
                              void* d_out, int out_size)
{
    const float* query = (const float*)d_in[0];
    const float* key   = (const float*)d_in[1];
    const float* value = (const float*)d_in[2];
    const int*   mask  = (const int*)d_in[3];
    const float* Wq = (const float*)d_in[4];  const float* bq = (const float*)d_in[5];
    const float* Wk = (const float*)d_in[6];  const float* bk = (const float*)d_in[7];
    const float* Wv = (const float*)d_in[8];  const float* bv = (const float*)d_in[9];
    const float* Wo = (const float*)d_in[10]; const float* bo = (const float*)d_in[11];
    float* out = (float*)d_out;

    const int GEMM_SMEM = 8 * 128 * BKP * 2;   // 81920 B
    cudaFuncSetAttribute(proj_qkv_kernel, cudaFuncAttributeMaxDynamicSharedMemorySize, GEMM_SMEM);
    cudaFuncSetAttribute(proj_o_kernel,   cudaFuncAttributeMaxDynamicSharedMemorySize, GEMM_SMEM);
    cudaFuncSetAttribute(flash_kernel,    cudaFuncAttributeMaxDynamicSharedMemorySize, FLASH_SMEM);

    bf16 *tqh,*tql,*tkh,*tkl,*tvh,*tvl,*wqh,*wql,*wkh,*wkl,*wvh,*wvl,*woh,*wol;
    bf16 *qh,*ql,*kh,*kl,*vth,*vtl,*ch,*cl;
    cudaGetSymbolAddress((void**)&tqh, g_tq_hi); cudaGetSymbolAddress((void**)&tql, g_tq_lo);
    cudaGetSymbolAddress((void**)&tkh, g_tk_hi); cudaGetSymbolAddress((void**)&tkl, g_tk_lo);
    cudaGetSymbolAddress((void**)&tvh, g_tv_hi); cudaGetSymbolAddress((void**)&tvl, g_tv_lo);
    cudaGetSymbolAddress((void**)&wqh, g_wq_hi); cudaGetSymbolAddress((void**)&wql, g_wq_lo);
    cudaGetSymbolAddress((void**)&wkh, g_wk_hi); cudaGetSymbolAddress((void**)&wkl, g_wk_lo);
    cudaGetSymbolAddress((void**)&wvh, g_wv_hi); cudaGetSymbolAddress((void**)&wvl, g_wv_lo);
    cudaGetSymbolAddress((void**)&woh, g_wo_hi); cudaGetSymbolAddress((void**)&wol, g_wo_lo);
    cudaGetSymbolAddress((void**)&qh,  g_q_hi);  cudaGetSymbolAddress((void**)&ql,  g_q_lo);
    cudaGetSymbolAddress((void**)&kh,  g_k_hi);  cudaGetSymbolAddress((void**)&kl,  g_k_lo);
    cudaGetSymbolAddress((void**)&vth, g_vt_hi); cudaGetSymbolAddress((void**)&vtl, g_vt_lo);
    cudaGetSymbolAddress((void**)&ch,  g_c_hi);  cudaGetSymbolAddress((void**)&cl,  g_c_lo);

    SplitArgs sa;
    sa.src[0] = query; sa.hi[0] = tqh; sa.lo[0] = tql;
    sa.src[1] = key;   sa.hi[1] = tkh; sa.lo[1] = tkl;
    sa.src[2] = value; sa.hi[2] = tvh; sa.lo[2] = tvl;
    sa.src[3] = Wq;    sa.hi[3] = wqh; sa.lo[3] = wql;
    sa.src[4] = Wk;    sa.hi[4] = wkh; sa.lo[4] = wkl;
    sa.src[5] = Wv;    sa.hi[5] = wvh; sa.lo[5] = wvl;
    sa.src[6] = Wo;    sa.hi[6] = woh; sa.lo[6] = wol;
    split_all_kernel<<<3*(NT/256) + 4*(NW/256), 256>>>(sa);

    ProjArgs pa;
    pa.Ah[0] = tqh; pa.Al[0] = tql; pa.Wh[0] = wqh; pa.Wl[0] = wql; pa.bias[0] = bq;
    pa.Oh[0] = qh;  pa.Ol[0] = ql;
    pa.Ah[1] = tkh; pa.Al[1] = tkl; pa.Wh[1] = wkh; pa.Wl[1] = wkl; pa.bias[1] = bk;
    pa.Oh[1] = kh;  pa.Ol[1] = kl;
    pa.Ah[2] = tvh; pa.Al[2] = tvl; pa.Wh[2] = wvh; pa.Wl[2] = wvl; pa.bias[2] = bv;
    pa.Oh[2] = vth; pa.Ol[2] = vtl;
    proj_qkv_kernel<<<dim3(D_/128, MTOK/128, 3), 256, GEMM_SMEM>>>(pa);

    flash_kernel<<<dim3(S_/64, BH_), 256, FLASH_SMEM>>>(mask);

    proj_o_kernel<<<dim3(D_/128, MTOK/128), 256, GEMM_SMEM>>>(ch, cl, woh, wol, bo, out);
}

// round 10
// speedup vs baseline: 4.0348x; 1.1402x over previous
#include <cuda_runtime.h>
#include <cuda_bf16.h>
#include <stdint.h>

#define B_   2
#define S_   2048
#define D_   1024
#define MTOK 4096
#define BH_  32
#define BKP  40

typedef __nv_bfloat16 bf16;

// ------------------------- scratch -------------------------
__device__ bf16 g_tq_hi[MTOK*D_], g_tq_lo[MTOK*D_];
__device__ bf16 g_tk_hi[MTOK*D_], g_tk_lo[MTOK*D_];
__device__ bf16 g_tv_hi[MTOK*D_], g_tv_lo[MTOK*D_];
__device__ bf16 g_wq_hi[D_*D_],  g_wq_lo[D_*D_];
__device__ bf16 g_wk_hi[D_*D_],  g_wk_lo[D_*D_];
__device__ bf16 g_wv_hi[D_*D_],  g_wv_lo[D_*D_];
__device__ bf16 g_wo_hi[D_*D_],  g_wo_lo[D_*D_];
__device__ bf16 g_q_hi[MTOK*D_], g_q_lo[MTOK*D_];   // Q proj, pre-scaled 1/8
__device__ bf16 g_k_hi[MTOK*D_], g_k_lo[MTOK*D_];
__device__ bf16 g_vt_hi[MTOK*D_], g_vt_lo[MTOK*D_]; // V proj, [bh][d][s]
__device__ bf16 g_c_hi[MTOK*D_], g_c_lo[MTOK*D_];   // context

// ------------------------- helpers -------------------------
__device__ __forceinline__ uint32_t sptr(const void* p) {
    return (uint32_t)__cvta_generic_to_shared(p);
}
__device__ __forceinline__ void cp16(void* smem, const void* g) {
    asm volatile("cp.async.cg.shared.global [%0], [%1], 16;\n" :: "r"(sptr(smem)), "l"(g));
}
#define CP_COMMIT asm volatile("cp.async.commit_group;\n")

__device__ __forceinline__ void ldsm4(uint32_t* r, uint32_t a) {
    asm volatile("ldmatrix.sync.aligned.m8n8.x4.shared.b16 {%0,%1,%2,%3}, [%4];\n"
        : "=r"(r[0]), "=r"(r[1]), "=r"(r[2]), "=r"(r[3]) : "r"(a));
}
__device__ __forceinline__ void ldsm2(uint32_t* r, uint32_t a) {
    asm volatile("ldmatrix.sync.aligned.m8n8.x2.shared.b16 {%0,%1}, [%2];\n"
        : "=r"(r[0]), "=r"(r[1]) : "r"(a));
}

__device__ __forceinline__ void mma_bf16(float c[4], const uint32_t a[4], const uint32_t b[2])
{
    asm volatile(
        "mma.sync.aligned.m16n8k16.row.col.f32.bf16.bf16.f32 "
        "{%0,%1,%2,%3}, {%4,%5,%6,%7}, {%8,%9}, {%0,%1,%2,%3};\n"
        : "+f"(c[0]), "+f"(c[1]), "+f"(c[2]), "+f"(c[3])
        : "r"(a[0]), "r"(a[1]), "r"(a[2]), "r"(a[3]), "r"(b[0]), "r"(b[1]));
}

__device__ __forceinline__ void split_store(float v, bf16* hi, bf16* lo, size_t i)
{
    bf16 h = __float2bfloat16(v);
    hi[i] = h;
    lo[i] = __float2bfloat16(v - __bfloat162float(h));
}

__device__ __forceinline__ void split2(float f0, float f1, uint32_t& hi, uint32_t& lo)
{
    __nv_bfloat162 hh, ll;
    hh.x = __float2bfloat16(f0);  hh.y = __float2bfloat16(f1);
    ll.x = __float2bfloat16(f0 - __bfloat162float(hh.x));
    ll.y = __float2bfloat16(f1 - __bfloat162float(hh.y));
    hi = *(uint32_t*)&hh;  lo = *(uint32_t*)&ll;
}

// proj staging: 128-row x 32-k hi/lo tile
__device__ __forceinline__ void stage128(bf16* dh, bf16* dl,
    const bf16* Sh, const bf16* Sl, size_t stride, int r0, int kt, int srow, int sch)
{
    size_t a0 = (size_t)(r0 + srow)      * stride + kt + sch;
    size_t a1 = (size_t)(r0 + srow + 64) * stride + kt + sch;
    cp16(dh +  srow      * BKP + sch, Sh + a0);
    cp16(dh + (srow + 64) * BKP + sch, Sh + a1);
    cp16(dl +  srow      * BKP + sch, Sl + a0);
    cp16(dl + (srow + 64) * BKP + sch, Sl + a1);
}

// 32-deep k step via ldmatrix, MT m-frags x 4 n-frags, 3-pass split mma
template<int MT>
__device__ __forceinline__ void mma_tileN(uint32_t ah, uint32_t al, uint32_t bh, uint32_t bl,
    int wm, int wn, int lane, float (*acc)[4][4])
{
    const uint32_t aoff = (uint32_t)((lane & 15) * BKP * 2 + (lane >> 4) * 16);
    const uint32_t boff = (uint32_t)((lane & 7) * BKP * 2 + ((lane >> 3) & 1) * 16);
    #pragma unroll
    for (int kk = 0; kk < 32; kk += 16) {
        uint32_t aH[MT][4], aL[MT][4], bH[4][2], bL[4][2];
        #pragma unroll
        for (int mt = 0; mt < MT; ++mt) {
            uint32_t base = (uint32_t)(((wm + mt*16)*BKP + kk) * 2);
            ldsm4(aH[mt], ah + base + aoff);
            ldsm4(aL[mt], al + base + aoff);
        }
        #pragma unroll
        for (int nt = 0; nt < 4; ++nt) {
            uint32_t base = (uint32_t)(((wn + nt*8)*BKP + kk) * 2);
            ldsm2(bH[nt], bh + base + boff);
            ldsm2(bL[nt], bl + base + boff);
        }
        #pragma unroll
        for (int mt = 0; mt < MT; ++mt)
            #pragma unroll
            for (int nt = 0; nt < 4; ++nt) {
                mma_bf16(acc[mt][nt], aH[mt], bH[nt]);
                mma_bf16(acc[mt][nt], aH[mt], bL[nt]);
                mma_bf16(acc[mt][nt], aL[mt], bH[nt]);
            }
    }
}

// ------------------------- split (all 7 tensors, one launch) ----------------
struct SplitArgs {
    const float* src[7];
    bf16* hi[7];
    bf16* lo[7];
};
#define NT (MTOK*D_)
#define NW (D_*D_)

__global__ __launch_bounds__(256) void split_all_kernel(SplitArgs a)
{
    int bid = blockIdx.x;
    int z, base;
    if (bid < 3 * (NT/256)) { z = bid / (NT/256); base = (bid % (NT/256)) * 256; }
    else { int r = bid - 3*(NT/256); z = 3 + r / (NW/256); base = (r % (NW/256)) * 256; }
    int i = base + threadIdx.x;
    float v = a.src[z][i];
    bf16 h = __float2bfloat16(v);
    a.hi[z][i] = h;
    a.lo[z][i] = __float2bfloat16(v - __bfloat162float(h));
}

// ------------------------- projection GEMM ----------------------------------
// C[4096,1024] = A @ W^T + bias.  mode 0: split bf16 (scaled); 1: fp32 out; 2: split V-transposed
__device__ __forceinline__ void proj_body(
    const bf16* __restrict__ Ahi, const bf16* __restrict__ Alo,
    const bf16* __restrict__ Whi, const bf16* __restrict__ Wlo,
    const float* __restrict__ bias, const float scale, const int mode,
    bf16* __restrict__ Ohi, bf16* __restrict__ Olo, float* __restrict__ Of)
{
    extern __shared__ bf16 sm[];
    #define TA(buf,hl) (sm + ((buf)*2 + (hl)) * (128*BKP))
    #define TB(buf,hl) (sm + (4 + (buf)*2 + (hl)) * (128*BKP))
    const int tid = threadIdx.x, lane = tid & 31, wid = tid >> 5;
    const int g = lane >> 2, t = lane & 3;
    const int wm = (wid >> 2) * 64, wn = (wid & 3) * 32;
    const int m0 = blockIdx.y * 128, n0 = blockIdx.x * 128;
    const int srow = tid >> 2, sch = (tid & 3) * 8;

    float acc[4][4][4] = {};
    stage128(TA(0,0), TA(0,1), Ahi, Alo, D_, m0, 0, srow, sch);
    stage128(TB(0,0), TB(0,1), Whi, Wlo, D_, n0, 0, srow, sch);
    CP_COMMIT;

    for (int kt = 0; kt < D_; kt += 32) {
        const int cur = (kt >> 5) & 1;
        asm volatile("cp.async.wait_group 0;\n");
        __syncthreads();
        if (kt + 32 < D_) {
            stage128(TA(cur^1,0), TA(cur^1,1), Ahi, Alo, D_, m0, kt + 32, srow, sch);
            stage128(TB(cur^1,0), TB(cur^1,1), Whi, Wlo, D_, n0, kt + 32, srow, sch);
            CP_COMMIT;
        }
        mma_tileN<4>(sptr(TA(cur,0)), sptr(TA(cur,1)), sptr(TB(cur,0)), sptr(TB(cur,1)),
                     wm, wn, lane, acc);
        __syncthreads();
    }

    #pragma unroll
    for (int mt = 0; mt < 4; ++mt) {
        int row0 = m0 + wm + mt*16 + g;
        #pragma unroll
        for (int nt = 0; nt < 4; ++nt) {
            int col = n0 + wn + nt*8 + 2*t;
            float v[4];
            v[0] = (acc[mt][nt][0] + bias[col])   * scale;
            v[1] = (acc[mt][nt][1] + bias[col+1]) * scale;
            v[2] = (acc[mt][nt][2] + bias[col])   * scale;
            v[3] = (acc[mt][nt][3] + bias[col+1]) * scale;
            if (mode == 0) {
                size_t i0 = (size_t)row0 * D_ + col, i1 = (size_t)(row0+8) * D_ + col;
                split_store(v[0], Ohi, Olo, i0);   split_store(v[1], Ohi, Olo, i0+1);
                split_store(v[2], Ohi, Olo, i1);   split_store(v[3], Ohi, Olo, i1+1);
            } else if (mode == 1) {
                size_t i0 = (size_t)row0 * D_ + col, i1 = (size_t)(row0+8) * D_ + col;
                Of[i0] = v[0]; Of[i0+1] = v[1]; Of[i1] = v[2]; Of[i1+1] = v[3];
            } else {  // V transposed: [bh][d][s]
                #pragma unroll
                for (int e = 0; e < 4; ++e) {
                    int row = row0 + (e >> 1) * 8, c = col + (e & 1);
                    size_t i = (((size_t)(row >> 11) * 16 + (c >> 6)) * 64 + (c & 63)) * S_
                             + (row & (S_-1));
                    split_store(v[e], Ohi, Olo, i);
                }
            }
        }
    }
    #undef TA
    #undef TB
}

struct ProjArgs {
    const bf16 *Ah[3], *Al[3], *Wh[3], *Wl[3];
    const float* bias[3];
    bf16 *Oh[3], *Ol[3];
};

__global__ __launch_bounds__(256) void proj_qkv_kernel(ProjArgs p)
{
    int z = blockIdx.z;
    proj_body(p.Ah[z], p.Al[z], p.Wh[z], p.Wl[z], p.bias[z],
              z == 0 ? 0.125f : 1.0f, z == 2 ? 2 : 0,
              p.Oh[z], p.Ol[z], nullptr);
}

__global__ __launch_bounds__(256) void proj_o_kernel(
    const bf16* Ahi, const bf16* Alo, const bf16* Whi, const bf16* Wlo,
    const float* bias, float* Of)
{
    proj_body(Ahi, Alo, Whi, Wlo, bias, 1.0f, 1, nullptr, nullptr, Of);
}

// ------------------------- flash attention (2 CTAs/SM) ----------------------
// q-tile 64 rows/CTA; K streamed in 64-token chunks; 8 warps = 4m(16q) x 2 k-slices.
// smem: Qs 18432 | Ks 36864 | Vs 36864 | Ms 8192 = 100352 bytes
#define KCH  64
#define QHL  (64*72)
#define KHL  (64*72)
#define VHL  (64*72)
#define FLASH_SMEM 100352

__device__ __forceinline__ void stage_k64(bf16* Ks, int buf, int b, int h, int kt, int kr, int kc)
{
    size_t gk = ((size_t)(b*S_ + kt + kr))*D_ + h*64 + kc;
    bf16* d = Ks + buf*(2*KHL) + kr*72 + kc;
    cp16(d,     g_k_hi + gk);
    cp16(d + 8, g_k_hi + gk + 8);
    d += KHL;
    cp16(d,     g_k_lo + gk);
    cp16(d + 8, g_k_lo + gk + 8);
}
__device__ __forceinline__ void stage_v64(bf16* Vs, int buf, int bh, int kt, int vr, int vc)
{
    size_t gv = ((size_t)(bh*64 + vr))*S_ + kt + vc;
    bf16* d = Vs + buf*(2*VHL) + vr*72 + vc;
    cp16(d,     g_vt_hi + gv);
    cp16(d + 8, g_vt_hi + gv + 8);
    d += VHL;
    cp16(d,     g_vt_lo + gv);
    cp16(d + 8, g_vt_lo + gv + 8);
}

__global__ __launch_bounds__(256, 2) void flash_kernel(const int* __restrict__ mask)
{
    extern __shared__ char smc[];
    bf16* Qs = (bf16*)smc;                 // [hl][64][72]
    bf16* Ks = (bf16*)(smc + 18432);       // [buf][hl][64][72]
    bf16* Vs = (bf16*)(smc + 55296);       // [buf][hl][64][72]
    int*  Ms = (int*)(smc + 92160);        // [2048]
    float* red   = (float*)smc;            // [64][68]  (post-loop reuse of Qs)
    float* lpart = (float*)(smc + 18432);  // [64]      (post-loop reuse of Ks)

    const int bh = blockIdx.y, b = bh >> 4, h = bh & 15;
    const int q0 = blockIdx.x * 64;
    const int tid = threadIdx.x, lane = tid & 31, wid = tid >> 5;
    const int g = lane >> 2, t = lane & 3;
    const int mg = wid >> 1;            // m-group: 16 q-rows
    const int j  = wid & 1;             // k-slice owner (32 tokens of each 64-chunk)
    const int wn = j * 32;

    const int qr = tid >> 2, qc = (tid & 3) * 16;
    const int kr = tid >> 2, kc = (tid & 3) * 16;

    const uint32_t aoff72 = (uint32_t)((lane & 15) * 144 + (lane >> 4) * 16);
    const uint32_t boff72 = (uint32_t)((lane & 7) * 144 + ((lane >> 3) & 1) * 16);
    const uint32_t qs_base = sptr(Qs);

    // prologue: Q, K0, V0, mask
    {
        size_t gq = ((size_t)(b*S_ + q0 + qr))*D_ + h*64 + qc;
        cp16(Qs +       qr*72 + qc,     g_q_hi + gq);
        cp16(Qs +       qr*72 + qc + 8, g_q_hi + gq + 8);
        cp16(Qs + QHL + qr*72 + qc,     g_q_lo + gq);
        cp16(Qs + QHL + qr*72 + qc + 8, g_q_lo + gq + 8);
        stage_k64(Ks, 0, b, h, 0, kr, kc);
        stage_v64(Vs, 0, bh, 0, kr, kc);
        cp16(Ms + tid*8,     mask + b*S_ + tid*8);
        cp16(Ms + tid*8 + 4, mask + b*S_ + tid*8 + 4);
        CP_COMMIT;
    }

    float acc_o[8][4] = {};
    float ls[2] = {};

    for (int it = 0; it < 32; ++it) {
        const int cur = it & 1;
        if (it < 31) {
            stage_k64(Ks, cur^1, b, h, (it+1)*KCH, kr, kc);
            stage_v64(Vs, cur^1, bh, (it+1)*KCH, kr, kc);
            CP_COMMIT;
            asm volatile("cp.async.wait_group 1;\n");
        } else {
            asm volatile("cp.async.wait_group 0;\n");
        }
        __syncthreads();

        // ---- scores: Q[16q x 64dk] . K_slice[32k x 64dk]^T ----
        float accs[4][4] = {};
        const uint32_t kb  = sptr(Ks + cur*(2*KHL));
        const uint32_t kbl = kb + KHL*2;
        #pragma unroll
        for (int kk = 0; kk < 64; kk += 16) {
            uint32_t aH[4], aL[4], bH[4][2], bL[4][2];
            uint32_t abase = (uint32_t)(((mg*16)*72 + kk) * 2);
            ldsm4(aH, qs_base + abase + aoff72);
            ldsm4(aL, qs_base + QHL*2 + abase + aoff72);
            #pragma unroll
            for (int nt = 0; nt < 4; ++nt) {
                uint32_t base = (uint32_t)(((wn + nt*8)*72 + kk) * 2);
                ldsm2(bH[nt], kb  + base + boff72);
                ldsm2(bL[nt], kbl + base + boff72);
            }
            #pragma unroll
            for (int nt = 0; nt < 4; ++nt) {
                mma_bf16(accs[nt], aH, bH[nt]);
                mma_bf16(accs[nt], aH, bL[nt]);
                mma_bf16(accs[nt], aL, bH[nt]);
            }
        }

        // ---- mask + exp + pack P acc -> A-frags ----
        uint32_t pH[2][4], pL[2][4];
        #pragma unroll
        for (int nt = 0; nt < 4; ++nt) {
            int c0 = it*KCH + wn + nt*8 + 2*t;
            bool m0 = Ms[c0] != 0, m1 = Ms[c0+1] != 0;
            float p0 = m0 ? __expf(accs[nt][0]) : 0.f;
            float p1 = m1 ? __expf(accs[nt][1]) : 0.f;
            float p2 = m0 ? __expf(accs[nt][2]) : 0.f;
            float p3 = m1 ? __expf(accs[nt][3]) : 0.f;
            ls[0] += p0 + p1;
            ls[1] += p2 + p3;
            int jj = nt >> 1, hf = (nt & 1) * 2;
            split2(p0, p1, pH[jj][hf],   pL[jj][hf]);
            split2(p2, p3, pH[jj][hf+1], pL[jj][hf+1]);
        }

        // ---- P_slice[16q x 32k] . V_slice[32k x 64d] ----
        const uint32_t vb  = sptr(Vs + cur*(2*VHL));
        const uint32_t vbl = vb + VHL*2;
        #pragma unroll
        for (int jj = 0; jj < 2; ++jj) {
            uint32_t bH[8][2], bL[8][2];
            #pragma unroll
            for (int dt = 0; dt < 8; ++dt) {
                uint32_t base = (uint32_t)(((dt*8)*72 + wn + jj*16) * 2);
                ldsm2(bH[dt], vb  + base + boff72);
                ldsm2(bL[dt], vbl + base + boff72);
            }
            #pragma unroll
            for (int dt = 0; dt < 8; ++dt) {
                mma_bf16(acc_o[dt], pH[jj], bH[dt]);
                mma_bf16(acc_o[dt], pH[jj], bL[dt]);
                mma_bf16(acc_o[dt], pL[jj], bH[dt]);
            }
        }
        __syncthreads();
    }

    // ---- cross-slice reduction (2 rounds over j) ----
    const int r0 = mg*16 + g;
    float s0 = ls[0], s1 = ls[1];
    s0 += __shfl_xor_sync(~0u, s0, 1);  s0 += __shfl_xor_sync(~0u, s0, 2);
    s1 += __shfl_xor_sync(~0u, s1, 1);  s1 += __shfl_xor_sync(~0u, s1, 2);

    #pragma unroll
    for (int round = 0; round < 2; ++round) {
        if (j == round) {
            #pragma unroll
            for (int dt = 0; dt < 8; ++dt) {
                int c = dt*8 + 2*t;
                if (round == 0) {
                    red[r0*68 + c]       = acc_o[dt][0];
                    red[r0*68 + c + 1]   = acc_o[dt][1];
                    red[(r0+8)*68 + c]   = acc_o[dt][2];
                    red[(r0+8)*68 + c+1] = acc_o[dt][3];
                } else {
                    red[r0*68 + c]       += acc_o[dt][0];
                    red[r0*68 + c + 1]   += acc_o[dt][1];
                    red[(r0+8)*68 + c]   += acc_o[dt][2];
                    red[(r0+8)*68 + c+1] += acc_o[dt][3];
                }
            }
            if (t == 0) {
                if (round == 0) { lpart[r0] = s0;  lpart[r0+8] = s1; }
                else            { lpart[r0] += s0; lpart[r0+8] += s1; }
            }
        }
        __syncthreads();
    }

    #pragma unroll
    for (int i = 0; i < 16; ++i) {
        int e = i*256 + tid;
        int row = e >> 6, col = e & 63;
        float v = red[row*68 + col] / lpart[row];
        size_t o = ((size_t)(b*S_ + q0 + row))*D_ + h*64 + col;
        split_store(v, g_c_hi, g_c_lo, o);
    }
}

// ------------------------- launch -------------------------
extern "C" void kernel_launch(void* const* d_in, const int* in_sizes, int n_in,
                              void* d_out, int out_size)
{
    const float* query = (const float*)d_in[0];
    const float* key   = (const float*)d_in[1];
    const float* value = (const float*)d_in[2];
    const int*   mask  = (const int*)d_in[3];
    const float* Wq = (const float*)d_in[4];  const float* bq = (const float*)d_in[5];
    const float* Wk = (const float*)d_in[6];  const float* bk = (const float*)d_in[7];
    const float* Wv = (const float*)d_in[8];  const float* bv = (const float*)d_in[9];
    const float* Wo = (const float*)d_in[10]; const float* bo = (const float*)d_in[11];
    float* out = (float*)d_out;

    const int GEMM_SMEM = 8 * 128 * BKP * 2;   // 81920 B
    cudaFuncSetAttribute(proj_qkv_kernel, cudaFuncAttributeMaxDynamicSharedMemorySize, GEMM_SMEM);
    cudaFuncSetAttribute(proj_o_kernel,   cudaFuncAttributeMaxDynamicSharedMemorySize, GEMM_SMEM);
    cudaFuncSetAttribute(flash_kernel,    cudaFuncAttributeMaxDynamicSharedMemorySize, FLASH_SMEM);

    bf16 *tqh,*tql,*tkh,*tkl,*tvh,*tvl,*wqh,*wql,*wkh,*wkl,*wvh,*wvl,*woh,*wol;
    bf16 *qh,*ql,*kh,*kl,*vth,*vtl,*ch,*cl;
    cudaGetSymbolAddress((void**)&tqh, g_tq_hi); cudaGetSymbolAddress((void**)&tql, g_tq_lo);
    cudaGetSymbolAddress((void**)&tkh, g_tk_hi); cudaGetSymbolAddress((void**)&tkl, g_tk_lo);
    cudaGetSymbolAddress((void**)&tvh, g_tv_hi); cudaGetSymbolAddress((void**)&tvl, g_tv_lo);
    cudaGetSymbolAddress((void**)&wqh, g_wq_hi); cudaGetSymbolAddress((void**)&wql, g_wq_lo);
    cudaGetSymbolAddress((void**)&wkh, g_wk_hi); cudaGetSymbolAddress((void**)&wkl, g_wk_lo);
    cudaGetSymbolAddress((void**)&wvh, g_wv_hi); cudaGetSymbolAddress((void**)&wvl, g_wv_lo);
    cudaGetSymbolAddress((void**)&woh, g_wo_hi); cudaGetSymbolAddress((void**)&wol, g_wo_lo);
    cudaGetSymbolAddress((void**)&qh,  g_q_hi);  cudaGetSymbolAddress((void**)&ql,  g_q_lo);
    cudaGetSymbolAddress((void**)&kh,  g_k_hi);  cudaGetSymbolAddress((void**)&kl,  g_k_lo);
    cudaGetSymbolAddress((void**)&vth, g_vt_hi); cudaGetSymbolAddress((void**)&vtl, g_vt_lo);
    cudaGetSymbolAddress((void**)&ch,  g_c_hi);  cudaGetSymbolAddress((void**)&cl,  g_c_lo);

    SplitArgs sa;
    sa.src[0] = query; sa.hi[0] = tqh; sa.lo[0] = tql;
    sa.src[1] = key;   sa.hi[1] = tkh; sa.lo[1] = tkl;
    sa.src[2] = value; sa.hi[2] = tvh; sa.lo[2] = tvl;
    sa.src[3] = Wq;    sa.hi[3] = wqh; sa.lo[3] = wql;
    sa.src[4] = Wk;    sa.hi[4] = wkh; sa.lo[4] = wkl;
    sa.src[5] = Wv;    sa.hi[5] = wvh; sa.lo[5] = wvl;
    sa.src[6] = Wo;    sa.hi[6] = woh; sa.lo[6] = wol;
    split_all_kernel<<<3*(NT/256) + 4*(NW/256), 256>>>(sa);

    ProjArgs pa;
    pa.Ah[0] = tqh; pa.Al[0] = tql; pa.Wh[0] = wqh; pa.Wl[0] = wql; pa.bias[0] = bq;
    pa.Oh[0] = qh;  pa.Ol[0] = ql;
    pa.Ah[1] = tkh; pa.Al[1] = tkl; pa.Wh[1] = wkh; pa.Wl[1] = wkl; pa.bias[1] = bk;
    pa.Oh[1] = kh;  pa.Ol[1] = kl;
    pa.Ah[2] = tvh; pa.Al[2] = tvl; pa.Wh[2] = wvh; pa.Wl[2] = wvl; pa.bias[2] = bv;
    pa.Oh[2] = vth; pa.Ol[2] = vtl;
    proj_qkv_kernel<<<dim3(D_/128, MTOK/128, 3), 256, GEMM_SMEM>>>(pa);

    flash_kernel<<<dim3(S_/64, BH_), 256, FLASH_SMEM>>>(mask);

    proj_o_kernel<<<dim3(D_/128, MTOK/128), 256, GEMM_SMEM>>>(ch, cl, woh, wol, bo, out);
}

// round 11
// speedup vs baseline: 4.9475x; 1.2262x over previous
#include <cuda_runtime.h>
#include <cuda_fp16.h>
#include <stdint.h>

#define B_   2
#define S_   2048
#define D_   1024
#define MTOK 4096
#define BH_  32
#define BKP  40
#define CORRF (64.0f/65.0f)

typedef __half f16;

// ------------------------- scratch (hi plane, m plane) -------------------------
__device__ f16 g_tq_hi[MTOK*D_], g_tq_lo[MTOK*D_];
__device__ f16 g_tk_hi[MTOK*D_], g_tk_lo[MTOK*D_];
__device__ f16 g_tv_hi[MTOK*D_], g_tv_lo[MTOK*D_];
__device__ f16 g_wq_hi[D_*D_],  g_wq_lo[D_*D_];
__device__ f16 g_wk_hi[D_*D_],  g_wk_lo[D_*D_];
__device__ f16 g_wv_hi[D_*D_],  g_wv_lo[D_*D_];
__device__ f16 g_wo_hi[D_*D_],  g_wo_lo[D_*D_];
__device__ f16 g_q_hi[MTOK*D_], g_q_lo[MTOK*D_];   // Q proj (A-side), scaled 0.125*64/65
__device__ f16 g_k_hi[MTOK*D_], g_k_lo[MTOK*D_];   // K proj (B-side)
__device__ f16 g_vt_hi[MTOK*D_], g_vt_lo[MTOK*D_]; // V proj (B-side), [bh][d][s]
__device__ f16 g_c_hi[MTOK*D_], g_c_lo[MTOK*D_];   // context (A-side)

// ------------------------- helpers -------------------------
__device__ __forceinline__ uint32_t sptr(const void* p) {
    return (uint32_t)__cvta_generic_to_shared(p);
}
__device__ __forceinline__ void cp16(void* smem, const void* g) {
    asm volatile("cp.async.cg.shared.global [%0], [%1], 16;\n" :: "r"(sptr(smem)), "l"(g));
}
#define CP_COMMIT asm volatile("cp.async.commit_group;\n")

__device__ __forceinline__ void ldsm4(uint32_t* r, uint32_t a) {
    asm volatile("ldmatrix.sync.aligned.m8n8.x4.shared.b16 {%0,%1,%2,%3}, [%4];\n"
        : "=r"(r[0]), "=r"(r[1]), "=r"(r[2]), "=r"(r[3]) : "r"(a));
}
__device__ __forceinline__ void ldsm2(uint32_t* r, uint32_t a) {
    asm volatile("ldmatrix.sync.aligned.m8n8.x2.shared.b16 {%0,%1}, [%2];\n"
        : "=r"(r[0]), "=r"(r[1]) : "r"(a));
}

__device__ __forceinline__ void mma_f16(float c[4], const uint32_t a[4], const uint32_t b[2])
{
    asm volatile(
        "mma.sync.aligned.m16n8k16.row.col.f32.f16.f16.f32 "
        "{%0,%1,%2,%3}, {%4,%5,%6,%7}, {%8,%9}, {%0,%1,%2,%3};\n"
        : "+f"(c[0]), "+f"(c[1]), "+f"(c[2]), "+f"(c[3])
        : "r"(a[0]), "r"(a[1]), "r"(a[2]), "r"(a[3]), "r"(b[0]), "r"(b[1]));
}

// A-side: hi = fp16(v), m = fp16(hi + 64*(v - hi))
__device__ __forceinline__ void store_A(float v, f16* hi, f16* m, size_t i)
{
    __half h = __float2half(v);
    float hf = __half2float(h);
    hi[i] = h;
    m[i] = __float2half(hf + 64.0f*(v - hf));
}
// B-side: hi = fp16(v), m = fp16(hi/64 + (v - hi))
__device__ __forceinline__ void store_B(float v, f16* hi, f16* m, size_t i)
{
    __half h = __float2half(v);
    float hf = __half2float(h);
    hi[i] = h;
    m[i] = __float2half(hf*(1.0f/64.0f) + (v - hf));
}
__device__ __forceinline__ void split2A(float f0, float f1, uint32_t& H, uint32_t& M)
{
    __half h0 = __float2half(f0), h1 = __float2half(f1);
    float g0 = __half2float(h0), g1 = __half2float(h1);
    __half2 hh = __halves2half2(h0, h1);
    __half2 mm = __floats2half2_rn(g0 + 64.0f*(f0 - g0), g1 + 64.0f*(f1 - g1));
    H = *(uint32_t*)&hh;  M = *(uint32_t*)&mm;
}

// proj staging: 128-row x 32-k hi/m tile
__device__ __forceinline__ void stage128(f16* dh, f16* dl,
    const f16* Sh, const f16* Sl, size_t stride, int r0, int kt, int srow, int sch)
{
    size_t a0 = (size_t)(r0 + srow)      * stride + kt + sch;
    size_t a1 = (size_t)(r0 + srow + 64) * stride + kt + sch;
    cp16(dh +  srow      * BKP + sch, Sh + a0);
    cp16(dh + (srow + 64) * BKP + sch, Sh + a1);
    cp16(dl +  srow      * BKP + sch, Sl + a0);
    cp16(dl + (srow + 64) * BKP + sch, Sl + a1);
}

// 32-deep k step via ldmatrix, MT m-frags x 4 n-frags, 2-pass compensated mma
template<int MT>
__device__ __forceinline__ void mma_tileN(uint32_t ah, uint32_t am, uint32_t bh, uint32_t bm,
    int wm, int wn, int lane, float (*acc)[4][4])
{
    const uint32_t aoff = (uint32_t)((lane & 15) * BKP * 2 + (lane >> 4) * 16);
    const uint32_t boff = (uint32_t)((lane & 7) * BKP * 2 + ((lane >> 3) & 1) * 16);
    #pragma unroll
    for (int kk = 0; kk < 32; kk += 16) {
        uint32_t aH[MT][4], aM[MT][4], bH[4][2], bM[4][2];
        #pragma unroll
        for (int mt = 0; mt < MT; ++mt) {
            uint32_t base = (uint32_t)(((wm + mt*16)*BKP + kk) * 2);
            ldsm4(aH[mt], ah + base + aoff);
            ldsm4(aM[mt], am + base + aoff);
        }
        #pragma unroll
        for (int nt = 0; nt < 4; ++nt) {
            uint32_t base = (uint32_t)(((wn + nt*8)*BKP + kk) * 2);
            ldsm2(bH[nt], bh + base + boff);
            ldsm2(bM[nt], bm + base + boff);
        }
        #pragma unroll
        for (int mt = 0; mt < MT; ++mt)
            #pragma unroll
            for (int nt = 0; nt < 4; ++nt) {
                mma_f16(acc[mt][nt], aH[mt], bH[nt]);
                mma_f16(acc[mt][nt], aM[mt], bM[nt]);
            }
    }
}

// ------------------------- split (all 7 tensors, one launch) ----------------
struct SplitArgs {
    const float* src[7];
    f16* hi[7];
    f16* lo[7];
};
#define NT (MTOK*D_)
#define NW (D_*D_)

__global__ __launch_bounds__(256) void split_all_kernel(SplitArgs a)
{
    int bid = blockIdx.x;
    int z, base;
    if (bid < 3 * (NT/256)) { z = bid / (NT/256); base = (bid % (NT/256)) * 256; }
    else { int r = bid - 3*(NT/256); z = 3 + r / (NW/256); base = (r % (NW/256)) * 256; }
    int i = base + threadIdx.x;
    float v = a.src[z][i];
    if (z < 3) store_A(v, a.hi[z], a.lo[z], i);    // activations: A-side
    else       store_B(v, a.hi[z], a.lo[z], i);    // weights: B-side
}

// ------------------------- projection GEMM ----------------------------------
// C = A @ W^T + bias.  modes: 0=A-side flat (Q); 3=B-side flat (K); 2=B-side V-transposed; 1=fp32 out
__device__ __forceinline__ void proj_body(
    const f16* __restrict__ Ahi, const f16* __restrict__ Alo,
    const f16* __restrict__ Whi, const f16* __restrict__ Wlo,
    const float* __restrict__ bias, const float scale, const int mode,
    f16* __restrict__ Ohi, f16* __restrict__ Olo, float* __restrict__ Of)
{
    extern __shared__ f16 sm[];
    #define TA(buf,hl) (sm + ((buf)*2 + (hl)) * (128*BKP))
    #define TB(buf,hl) (sm + (4 + (buf)*2 + (hl)) * (128*BKP))
    const int tid = threadIdx.x, lane = tid & 31, wid = tid >> 5;
    const int g = lane >> 2, t = lane & 3;
    const int wm = (wid >> 2) * 64, wn = (wid & 3) * 32;
    const int m0 = blockIdx.y * 128, n0 = blockIdx.x * 128;
    const int srow = tid >> 2, sch = (tid & 3) * 8;

    float acc[4][4][4] = {};
    stage128(TA(0,0), TA(0,1), Ahi, Alo, D_, m0, 0, srow, sch);
    stage128(TB(0,0), TB(0,1), Whi, Wlo, D_, n0, 0, srow, sch);
    CP_COMMIT;

    for (int kt = 0; kt < D_; kt += 32) {
        const int cur = (kt >> 5) & 1;
        asm volatile("cp.async.wait_group 0;\n");
        __syncthreads();
        if (kt + 32 < D_) {
            stage128(TA(cur^1,0), TA(cur^1,1), Ahi, Alo, D_, m0, kt + 32, srow, sch);
            stage128(TB(cur^1,0), TB(cur^1,1), Whi, Wlo, D_, n0, kt + 32, srow, sch);
            CP_COMMIT;
        }
        mma_tileN<4>(sptr(TA(cur,0)), sptr(TA(cur,1)), sptr(TB(cur,0)), sptr(TB(cur,1)),
                     wm, wn, lane, acc);
        __syncthreads();
    }

    #pragma unroll
    for (int mt = 0; mt < 4; ++mt) {
        int row0 = m0 + wm + mt*16 + g;
        #pragma unroll
        for (int nt = 0; nt < 4; ++nt) {
            int col = n0 + wn + nt*8 + 2*t;
            float v[4];
            v[0] = (acc[mt][nt][0]*CORRF + bias[col])   * scale;
            v[1] = (acc[mt][nt][1]*CORRF + bias[col+1]) * scale;
            v[2] = (acc[mt][nt][2]*CORRF + bias[col])   * scale;
            v[3] = (acc[mt][nt][3]*CORRF + bias[col+1]) * scale;
            size_t i0 = (size_t)row0 * D_ + col, i1 = (size_t)(row0+8) * D_ + col;
            if (mode == 0) {
                store_A(v[0], Ohi, Olo, i0);   store_A(v[1], Ohi, Olo, i0+1);
                store_A(v[2], Ohi, Olo, i1);   store_A(v[3], Ohi, Olo, i1+1);
            } else if (mode == 3) {
                store_B(v[0], Ohi, Olo, i0);   store_B(v[1], Ohi, Olo, i0+1);
                store_B(v[2], Ohi, Olo, i1);   store_B(v[3], Ohi, Olo, i1+1);
            } else if (mode == 1) {
                Of[i0] = v[0]; Of[i0+1] = v[1]; Of[i1] = v[2]; Of[i1+1] = v[3];
            } else {  // V transposed: [bh][d][s], B-side
                #pragma unroll
                for (int e = 0; e < 4; ++e) {
                    int row = row0 + (e >> 1) * 8, c = col + (e & 1);
                    size_t i = (((size_t)(row >> 11) * 16 + (c >> 6)) * 64 + (c & 63)) * S_
                             + (row & (S_-1));
                    store_B(v[e], Ohi, Olo, i);
                }
            }
        }
    }
    #undef TA
    #undef TB
}

struct ProjArgs {
    const f16 *Ah[3], *Al[3], *Wh[3], *Wl[3];
    const float* bias[3];
    f16 *Oh[3], *Ol[3];
};

__global__ __launch_bounds__(256) void proj_qkv_kernel(ProjArgs p)
{
    int z = blockIdx.z;
    // Q: A-side, scale folds 1/8 and the scores-GEMM compensation 64/65
    proj_body(p.Ah[z], p.Al[z], p.Wh[z], p.Wl[z], p.bias[z],
              z == 0 ? 0.125f*CORRF : 1.0f,
              z == 0 ? 0 : (z == 1 ? 3 : 2),
              p.Oh[z], p.Ol[z], nullptr);
}

__global__ __launch_bounds__(256) void proj_o_kernel(
    const f16* Ahi, const f16* Alo, const f16* Whi, const f16* Wlo,
    const float* bias, float* Of)
{
    proj_body(Ahi, Alo, Whi, Wlo, bias, 1.0f, 1, nullptr, nullptr, Of);
}

// ------------------------- flash attention (2 CTAs/SM) ----------------------
#define KCH  64
#define QHL  (64*72)
#define KHL  (64*72)
#define VHL  (64*72)
#define FLASH_SMEM 100352

__device__ __forceinline__ void stage_k64(f16* Ks, int buf, int b, int h, int kt, int kr, int kc)
{
    size_t gk = ((size_t)(b*S_ + kt + kr))*D_ + h*64 + kc;
    f16* d = Ks + buf*(2*KHL) + kr*72 + kc;
    cp16(d,     g_k_hi + gk);
    cp16(d + 8, g_k_hi + gk + 8);
    d += KHL;
    cp16(d,     g_k_lo + gk);
    cp16(d + 8, g_k_lo + gk + 8);
}
__device__ __forceinline__ void stage_v64(f16* Vs, int buf, int bh, int kt, int vr, int vc)
{
    size_t gv = ((size_t)(bh*64 + vr))*S_ + kt + vc;
    f16* d = Vs + buf*(2*VHL) + vr*72 + vc;
    cp16(d,     g_vt_hi + gv);
    cp16(d + 8, g_vt_hi + gv + 8);
    d += VHL;
    cp16(d,     g_vt_lo + gv);
    cp16(d + 8, g_vt_lo + gv + 8);
}

__global__ __launch_bounds__(256, 2) void flash_kernel(const int* __restrict__ mask)
{
    extern __shared__ char smc[];
    f16* Qs = (f16*)smc;                   // [hl][64][72]
    f16* Ks = (f16*)(smc + 18432);         // [buf][hl][64][72]
    f16* Vs = (f16*)(smc + 55296);         // [buf][hl][64][72]
    int* Ms = (int*)(smc + 92160);         // [2048]
    float* red   = (float*)smc;            // [64][68] (post-loop reuse)
    float* lpart = (float*)(smc + 18432);  // [64]

    const int bh = blockIdx.y, b = bh >> 4, h = bh & 15;
    const int q0 = blockIdx.x * 64;
    const int tid = threadIdx.x, lane = tid & 31, wid = tid >> 5;
    const int g = lane >> 2, t = lane & 3;
    const int mg = wid >> 1;
    const int j  = wid & 1;
    const int wn = j * 32;

    const int qr = tid >> 2, qc = (tid & 3) * 16;
    const int kr = tid >> 2, kc = (tid & 3) * 16;

    const uint32_t aoff72 = (uint32_t)((lane & 15) * 144 + (lane >> 4) * 16);
    const uint32_t boff72 = (uint32_t)((lane & 7) * 144 + ((lane >> 3) & 1) * 16);
    const uint32_t qs_base = sptr(Qs);

    {
        size_t gq = ((size_t)(b*S_ + q0 + qr))*D_ + h*64 + qc;
        cp16(Qs +       qr*72 + qc,     g_q_hi + gq);
        cp16(Qs +       qr*72 + qc + 8, g_q_hi + gq + 8);
        cp16(Qs + QHL + qr*72 + qc,     g_q_lo + gq);
        cp16(Qs + QHL + qr*72 + qc + 8, g_q_lo + gq + 8);
        stage_k64(Ks, 0, b, h, 0, kr, kc);
        stage_v64(Vs, 0, bh, 0, kr, kc);
        cp16(Ms + tid*8,     mask + b*S_ + tid*8);
        cp16(Ms + tid*8 + 4, mask + b*S_ + tid*8 + 4);
        CP_COMMIT;
    }

    float acc_o[8][4] = {};
    float ls[2] = {};

    for (int it = 0; it < 32; ++it) {
        const int cur = it & 1;
        if (it < 31) {
            stage_k64(Ks, cur^1, b, h, (it+1)*KCH, kr, kc);
            stage_v64(Vs, cur^1, bh, (it+1)*KCH, kr, kc);
            CP_COMMIT;
            asm volatile("cp.async.wait_group 1;\n");
        } else {
            asm volatile("cp.async.wait_group 0;\n");
        }
        __syncthreads();

        // ---- scores: Q[16q x 64dk] . K_slice[32k x 64dk]^T (2-pass) ----
        float accs[4][4] = {};
        const uint32_t kb  = sptr(Ks + cur*(2*KHL));
        const uint32_t kbm = kb + KHL*2;
        #pragma unroll
        for (int kk = 0; kk < 64; kk += 16) {
            uint32_t aH[4], aM[4], bH[4][2], bM[4][2];
            uint32_t abase = (uint32_t)(((mg*16)*72 + kk) * 2);
            ldsm4(aH, qs_base + abase + aoff72);
            ldsm4(aM, qs_base + QHL*2 + abase + aoff72);
            #pragma unroll
            for (int nt = 0; nt < 4; ++nt) {
                uint32_t base = (uint32_t)(((wn + nt*8)*72 + kk) * 2);
                ldsm2(bH[nt], kb  + base + boff72);
                ldsm2(bM[nt], kbm + base + boff72);
            }
            #pragma unroll
            for (int nt = 0; nt < 4; ++nt) {
                mma_f16(accs[nt], aH, bH[nt]);
                mma_f16(accs[nt], aM, bM[nt]);
            }
        }

        // ---- mask + exp + pack P (A-side pair) ----
        uint32_t pH[2][4], pM[2][4];
        #pragma unroll
        for (int nt = 0; nt < 4; ++nt) {
            int c0 = it*KCH + wn + nt*8 + 2*t;
            bool m0 = Ms[c0] != 0, m1 = Ms[c0+1] != 0;
            float p0 = m0 ? __expf(accs[nt][0]) : 0.f;
            float p1 = m1 ? __expf(accs[nt][1]) : 0.f;
            float p2 = m0 ? __expf(accs[nt][2]) : 0.f;
            float p3 = m1 ? __expf(accs[nt][3]) : 0.f;
            ls[0] += p0 + p1;
            ls[1] += p2 + p3;
            int jj = nt >> 1, hf = (nt & 1) * 2;
            split2A(p0, p1, pH[jj][hf],   pM[jj][hf]);
            split2A(p2, p3, pH[jj][hf+1], pM[jj][hf+1]);
        }

        // ---- P_slice[16q x 32k] . V_slice[32k x 64d] (2-pass) ----
        const uint32_t vb  = sptr(Vs + cur*(2*VHL));
        const uint32_t vbm = vb + VHL*2;
        #pragma unroll
        for (int jj = 0; jj < 2; ++jj) {
            uint32_t bH[8][2], bM[8][2];
            #pragma unroll
            for (int dt = 0; dt < 8; ++dt) {
                uint32_t base = (uint32_t)(((dt*8)*72 + wn + jj*16) * 2);
                ldsm2(bH[dt], vb  + base + boff72);
                ldsm2(bM[dt], vbm + base + boff72);
            }
            #pragma unroll
            for (int dt = 0; dt < 8; ++dt) {
                mma_f16(acc_o[dt], pH[jj], bH[dt]);
                mma_f16(acc_o[dt], pM[jj], bM[dt]);
            }
        }
        __syncthreads();
    }

    // ---- cross-slice reduction ----
    const int r0 = mg*16 + g;
    float s0 = ls[0], s1 = ls[1];
    s0 += __shfl_xor_sync(~0u, s0, 1);  s0 += __shfl_xor_sync(~0u, s0, 2);
    s1 += __shfl_xor_sync(~0u, s1, 1);  s1 += __shfl_xor_sync(~0u, s1, 2);

    #pragma unroll
    for (int round = 0; round < 2; ++round) {
        if (j == round) {
            #pragma unroll
            for (int dt = 0; dt < 8; ++dt) {
                int c = dt*8 + 2*t;
                if (round == 0) {
                    red[r0*68 + c]       = acc_o[dt][0];
                    red[r0*68 + c + 1]   = acc_o[dt][1];
                    red[(r0+8)*68 + c]   = acc_o[dt][2];
                    red[(r0+8)*68 + c+1] = acc_o[dt][3];
                } else {
                    red[r0*68 + c]       += acc_o[dt][0];
                    red[r0*68 + c + 1]   += acc_o[dt][1];
                    red[(r0+8)*68 + c]   += acc_o[dt][2];
                    red[(r0+8)*68 + c+1] += acc_o[dt][3];
                }
            }
            if (t == 0) {
                if (round == 0) { lpart[r0] = s0;  lpart[r0+8] = s1; }
                else            { lpart[r0] += s0; lpart[r0+8] += s1; }
            }
        }
        __syncthreads();
    }

    #pragma unroll
    for (int i = 0; i < 16; ++i) {
        int e = i*256 + tid;
        int row = e >> 6, col = e & 63;
        float v = red[row*68 + col] * CORRF / lpart[row];   // PV compensation folded
        size_t o = ((size_t)(b*S_ + q0 + row))*D_ + h*64 + col;
        store_A(v, g_c_hi, g_c_lo, o);
    }
}

// ------------------------- launch -------------------------
extern "C" void kernel_launch(void* const* d_in, const int* in_sizes, int n_in,
                              void* d_out, int out_size)
{
    const float* query = (const float*)d_in[0];
    const float* key   = (const float*)d_in[1];
    const float* value = (const float*)d_in[2];
    const int*   mask  = (const int*)d_in[3];
    const float* Wq = (const float*)d_in[4];  const float* bq = (const float*)d_in[5];
    const float* Wk = (const float*)d_in[6];  const float* bk = (const float*)d_in[7];
    const float* Wv = (const float*)d_in[8];  const float* bv = (const float*)d_in[9];
    const float* Wo = (const float*)d_in[10]; const float* bo = (const float*)d_in[11];
    float* out = (float*)d_out;

    const int GEMM_SMEM = 8 * 128 * BKP * 2;   // 81920 B
    cudaFuncSetAttribute(proj_qkv_kernel, cudaFuncAttributeMaxDynamicSharedMemorySize, GEMM_SMEM);
    cudaFuncSetAttribute(proj_o_kernel,   cudaFuncAttributeMaxDynamicSharedMemorySize, GEMM_SMEM);
    cudaFuncSetAttribute(flash_kernel,    cudaFuncAttributeMaxDynamicSharedMemorySize, FLASH_SMEM);

    f16 *tqh,*tql,*tkh,*tkl,*tvh,*tvl,*wqh,*wql,*wkh,*wkl,*wvh,*wvl,*woh,*wol;
    f16 *qh,*ql,*kh,*kl,*vth,*vtl,*ch,*cl;
    cudaGetSymbolAddress((void**)&tqh, g_tq_hi); cudaGetSymbolAddress((void**)&tql, g_tq_lo);
    cudaGetSymbolAddress((void**)&tkh, g_tk_hi); cudaGetSymbolAddress((void**)&tkl, g_tk_lo);
    cudaGetSymbolAddress((void**)&tvh, g_tv_hi); cudaGetSymbolAddress((void**)&tvl, g_tv_lo);
    cudaGetSymbolAddress((void**)&wqh, g_wq_hi); cudaGetSymbolAddress((void**)&wql, g_wq_lo);
    cudaGetSymbolAddress((void**)&wkh, g_wk_hi); cudaGetSymbolAddress((void**)&wkl, g_wk_lo);
    cudaGetSymbolAddress((void**)&wvh, g_wv_hi); cudaGetSymbolAddress((void**)&wvl, g_wv_lo);
    cudaGetSymbolAddress((void**)&woh, g_wo_hi); cudaGetSymbolAddress((void**)&wol, g_wo_lo);
    cudaGetSymbolAddress((void**)&qh,  g_q_hi);  cudaGetSymbolAddress((void**)&ql,  g_q_lo);
    cudaGetSymbolAddress((void**)&kh,  g_k_hi);  cudaGetSymbolAddress((void**)&kl,  g_k_lo);
    cudaGetSymbolAddress((void**)&vth, g_vt_hi); cudaGetSymbolAddress((void**)&vtl, g_vt_lo);
    cudaGetSymbolAddress((void**)&ch,  g_c_hi);  cudaGetSymbolAddress((void**)&cl,  g_c_lo);

    SplitArgs sa;
    sa.src[0] = query; sa.hi[0] = tqh; sa.lo[0] = tql;
    sa.src[1] = key;   sa.hi[1] = tkh; sa.lo[1] = tkl;
    sa.src[2] = value; sa.hi[2] = tvh; sa.lo[2] = tvl;
    sa.src[3] = Wq;    sa.hi[3] = wqh; sa.lo[3] = wql;
    sa.src[4] = Wk;    sa.hi[4] = wkh; sa.lo[4] = wkl;
    sa.src[5] = Wv;    sa.hi[5] = wvh; sa.lo[5] = wvl;
    sa.src[6] = Wo;    sa.hi[6] = woh; sa.lo[6] = wol;
    split_all_kernel<<<3*(NT/256) + 4*(NW/256), 256>>>(sa);

    ProjArgs pa;
    pa.Ah[0] = tqh; pa.Al[0] = tql; pa.Wh[0] = wqh; pa.Wl[0] = wql; pa.bias[0] = bq;
    pa.Oh[0] = qh;  pa.Ol[0] = ql;
    pa.Ah[1] = tkh; pa.Al[1] = tkl; pa.Wh[1] = wkh; pa.Wl[1] = wkl; pa.bias[1] = bk;
    pa.Oh[1] = kh;  pa.Ol[1] = kl;
    pa.Ah[2] = tvh; pa.Al[2] = tvl; pa.Wh[2] = wvh; pa.Wl[2] = wvl; pa.bias[2] = bv;
    pa.Oh[2] = vth; pa.Ol[2] = vtl;
    proj_qkv_kernel<<<dim3(D_/128, MTOK/128, 3), 256, GEMM_SMEM>>>(pa);

    flash_kernel<<<dim3(S_/64, BH_), 256, FLASH_SMEM>>>(mask);

    proj_o_kernel<<<dim3(D_/128, MTOK/128), 256, GEMM_SMEM>>>(ch, cl, woh, wol, bo, out);
}

// round 13
// speedup vs baseline: 5.4625x; 1.1041x over previous
#include <cuda_runtime.h>
#include <cuda_fp16.h>
#include <stdint.h>

#define B_   2
#define S_   2048
#define D_   1024
#define MTOK 4096
#define BH_  32
#define BKP  40
#define CORRF (64.0f/65.0f)

typedef __half f16;

// ------------------------- scratch (hi plane, m plane) -------------------------
__device__ f16 g_tq_hi[MTOK*D_], g_tq_lo[MTOK*D_];
__device__ f16 g_tk_hi[MTOK*D_], g_tk_lo[MTOK*D_];
__device__ f16 g_tv_hi[MTOK*D_], g_tv_lo[MTOK*D_];
__device__ f16 g_wq_hi[D_*D_],  g_wq_lo[D_*D_];
__device__ f16 g_wk_hi[D_*D_],  g_wk_lo[D_*D_];
__device__ f16 g_wv_hi[D_*D_],  g_wv_lo[D_*D_];
__device__ f16 g_wo_hi[D_*D_],  g_wo_lo[D_*D_];
__device__ f16 g_q_hi[MTOK*D_], g_q_lo[MTOK*D_];   // Q proj (A-side), scaled 0.125*64/65
__device__ f16 g_k_hi[MTOK*D_], g_k_lo[MTOK*D_];   // K proj (B-side)
__device__ f16 g_vt_hi[MTOK*D_], g_vt_lo[MTOK*D_]; // V proj, [bh][d][s] (flash uses hi only)
__device__ f16 g_c_hi[MTOK*D_], g_c_lo[MTOK*D_];   // context (A-side)

// ------------------------- helpers -------------------------
__device__ __forceinline__ uint32_t sptr(const void* p) {
    return (uint32_t)__cvta_generic_to_shared(p);
}
__device__ __forceinline__ void cp16(void* smem, const void* g) {
    asm volatile("cp.async.cg.shared.global [%0], [%1], 16;\n" :: "r"(sptr(smem)), "l"(g));
}
#define CP_COMMIT asm volatile("cp.async.commit_group;\n")

__device__ __forceinline__ void ldsm4(uint32_t* r, uint32_t a) {
    asm volatile("ldmatrix.sync.aligned.m8n8.x4.shared.b16 {%0,%1,%2,%3}, [%4];\n"
        : "=r"(r[0]), "=r"(r[1]), "=r"(r[2]), "=r"(r[3]) : "r"(a));
}
__device__ __forceinline__ void ldsm2(uint32_t* r, uint32_t a) {
    asm volatile("ldmatrix.sync.aligned.m8n8.x2.shared.b16 {%0,%1}, [%2];\n"
        : "=r"(r[0]), "=r"(r[1]) : "r"(a));
}

__device__ __forceinline__ void mma_f16(float c[4], const uint32_t a[4], const uint32_t b[2])
{
    asm volatile(
        "mma.sync.aligned.m16n8k16.row.col.f32.f16.f16.f32 "
        "{%0,%1,%2,%3}, {%4,%5,%6,%7}, {%8,%9}, {%0,%1,%2,%3};\n"
        : "+f"(c[0]), "+f"(c[1]), "+f"(c[2]), "+f"(c[3])
        : "r"(a[0]), "r"(a[1]), "r"(a[2]), "r"(a[3]), "r"(b[0]), "r"(b[1]));
}

// A-side: hi = fp16(v), m = fp16(hi + 64*(v - hi))
__device__ __forceinline__ void store_A(float v, f16* hi, f16* m, size_t i)
{
    __half h = __float2half(v);
    float hf = __half2float(h);
    hi[i] = h;
    m[i] = __float2half(hf + 64.0f*(v - hf));
}
// B-side: hi = fp16(v), m = fp16(hi/64 + (v - hi))
__device__ __forceinline__ void store_B(float v, f16* hi, f16* m, size_t i)
{
    __half h = __float2half(v);
    float hf = __half2float(h);
    hi[i] = h;
    m[i] = __float2half(hf*(1.0f/64.0f) + (v - hf));
}

// proj staging: 128-row x 32-k hi/m tile
__device__ __forceinline__ void stage128(f16* dh, f16* dl,
    const f16* Sh, const f16* Sl, size_t stride, int r0, int kt, int srow, int sch)
{
    size_t a0 = (size_t)(r0 + srow)      * stride + kt + sch;
    size_t a1 = (size_t)(r0 + srow + 64) * stride + kt + sch;
    cp16(dh +  srow      * BKP + sch, Sh + a0);
    cp16(dh + (srow + 64) * BKP + sch, Sh + a1);
    cp16(dl +  srow      * BKP + sch, Sl + a0);
    cp16(dl + (srow + 64) * BKP + sch, Sl + a1);
}

// 32-deep k step via ldmatrix, MT m-frags x 4 n-frags, 2-pass compensated mma
template<int MT>
__device__ __forceinline__ void mma_tileN(uint32_t ah, uint32_t am, uint32_t bh, uint32_t bm,
    int wm, int wn, int lane, float (*acc)[4][4])
{
    const uint32_t aoff = (uint32_t)((lane & 15) * BKP * 2 + (lane >> 4) * 16);
    const uint32_t boff = (uint32_t)((lane & 7) * BKP * 2 + ((lane >> 3) & 1) * 16);
    #pragma unroll
    for (int kk = 0; kk < 32; kk += 16) {
        uint32_t aH[MT][4], aM[MT][4], bH[4][2], bM[4][2];
        #pragma unroll
        for (int mt = 0; mt < MT; ++mt) {
            uint32_t base = (uint32_t)(((wm + mt*16)*BKP + kk) * 2);
            ldsm4(aH[mt], ah + base + aoff);
            ldsm4(aM[mt], am + base + aoff);
        }
        #pragma unroll
        for (int nt = 0; nt < 4; ++nt) {
            uint32_t base = (uint32_t)(((wn + nt*8)*BKP + kk) * 2);
            ldsm2(bH[nt], bh + base + boff);
            ldsm2(bM[nt], bm + base + boff);
        }
        #pragma unroll
        for (int mt = 0; mt < MT; ++mt)
            #pragma unroll
            for (int nt = 0; nt < 4; ++nt) {
                mma_f16(acc[mt][nt], aH[mt], bH[nt]);
                mma_f16(acc[mt][nt], aM[mt], bM[nt]);
            }
    }
}

// ------------------------- split (all 7 tensors, one launch) ----------------
struct SplitArgs {
    const float* src[7];
    f16* hi[7];
    f16* lo[7];
};
#define NT (MTOK*D_)
#define NW (D_*D_)

__global__ __launch_bounds__(256) void split_all_kernel(SplitArgs a)
{
    int bid = blockIdx.x;
    int z, base;
    if (bid < 3 * (NT/256)) { z = bid / (NT/256); base = (bid % (NT/256)) * 256; }
    else { int r = bid - 3*(NT/256); z = 3 + r / (NW/256); base = (r % (NW/256)) * 256; }
    int i = base + threadIdx.x;
    float v = a.src[z][i];
    if (z < 3) store_A(v, a.hi[z], a.lo[z], i);    // activations: A-side
    else       store_B(v, a.hi[z], a.lo[z], i);    // weights: B-side
}

// ------------------------- projection GEMM ----------------------------------
// C = A @ W^T + bias.  modes: 0=A-side flat (Q); 3=B-side flat (K); 2=B-side V-transposed; 1=fp32 out
__device__ __forceinline__ void proj_body(
    const f16* __restrict__ Ahi, const f16* __restrict__ Alo,
    const f16* __restrict__ Whi, const f16* __restrict__ Wlo,
    const float* __restrict__ bias, const float scale, const int mode,
    f16* __restrict__ Ohi, f16* __restrict__ Olo, float* __restrict__ Of)
{
    extern __shared__ f16 sm[];
    #define TA(buf,hl) (sm + ((buf)*2 + (hl)) * (128*BKP))
    #define TB(buf,hl) (sm + (4 + (buf)*2 + (hl)) * (128*BKP))
    const int tid = threadIdx.x, lane = tid & 31, wid = tid >> 5;
    const int g = lane >> 2, t = lane & 3;
    const int wm = (wid >> 2) * 64, wn = (wid & 3) * 32;
    const int m0 = blockIdx.y * 128, n0 = blockIdx.x * 128;
    const int srow = tid >> 2, sch = (tid & 3) * 8;

    float acc[4][4][4] = {};
    stage128(TA(0,0), TA(0,1), Ahi, Alo, D_, m0, 0, srow, sch);
    stage128(TB(0,0), TB(0,1), Whi, Wlo, D_, n0, 0, srow, sch);
    CP_COMMIT;

    for (int kt = 0; kt < D_; kt += 32) {
        const int cur = (kt >> 5) & 1;
        asm volatile("cp.async.wait_group 0;\n");
        __syncthreads();
        if (kt + 32 < D_) {
            stage128(TA(cur^1,0), TA(cur^1,1), Ahi, Alo, D_, m0, kt + 32, srow, sch);
            stage128(TB(cur^1,0), TB(cur^1,1), Whi, Wlo, D_, n0, kt + 32, srow, sch);
            CP_COMMIT;
        }
        mma_tileN<4>(sptr(TA(cur,0)), sptr(TA(cur,1)), sptr(TB(cur,0)), sptr(TB(cur,1)),
                     wm, wn, lane, acc);
        __syncthreads();
    }

    #pragma unroll
    for (int mt = 0; mt < 4; ++mt) {
        int row0 = m0 + wm + mt*16 + g;
        #pragma unroll
        for (int nt = 0; nt < 4; ++nt) {
            int col = n0 + wn + nt*8 + 2*t;
            float v[4];
            v[0] = (acc[mt][nt][0]*CORRF + bias[col])   * scale;
            v[1] = (acc[mt][nt][1]*CORRF + bias[col+1]) * scale;
            v[2] = (acc[mt][nt][2]*CORRF + bias[col])   * scale;
            v[3] = (acc[mt][nt][3]*CORRF + bias[col+1]) * scale;
            size_t i0 = (size_t)row0 * D_ + col, i1 = (size_t)(row0+8) * D_ + col;
            if (mode == 0) {
                store_A(v[0], Ohi, Olo, i0);   store_A(v[1], Ohi, Olo, i0+1);
                store_A(v[2], Ohi, Olo, i1);   store_A(v[3], Ohi, Olo, i1+1);
            } else if (mode == 3) {
                store_B(v[0], Ohi, Olo, i0);   store_B(v[1], Ohi, Olo, i0+1);
                store_B(v[2], Ohi, Olo, i1);   store_B(v[3], Ohi, Olo, i1+1);
            } else if (mode == 1) {
                Of[i0] = v[0]; Of[i0+1] = v[1]; Of[i1] = v[2]; Of[i1+1] = v[3];
            } else {  // V transposed: [bh][d][s], B-side
                #pragma unroll
                for (int e = 0; e < 4; ++e) {
                    int row = row0 + (e >> 1) * 8, c = col + (e & 1);
                    size_t i = (((size_t)(row >> 11) * 16 + (c >> 6)) * 64 + (c & 63)) * S_
                             + (row & (S_-1));
                    store_B(v[e], Ohi, Olo, i);
                }
            }
        }
    }
    #undef TA
    #undef TB
}

struct ProjArgs {
    const f16 *Ah[3], *Al[3], *Wh[3], *Wl[3];
    const float* bias[3];
    f16 *Oh[3], *Ol[3];
};

__global__ __launch_bounds__(256) void proj_qkv_kernel(ProjArgs p)
{
    int z = blockIdx.z;
    proj_body(p.Ah[z], p.Al[z], p.Wh[z], p.Wl[z], p.bias[z],
              z == 0 ? 0.125f*CORRF : 1.0f,
              z == 0 ? 0 : (z == 1 ? 3 : 2),
              p.Oh[z], p.Ol[z], nullptr);
}

__global__ __launch_bounds__(256) void proj_o_kernel(
    const f16* Ahi, const f16* Alo, const f16* Whi, const f16* Wlo,
    const float* bias, float* Of)
{
    proj_body(Ahi, Alo, Whi, Wlo, bias, 1.0f, 1, nullptr, nullptr, Of);
}

// ------------------------- flash attention (2 CTAs/SM) ----------------------
// smem: Qs 18432 | Ks 36864 | Vs 18432 (hi only) | Ms 8192 = 81920 bytes
#define KCH  64
#define QHL  (64*72)
#define KHL  (64*72)
#define VPL  (64*72)
#define FLASH_SMEM 81920

__device__ __forceinline__ void stage_k64(f16* Ks, int buf, int b, int h, int kt, int kr, int kc)
{
    size_t gk = ((size_t)(b*S_ + kt + kr))*D_ + h*64 + kc;
    f16* d = Ks + buf*(2*KHL) + kr*72 + kc;
    cp16(d,     g_k_hi + gk);
    cp16(d + 8, g_k_hi + gk + 8);
    d += KHL;
    cp16(d,     g_k_lo + gk);
    cp16(d + 8, g_k_lo + gk + 8);
}
// V: hi plane only (1-pass PV). 64 d-rows x 64 tokens: vr=tid>>2 (0..63), vc=(tid&3)*16
__device__ __forceinline__ void stage_v64(f16* Vs, int buf, int bh, int kt, int vr, int vc)
{
    size_t gv = ((size_t)(bh*64 + vr))*S_ + kt + vc;
    f16* d = Vs + buf*VPL + vr*72 + vc;
    cp16(d,     g_vt_hi + gv);
    cp16(d + 8, g_vt_hi + gv + 8);
}

__global__ __launch_bounds__(256, 2) void flash_kernel(const int* __restrict__ mask)
{
    extern __shared__ char smc[];
    f16* Qs = (f16*)smc;                   // [hl][64][72]
    f16* Ks = (f16*)(smc + 18432);         // [buf][hl][64][72]
    f16* Vs = (f16*)(smc + 55296);         // [buf][64][72]  hi only
    int* Ms = (int*)(smc + 73728);         // [2048]
    float* red   = (float*)smc;            // [64][68] (post-loop reuse)
    float* lpart = (float*)(smc + 18432);  // [64]

    const int bh = blockIdx.y, b = bh >> 4, h = bh & 15;
    const int q0 = blockIdx.x * 64;
    const int tid = threadIdx.x, lane = tid & 31, wid = tid >> 5;
    const int g = lane >> 2, t = lane & 3;
    const int mg = wid >> 1;
    const int j  = wid & 1;
    const int wn = j * 32;

    const int qr = tid >> 2, qc = (tid & 3) * 16;
    const int kr = tid >> 2, kc = (tid & 3) * 16;

    const uint32_t aoff72 = (uint32_t)((lane & 15) * 144 + (lane >> 4) * 16);
    const uint32_t boff72 = (uint32_t)((lane & 7) * 144 + ((lane >> 3) & 1) * 16);
    const uint32_t qs_base = sptr(Qs);

    {
        size_t gq = ((size_t)(b*S_ + q0 + qr))*D_ + h*64 + qc;
        cp16(Qs +       qr*72 + qc,     g_q_hi + gq);
        cp16(Qs +       qr*72 + qc + 8, g_q_hi + gq + 8);
        cp16(Qs + QHL + qr*72 + qc,     g_q_lo + gq);
        cp16(Qs + QHL + qr*72 + qc + 8, g_q_lo + gq + 8);
        stage_k64(Ks, 0, b, h, 0, kr, kc);
        stage_v64(Vs, 0, bh, 0, kr, kc);
        cp16(Ms + tid*8,     mask + b*S_ + tid*8);
        cp16(Ms + tid*8 + 4, mask + b*S_ + tid*8 + 4);
        CP_COMMIT;
    }

    float acc_o[8][4] = {};
    float ls[2] = {};

    for (int it = 0; it < 32; ++it) {
        const int cur = it & 1;
        if (it < 31) {
            stage_k64(Ks, cur^1, b, h, (it+1)*KCH, kr, kc);
            stage_v64(Vs, cur^1, bh, (it+1)*KCH, kr, kc);
            CP_COMMIT;
            asm volatile("cp.async.wait_group 1;\n");
        } else {
            asm volatile("cp.async.wait_group 0;\n");
        }
        __syncthreads();

        // ---- scores: Q[16q x 64dk] . K_slice[32k x 64dk]^T (2-pass) ----
        float accs[4][4] = {};
        const uint32_t kb  = sptr(Ks + cur*(2*KHL));
        const uint32_t kbm = kb + KHL*2;
        #pragma unroll
        for (int kk = 0; kk < 64; kk += 16) {
            uint32_t aH[4], aM[4], bH[4][2], bM[4][2];
            uint32_t abase = (uint32_t)(((mg*16)*72 + kk) * 2);
            ldsm4(aH, qs_base + abase + aoff72);
            ldsm4(aM, qs_base + QHL*2 + abase + aoff72);
            #pragma unroll
            for (int nt = 0; nt < 4; ++nt) {
                uint32_t base = (uint32_t)(((wn + nt*8)*72 + kk) * 2);
                ldsm2(bH[nt], kb  + base + boff72);
                ldsm2(bM[nt], kbm + base + boff72);
            }
            #pragma unroll
            for (int nt = 0; nt < 4; ++nt) {
                mma_f16(accs[nt], aH, bH[nt]);
                mma_f16(accs[nt], aM, bM[nt]);
            }
        }

        // ---- mask + exp + pack P (single fp16 plane) ----
        uint32_t pP[2][4];
        #pragma unroll
        for (int nt = 0; nt < 4; ++nt) {
            int c0 = it*KCH + wn + nt*8 + 2*t;
            bool m0 = Ms[c0] != 0, m1 = Ms[c0+1] != 0;
            float p0 = m0 ? __expf(accs[nt][0]) : 0.f;
            float p1 = m1 ? __expf(accs[nt][1]) : 0.f;
            float p2 = m0 ? __expf(accs[nt][2]) : 0.f;
            float p3 = m1 ? __expf(accs[nt][3]) : 0.f;
            ls[0] += p0 + p1;
            ls[1] += p2 + p3;
            int jj = nt >> 1, hf = (nt & 1) * 2;
            __half2 h01 = __floats2half2_rn(p0, p1);
            __half2 h23 = __floats2half2_rn(p2, p3);
            pP[jj][hf]   = *(uint32_t*)&h01;
            pP[jj][hf+1] = *(uint32_t*)&h23;
        }

        // ---- P_slice[16q x 32k] . V_slice[32k x 64d] (1-pass) ----
        const uint32_t vb = sptr(Vs + cur*VPL);
        #pragma unroll
        for (int jj = 0; jj < 2; ++jj) {
            uint32_t bH[8][2];
            #pragma unroll
            for (int dt = 0; dt < 8; ++dt) {
                uint32_t base = (uint32_t)(((dt*8)*72 + wn + jj*16) * 2);
                ldsm2(bH[dt], vb + base + boff72);
            }
            #pragma unroll
            for (int dt = 0; dt < 8; ++dt)
                mma_f16(acc_o[dt], pP[jj], bH[dt]);
        }
        __syncthreads();
    }

    // ---- cross-slice reduction ----
    const int r0 = mg*16 + g;
    float s0 = ls[0], s1 = ls[1];
    s0 += __shfl_xor_sync(~0u, s0, 1);  s0 += __shfl_xor_sync(~0u, s0, 2);
    s1 += __shfl_xor_sync(~0u, s1, 1);  s1 += __shfl_xor_sync(~0u, s1, 2);

    #pragma unroll
    for (int round = 0; round < 2; ++round) {
        if (j == round) {
            #pragma unroll
            for (int dt = 0; dt < 8; ++dt) {
                int c = dt*8 + 2*t;
                if (round == 0) {
                    red[r0*68 + c]       = acc_o[dt][0];
                    red[r0*68 + c + 1]   = acc_o[dt][1];
                    red[(r0+8)*68 + c]   = acc_o[dt][2];
                    red[(r0+8)*68 + c+1] = acc_o[dt][3];
                } else {
                    red[r0*68 + c]       += acc_o[dt][0];
                    red[r0*68 + c + 1]   += acc_o[dt][1];
                    red[(r0+8)*68 + c]   += acc_o[dt][2];
                    red[(r0+8)*68 + c+1] += acc_o[dt][3];
                }
            }
            if (t == 0) {
                if (round == 0) { lpart[r0] = s0;  lpart[r0+8] = s1; }
                else            { lpart[r0] += s0; lpart[r0+8] += s1; }
            }
        }
        __syncthreads();
    }

    #pragma unroll
    for (int i = 0; i < 16; ++i) {
        int e = i*256 + tid;
        int row = e >> 6, col = e & 63;
        float v = red[row*68 + col] / lpart[row];   // 1-pass PV: no scale compensation
        size_t o = ((size_t)(b*S_ + q0 + row))*D_ + h*64 + col;
        store_A(v, g_c_hi, g_c_lo, o);
    }
}

// ------------------------- launch -------------------------
extern "C" void kernel_launch(void* const* d_in, const int* in_sizes, int n_in,
                              void* d_out, int out_size)
{
    const float* query = (const float*)d_in[0];
    const float* key   = (const float*)d_in[1];
    const float* value = (const float*)d_in[2];
    const int*   mask  = (const int*)d_in[3];
    const float* Wq = (const float*)d_in[4];  const float* bq = (const float*)d_in[5];
    const float* Wk = (const float*)d_in[6];  const float* bk = (const float*)d_in[7];
    const float* Wv = (const float*)d_in[8];  const float* bv = (const float*)d_in[9];
    const float* Wo = (const float*)d_in[10]; const float* bo = (const float*)d_in[11];
    float* out = (float*)d_out;

    const int GEMM_SMEM = 8 * 128 * BKP * 2;   // 81920 B
    cudaFuncSetAttribute(proj_qkv_kernel, cudaFuncAttributeMaxDynamicSharedMemorySize, GEMM_SMEM);
    cudaFuncSetAttribute(proj_o_kernel,   cudaFuncAttributeMaxDynamicSharedMemorySize, GEMM_SMEM);
    cudaFuncSetAttribute(flash_kernel,    cudaFuncAttributeMaxDynamicSharedMemorySize, FLASH_SMEM);

    f16 *tqh,*tql,*tkh,*tkl,*tvh,*tvl,*wqh,*wql,*wkh,*wkl,*wvh,*wvl,*woh,*wol;
    f16 *qh,*ql,*kh,*kl,*vth,*vtl,*ch,*cl;
    cudaGetSymbolAddress((void**)&tqh, g_tq_hi); cudaGetSymbolAddress((void**)&tql, g_tq_lo);
    cudaGetSymbolAddress((void**)&tkh, g_tk_hi); cudaGetSymbolAddress((void**)&tkl, g_tk_lo);
    cudaGetSymbolAddress((void**)&tvh, g_tv_hi); cudaGetSymbolAddress((void**)&tvl, g_tv_lo);
    cudaGetSymbolAddress((void**)&wqh, g_wq_hi); cudaGetSymbolAddress((void**)&wql, g_wq_lo);
    cudaGetSymbolAddress((void**)&wkh, g_wk_hi); cudaGetSymbolAddress((void**)&wkl, g_wk_lo);
    cudaGetSymbolAddress((void**)&wvh, g_wv_hi); cudaGetSymbolAddress((void**)&wvl, g_wv_lo);
    cudaGetSymbolAddress((void**)&woh, g_wo_hi); cudaGetSymbolAddress((void**)&wol, g_wo_lo);
    cudaGetSymbolAddress((void**)&qh,  g_q_hi);  cudaGetSymbolAddress((void**)&ql,  g_q_lo);
    cudaGetSymbolAddress((void**)&kh,  g_k_hi);  cudaGetSymbolAddress((void**)&kl,  g_k_lo);
    cudaGetSymbolAddress((void**)&vth, g_vt_hi); cudaGetSymbolAddress((void**)&vtl, g_vt_lo);
    cudaGetSymbolAddress((void**)&ch,  g_c_hi);  cudaGetSymbolAddress((void**)&cl,  g_c_lo);

    SplitArgs sa;
    sa.src[0] = query; sa.hi[0] = tqh; sa.lo[0] = tql;
    sa.src[1] = key;   sa.hi[1] = tkh; sa.lo[1] = tkl;
    sa.src[2] = value; sa.hi[2] = tvh; sa.lo[2] = tvl;
    sa.src[3] = Wq;    sa.hi[3] = wqh; sa.lo[3] = wql;
    sa.src[4] = Wk;    sa.hi[4] = wkh; sa.lo[4] = wkl;
    sa.src[5] = Wv;    sa.hi[5] = wvh; sa.lo[5] = wvl;
    sa.src[6] = Wo;    sa.hi[6] = woh; sa.lo[6] = wol;
    split_all_kernel<<<3*(NT/256) + 4*(NW/256), 256>>>(sa);

    ProjArgs pa;
    pa.Ah[0] = tqh; pa.Al[0] = tql; pa.Wh[0] = wqh; pa.Wl[0] = wql; pa.bias[0] = bq;
    pa.Oh[0] = qh;  pa.Ol[0] = ql;
    pa.Ah[1] = tkh; pa.Al[1] = tkl; pa.Wh[1] = wkh; pa.Wl[1] = wkl; pa.bias[1] = bk;
    pa.Oh[1] = kh;  pa.Ol[1] = kl;
    pa.Ah[2] = tvh; pa.Al[2] = tvl; pa.Wh[2] = wvh; pa.Wl[2] = wvl; pa.bias[2] = bv;
    pa.Oh[2] = vth; pa.Ol[2] = vtl;
    proj_qkv_kernel<<<dim3(D_/128, MTOK/128, 3), 256, GEMM_SMEM>>>(pa);

    flash_kernel<<<dim3(S_/64, BH_), 256, FLASH_SMEM>>>(mask);

    proj_o_kernel<<<dim3(D_/128, MTOK/128), 256, GEMM_SMEM>>>(ch, cl, woh, wol, bo, out);
}

// round 14
// speedup vs baseline: 6.5085x; 1.1915x over previous
#include <cuda_runtime.h>
#include <cuda_fp16.h>
#include <stdint.h>

#define B_   2
#define S_   2048
#define D_   1024
#define MTOK 4096
#define BH_  32
#define BKP  40
#define CORRF (64.0f/65.0f)

typedef __half f16;

// ------------------------- scratch -------------------------
__device__ f16 g_tq_hi[MTOK*D_], g_tq_lo[MTOK*D_];
__device__ f16 g_tk_hi[MTOK*D_], g_tk_lo[MTOK*D_];
__device__ f16 g_tv_hi[MTOK*D_], g_tv_lo[MTOK*D_];
__device__ f16 g_wq_hi[D_*D_],  g_wq_lo[D_*D_];
__device__ f16 g_wk_hi[D_*D_],  g_wk_lo[D_*D_];
__device__ f16 g_wv_hi[D_*D_],  g_wv_lo[D_*D_];
__device__ f16 g_wo_hi[D_*D_],  g_wo_lo[D_*D_];
__device__ f16 g_q[MTOK*D_];                        // Q proj fp16, scaled 1/8
__device__ f16 g_k[MTOK*D_];                        // K proj fp16
__device__ f16 g_vt[MTOK*D_];                       // V proj fp16, [bh][d][s]
__device__ f16 g_c_hi[MTOK*D_], g_c_lo[MTOK*D_];    // context (A-side pair)

// ------------------------- helpers -------------------------
__device__ __forceinline__ uint32_t sptr(const void* p) {
    return (uint32_t)__cvta_generic_to_shared(p);
}
__device__ __forceinline__ void cp16(void* smem, const void* g) {
    asm volatile("cp.async.cg.shared.global [%0], [%1], 16;\n" :: "r"(sptr(smem)), "l"(g));
}
#define CP_COMMIT asm volatile("cp.async.commit_group;\n")

__device__ __forceinline__ void ldsm4(uint32_t* r, uint32_t a) {
    asm volatile("ldmatrix.sync.aligned.m8n8.x4.shared.b16 {%0,%1,%2,%3}, [%4];\n"
        : "=r"(r[0]), "=r"(r[1]), "=r"(r[2]), "=r"(r[3]) : "r"(a));
}
__device__ __forceinline__ void ldsm2(uint32_t* r, uint32_t a) {
    asm volatile("ldmatrix.sync.aligned.m8n8.x2.shared.b16 {%0,%1}, [%2];\n"
        : "=r"(r[0]), "=r"(r[1]) : "r"(a));
}

__device__ __forceinline__ void mma_f16(float c[4], const uint32_t a[4], const uint32_t b[2])
{
    asm volatile(
        "mma.sync.aligned.m16n8k16.row.col.f32.f16.f16.f32 "
        "{%0,%1,%2,%3}, {%4,%5,%6,%7}, {%8,%9}, {%0,%1,%2,%3};\n"
        : "+f"(c[0]), "+f"(c[1]), "+f"(c[2]), "+f"(c[3])
        : "r"(a[0]), "r"(a[1]), "r"(a[2]), "r"(a[3]), "r"(b[0]), "r"(b[1]));
}

// A-side pair: hi = fp16(v), m = fp16(hi + 64*(v - hi))
__device__ __forceinline__ void store_A(float v, f16* hi, f16* m, size_t i)
{
    __half h = __float2half(v);
    float hf = __half2float(h);
    hi[i] = h;
    m[i] = __float2half(hf + 64.0f*(v - hf));
}
// B-side pair: hi = fp16(v), m = fp16(hi/64 + (v - hi))
__device__ __forceinline__ void store_B(float v, f16* hi, f16* m, size_t i)
{
    __half h = __float2half(v);
    float hf = __half2float(h);
    hi[i] = h;
    m[i] = __float2half(hf*(1.0f/64.0f) + (v - hf));
}

// proj staging: 128-row x 32-k hi/m tile
__device__ __forceinline__ void stage128(f16* dh, f16* dl,
    const f16* Sh, const f16* Sl, size_t stride, int r0, int kt, int srow, int sch)
{
    size_t a0 = (size_t)(r0 + srow)      * stride + kt + sch;
    size_t a1 = (size_t)(r0 + srow + 64) * stride + kt + sch;
    cp16(dh +  srow      * BKP + sch, Sh + a0);
    cp16(dh + (srow + 64) * BKP + sch, Sh + a1);
    cp16(dl +  srow      * BKP + sch, Sl + a0);
    cp16(dl + (srow + 64) * BKP + sch, Sl + a1);
}

// 32-deep k step via ldmatrix, MT m-frags x 4 n-frags, 2-pass compensated mma
template<int MT>
__device__ __forceinline__ void mma_tileN(uint32_t ah, uint32_t am, uint32_t bh, uint32_t bm,
    int wm, int wn, int lane, float (*acc)[4][4])
{
    const uint32_t aoff = (uint32_t)((lane & 15) * BKP * 2 + (lane >> 4) * 16);
    const uint32_t boff = (uint32_t)((lane & 7) * BKP * 2 + ((lane >> 3) & 1) * 16);
    #pragma unroll
    for (int kk = 0; kk < 32; kk += 16) {
        uint32_t aH[MT][4], aM[MT][4], bH[4][2], bM[4][2];
        #pragma unroll
        for (int mt = 0; mt < MT; ++mt) {
            uint32_t base = (uint32_t)(((wm + mt*16)*BKP + kk) * 2);
            ldsm4(aH[mt], ah + base + aoff);
            ldsm4(aM[mt], am + base + aoff);
        }
        #pragma unroll
        for (int nt = 0; nt < 4; ++nt) {
            uint32_t base = (uint32_t)(((wn + nt*8)*BKP + kk) * 2);
            ldsm2(bH[nt], bh + base + boff);
            ldsm2(bM[nt], bm + base + boff);
        }
        #pragma unroll
        for (int mt = 0; mt < MT; ++mt)
            #pragma unroll
            for (int nt = 0; nt < 4; ++nt) {
                mma_f16(acc[mt][nt], aH[mt], bH[nt]);
                mma_f16(acc[mt][nt], aM[mt], bM[nt]);
            }
    }
}

// ------------------------- split (all 7 tensors, one launch) ----------------
struct SplitArgs {
    const float* src[7];
    f16* hi[7];
    f16* lo[7];
};
#define NT (MTOK*D_)
#define NW (D_*D_)

__global__ __launch_bounds__(256) void split_all_kernel(SplitArgs a)
{
    int bid = blockIdx.x;
    int z, base;
    if (bid < 3 * (NT/256)) { z = bid / (NT/256); base = (bid % (NT/256)) * 256; }
    else { int r = bid - 3*(NT/256); z = 3 + r / (NW/256); base = (r % (NW/256)) * 256; }
    int i = base + threadIdx.x;
    float v = a.src[z][i];
    if (z < 3) store_A(v, a.hi[z], a.lo[z], i);    // activations: A-side
    else       store_B(v, a.hi[z], a.lo[z], i);    // weights: B-side
}

// ------------------------- projection GEMM ----------------------------------
// C = A @ W^T + bias.
// modes: 0 = fp16 flat (Q/K, hi only); 2 = fp16 V-transposed (hi only); 1 = fp32 out
__device__ __forceinline__ void proj_body(
    const f16* __restrict__ Ahi, const f16* __restrict__ Alo,
    const f16* __restrict__ Whi, const f16* __restrict__ Wlo,
    const float* __restrict__ bias, const float scale, const int mode,
    f16* __restrict__ Oh, float* __restrict__ Of)
{
    extern __shared__ f16 sm[];
    #define TA(buf,hl) (sm + ((buf)*2 + (hl)) * (128*BKP))
    #define TB(buf,hl) (sm + (4 + (buf)*2 + (hl)) * (128*BKP))
    const int tid = threadIdx.x, lane = tid & 31, wid = tid >> 5;
    const int g = lane >> 2, t = lane & 3;
    const int wm = (wid >> 2) * 64, wn = (wid & 3) * 32;
    const int m0 = blockIdx.y * 128, n0 = blockIdx.x * 128;
    const int srow = tid >> 2, sch = (tid & 3) * 8;

    float acc[4][4][4] = {};
    stage128(TA(0,0), TA(0,1), Ahi, Alo, D_, m0, 0, srow, sch);
    stage128(TB(0,0), TB(0,1), Whi, Wlo, D_, n0, 0, srow, sch);
    CP_COMMIT;

    for (int kt = 0; kt < D_; kt += 32) {
        const int cur = (kt >> 5) & 1;
        asm volatile("cp.async.wait_group 0;\n");
        __syncthreads();
        if (kt + 32 < D_) {
            stage128(TA(cur^1,0), TA(cur^1,1), Ahi, Alo, D_, m0, kt + 32, srow, sch);
            stage128(TB(cur^1,0), TB(cur^1,1), Whi, Wlo, D_, n0, kt + 32, srow, sch);
            CP_COMMIT;
        }
        mma_tileN<4>(sptr(TA(cur,0)), sptr(TA(cur,1)), sptr(TB(cur,0)), sptr(TB(cur,1)),
                     wm, wn, lane, acc);
        __syncthreads();
    }

    #pragma unroll
    for (int mt = 0; mt < 4; ++mt) {
        int row0 = m0 + wm + mt*16 + g;
        #pragma unroll
        for (int nt = 0; nt < 4; ++nt) {
            int col = n0 + wn + nt*8 + 2*t;
            float v[4];
            v[0] = (acc[mt][nt][0]*CORRF + bias[col])   * scale;
            v[1] = (acc[mt][nt][1]*CORRF + bias[col+1]) * scale;
            v[2] = (acc[mt][nt][2]*CORRF + bias[col])   * scale;
            v[3] = (acc[mt][nt][3]*CORRF + bias[col+1]) * scale;
            size_t i0 = (size_t)row0 * D_ + col, i1 = (size_t)(row0+8) * D_ + col;
            if (mode == 0) {
                __half2 a01 = __floats2half2_rn(v[0], v[1]);
                __half2 a23 = __floats2half2_rn(v[2], v[3]);
                *(uint32_t*)(Oh + i0) = *(uint32_t*)&a01;
                *(uint32_t*)(Oh + i1) = *(uint32_t*)&a23;
            } else if (mode == 1) {
                Of[i0] = v[0]; Of[i0+1] = v[1]; Of[i1] = v[2]; Of[i1+1] = v[3];
            } else {  // V transposed: [bh][d][s]
                #pragma unroll
                for (int e = 0; e < 4; ++e) {
                    int row = row0 + (e >> 1) * 8, c = col + (e & 1);
                    size_t i = (((size_t)(row >> 11) * 16 + (c >> 6)) * 64 + (c & 63)) * S_
                             + (row & (S_-1));
                    Oh[i] = __float2half(v[e]);
                }
            }
        }
    }
    #undef TA
    #undef TB
}

struct ProjArgs {
    const f16 *Ah[3], *Al[3], *Wh[3], *Wl[3];
    const float* bias[3];
    f16 *Oh[3];
};

__global__ __launch_bounds__(256) void proj_qkv_kernel(ProjArgs p)
{
    int z = blockIdx.z;
    proj_body(p.Ah[z], p.Al[z], p.Wh[z], p.Wl[z], p.bias[z],
              z == 0 ? 0.125f : 1.0f,
              z == 2 ? 2 : 0,
              p.Oh[z], nullptr);
}

__global__ __launch_bounds__(256) void proj_o_kernel(
    const f16* Ahi, const f16* Alo, const f16* Whi, const f16* Wlo,
    const float* bias, float* Of)
{
    proj_body(Ahi, Alo, Whi, Wlo, bias, 1.0f, 1, nullptr, Of);
}

// ------------------------- flash attention (2 CTAs/SM, 1-pass QK+PV) --------
// smem: Qs 9216 | Ks 18432 | Vs 18432 | Ms 8192 = 54272 bytes
#define KCH  64
#define KPL  (64*72)
#define FLASH_SMEM 54272

__global__ __launch_bounds__(256, 2) void flash_kernel(const int* __restrict__ mask)
{
    extern __shared__ char smc[];
    f16* Qs = (f16*)smc;                   // [64][72]
    f16* Ks = (f16*)(smc + 9216);          // [buf][64][72]
    f16* Vs = (f16*)(smc + 27648);         // [buf][64][72]
    int* Ms = (int*)(smc + 46080);         // [2048]
    float* red   = (float*)smc;            // [64][68] (post-loop reuse)
    float* lpart = (float*)(smc + 18432);  // [64]

    const int bh = blockIdx.y, b = bh >> 4, h = bh & 15;
    const int q0 = blockIdx.x * 64;
    const int tid = threadIdx.x, lane = tid & 31, wid = tid >> 5;
    const int g = lane >> 2, t = lane & 3;
    const int mg = wid >> 1;
    const int j  = wid & 1;
    const int wn = j * 32;

    const int kr = tid >> 2, kc = (tid & 3) * 16;

    const uint32_t aoff72 = (uint32_t)((lane & 15) * 144 + (lane >> 4) * 16);
    const uint32_t boff72 = (uint32_t)((lane & 7) * 144 + ((lane >> 3) & 1) * 16);
    const uint32_t qs_base = sptr(Qs);

    {
        size_t gq = ((size_t)(b*S_ + q0 + kr))*D_ + h*64 + kc;
        cp16(Qs + kr*72 + kc,     g_q + gq);
        cp16(Qs + kr*72 + kc + 8, g_q + gq + 8);
        size_t gk = ((size_t)(b*S_ + kr))*D_ + h*64 + kc;
        cp16(Ks + kr*72 + kc,     g_k + gk);
        cp16(Ks + kr*72 + kc + 8, g_k + gk + 8);
        size_t gv = ((size_t)(bh*64 + kr))*S_ + kc;
        cp16(Vs + kr*72 + kc,     g_vt + gv);
        cp16(Vs + kr*72 + kc + 8, g_vt + gv + 8);
        cp16(Ms + tid*8,     mask + b*S_ + tid*8);
        cp16(Ms + tid*8 + 4, mask + b*S_ + tid*8 + 4);
        CP_COMMIT;
    }

    float acc_o[8][4] = {};
    float ls[2] = {};

    for (int it = 0; it < 32; ++it) {
        const int cur = it & 1;
        if (it < 31) {
            size_t gk = ((size_t)(b*S_ + (it+1)*KCH + kr))*D_ + h*64 + kc;
            f16* dk = Ks + (cur^1)*KPL + kr*72 + kc;
            cp16(dk,     g_k + gk);
            cp16(dk + 8, g_k + gk + 8);
            size_t gv = ((size_t)(bh*64 + kr))*S_ + (it+1)*KCH + kc;
            f16* dv = Vs + (cur^1)*KPL + kr*72 + kc;
            cp16(dv,     g_vt + gv);
            cp16(dv + 8, g_vt + gv + 8);
            CP_COMMIT;
            asm volatile("cp.async.wait_group 1;\n");
        } else {
            asm volatile("cp.async.wait_group 0;\n");
        }
        __syncthreads();

        // ---- scores: Q[16q x 64dk] . K_slice[32k x 64dk]^T (1-pass) ----
        float accs[4][4] = {};
        const uint32_t kb = sptr(Ks + cur*KPL);
        #pragma unroll
        for (int kk = 0; kk < 64; kk += 16) {
            uint32_t aH[4], bHf[4][2];
            uint32_t abase = (uint32_t)(((mg*16)*72 + kk) * 2);
            ldsm4(aH, qs_base + abase + aoff72);
            #pragma unroll
            for (int nt = 0; nt < 4; ++nt) {
                uint32_t base = (uint32_t)(((wn + nt*8)*72 + kk) * 2);
                ldsm2(bHf[nt], kb + base + boff72);
            }
            #pragma unroll
            for (int nt = 0; nt < 4; ++nt)
                mma_f16(accs[nt], aH, bHf[nt]);
        }

        // ---- mask + exp + pack P ----
        uint32_t pP[2][4];
        #pragma unroll
        for (int nt = 0; nt < 4; ++nt) {
            int c0 = it*KCH + wn + nt*8 + 2*t;
            bool m0 = Ms[c0] != 0, m1 = Ms[c0+1] != 0;
            float p0 = m0 ? __expf(accs[nt][0]) : 0.f;
            float p1 = m1 ? __expf(accs[nt][1]) : 0.f;
            float p2 = m0 ? __expf(accs[nt][2]) : 0.f;
            float p3 = m1 ? __expf(accs[nt][3]) : 0.f;
            ls[0] += p0 + p1;
            ls[1] += p2 + p3;
            int jj = nt >> 1, hf = (nt & 1) * 2;
            __half2 h01 = __floats2half2_rn(p0, p1);
            __half2 h23 = __floats2half2_rn(p2, p3);
            pP[jj][hf]   = *(uint32_t*)&h01;
            pP[jj][hf+1] = *(uint32_t*)&h23;
        }

        // ---- P_slice[16q x 32k] . V_slice[32k x 64d] (1-pass) ----
        const uint32_t vb = sptr(Vs + cur*KPL);
        #pragma unroll
        for (int jj = 0; jj < 2; ++jj) {
            uint32_t bHf[8][2];
            #pragma unroll
            for (int dt = 0; dt < 8; ++dt) {
                uint32_t base = (uint32_t)(((dt*8)*72 + wn + jj*16) * 2);
                ldsm2(bHf[dt], vb + base + boff72);
            }
            #pragma unroll
            for (int dt = 0; dt < 8; ++dt)
                mma_f16(acc_o[dt], pP[jj], bHf[dt]);
        }
        __syncthreads();
    }

    // ---- cross-slice reduction ----
    const int r0 = mg*16 + g;
    float s0 = ls[0], s1 = ls[1];
    s0 += __shfl_xor_sync(~0u, s0, 1);  s0 += __shfl_xor_sync(~0u, s0, 2);
    s1 += __shfl_xor_sync(~0u, s1, 1);  s1 += __shfl_xor_sync(~0u, s1, 2);

    #pragma unroll
    for (int round = 0; round < 2; ++round) {
        if (j == round) {
            #pragma unroll
            for (int dt = 0; dt < 8; ++dt) {
                int c = dt*8 + 2*t;
                if (round == 0) {
                    red[r0*68 + c]       = acc_o[dt][0];
                    red[r0*68 + c + 1]   = acc_o[dt][1];
                    red[(r0+8)*68 + c]   = acc_o[dt][2];
                    red[(r0+8)*68 + c+1] = acc_o[dt][3];
                } else {
                    red[r0*68 + c]       += acc_o[dt][0];
                    red[r0*68 + c + 1]   += acc_o[dt][1];
                    red[(r0+8)*68 + c]   += acc_o[dt][2];
                    red[(r0+8)*68 + c+1] += acc_o[dt][3];
                }
            }
            if (t == 0) {
                if (round == 0) { lpart[r0] = s0;  lpart[r0+8] = s1; }
                else            { lpart[r0] += s0; lpart[r0+8] += s1; }
            }
        }
        __syncthreads();
    }

    #pragma unroll
    for (int i = 0; i < 16; ++i) {
        int e = i*256 + tid;
        int row = e >> 6, col = e & 63;
        float v = red[row*68 + col] / lpart[row];
        size_t o = ((size_t)(b*S_ + q0 + row))*D_ + h*64 + col;
        store_A(v, g_c_hi, g_c_lo, o);
    }
}

// ------------------------- launch -------------------------
extern "C" void kernel_launch(void* const* d_in, const int* in_sizes, int n_in,
                              void* d_out, int out_size)
{
    const float* query = (const float*)d_in[0];
    const float* key   = (const float*)d_in[1];
    const float* value = (const float*)d_in[2];
    const int*   mask  = (const int*)d_in[3];
    const float* Wq = (const float*)d_in[4];  const float* bq = (const float*)d_in[5];
    const float* Wk = (const float*)d_in[6];  const float* bk = (const float*)d_in[7];
    const float* Wv = (const float*)d_in[8];  const float* bv = (const float*)d_in[9];
    const float* Wo = (const float*)d_in[10]; const float* bo = (const float*)d_in[11];
    float* out = (float*)d_out;

    const int GEMM_SMEM = 8 * 128 * BKP * 2;   // 81920 B
    cudaFuncSetAttribute(proj_qkv_kernel, cudaFuncAttributeMaxDynamicSharedMemorySize, GEMM_SMEM);
    cudaFuncSetAttribute(proj_o_kernel,   cudaFuncAttributeMaxDynamicSharedMemorySize, GEMM_SMEM);
    cudaFuncSetAttribute(flash_kernel,    cudaFuncAttributeMaxDynamicSharedMemorySize, FLASH_SMEM);

    f16 *tqh,*tql,*tkh,*tkl,*tvh,*tvl,*wqh,*wql,*wkh,*wkl,*wvh,*wvl,*woh,*wol;
    f16 *qp,*kp,*vtp,*ch,*cl;
    cudaGetSymbolAddress((void**)&tqh, g_tq_hi); cudaGetSymbolAddress((void**)&tql, g_tq_lo);
    cudaGetSymbolAddress((void**)&tkh, g_tk_hi); cudaGetSymbolAddress((void**)&tkl, g_tk_lo);
    cudaGetSymbolAddress((void**)&tvh, g_tv_hi); cudaGetSymbolAddress((void**)&tvl, g_tv_lo);
    cudaGetSymbolAddress((void**)&wqh, g_wq_hi); cudaGetSymbolAddress((void**)&wql, g_wq_lo);
    cudaGetSymbolAddress((void**)&wkh, g_wk_hi); cudaGetSymbolAddress((void**)&wkl, g_wk_lo);
    cudaGetSymbolAddress((void**)&wvh, g_wv_hi); cudaGetSymbolAddress((void**)&wvl, g_wv_lo);
    cudaGetSymbolAddress((void**)&woh, g_wo_hi); cudaGetSymbolAddress((void**)&wol, g_wo_lo);
    cudaGetSymbolAddress((void**)&qp,  g_q);
    cudaGetSymbolAddress((void**)&kp,  g_k);
    cudaGetSymbolAddress((void**)&vtp, g_vt);
    cudaGetSymbolAddress((void**)&ch,  g_c_hi);  cudaGetSymbolAddress((void**)&cl,  g_c_lo);

    SplitArgs sa;
    sa.src[0] = query; sa.hi[0] = tqh; sa.lo[0] = tql;
    sa.src[1] = key;   sa.hi[1] = tkh; sa.lo[1] = tkl;
    sa.src[2] = value; sa.hi[2] = tvh; sa.lo[2] = tvl;
    sa.src[3] = Wq;    sa.hi[3] = wqh; sa.lo[3] = wql;
    sa.src[4] = Wk;    sa.hi[4] = wkh; sa.lo[4] = wkl;
    sa.src[5] = Wv;    sa.hi[5] = wvh; sa.lo[5] = wvl;
    sa.src[6] = Wo;    sa.hi[6] = woh; sa.lo[6] = wol;
    split_all_kernel<<<3*(NT/256) + 4*(NW/256), 256>>>(sa);

    ProjArgs pa;
    pa.Ah[0] = tqh; pa.Al[0] = tql; pa.Wh[0] = wqh; pa.Wl[0] = wql; pa.bias[0] = bq; pa.Oh[0] = qp;
    pa.Ah[1] = tkh; pa.Al[1] = tkl; pa.Wh[1] = wkh; pa.Wl[1] = wkl; pa.bias[1] = bk; pa.Oh[1] = kp;
    pa.Ah[2] = tvh; pa.Al[2] = tvl; pa.Wh[2] = wvh; pa.Wl[2] = wvl; pa.bias[2] = bv; pa.Oh[2] = vtp;
    proj_qkv_kernel<<<dim3(D_/128, MTOK/128, 3), 256, GEMM_SMEM>>>(pa);

    flash_kernel<<<dim3(S_/64, BH_), 256, FLASH_SMEM>>>(mask);

    proj_o_kernel<<<dim3(D_/128, MTOK/128), 256, GEMM_SMEM>>>(ch, cl, woh, wol, bo, out);
}

// round 15
// speedup vs baseline: 8.0073x; 1.2303x over previous
#include <cuda_runtime.h>
#include <cuda_fp16.h>
#include <stdint.h>

#define B_   2
#define S_   2048
#define D_   1024
#define MTOK 4096
#define BH_  32
#define BKP  40
#define CORRF (64.0f/65.0f)

typedef __half f16;

// ------------------------- scratch -------------------------
__device__ f16 g_tq[MTOK*D_];                       // query fp16
__device__ f16 g_tk[MTOK*D_];
__device__ f16 g_tv[MTOK*D_];
__device__ f16 g_wq[D_*D_], g_wk[D_*D_], g_wv[D_*D_];
__device__ f16 g_wo_hi[D_*D_], g_wo_lo[D_*D_];      // Wo: B-side pair (O-proj 2-pass)
__device__ f16 g_q[MTOK*D_];                        // Q proj fp16, scaled 1/8
__device__ f16 g_k[MTOK*D_];
__device__ f16 g_vt[MTOK*D_];                       // V proj fp16, [bh][d][s]
__device__ f16 g_c_hi[MTOK*D_], g_c_lo[MTOK*D_];    // context: A-side pair

// ------------------------- helpers -------------------------
__device__ __forceinline__ uint32_t sptr(const void* p) {
    return (uint32_t)__cvta_generic_to_shared(p);
}
__device__ __forceinline__ void cp16(void* smem, const void* g) {
    asm volatile("cp.async.cg.shared.global [%0], [%1], 16;\n" :: "r"(sptr(smem)), "l"(g));
}
#define CP_COMMIT asm volatile("cp.async.commit_group;\n")

__device__ __forceinline__ void ldsm4(uint32_t* r, uint32_t a) {
    asm volatile("ldmatrix.sync.aligned.m8n8.x4.shared.b16 {%0,%1,%2,%3}, [%4];\n"
        : "=r"(r[0]), "=r"(r[1]), "=r"(r[2]), "=r"(r[3]) : "r"(a));
}
__device__ __forceinline__ void ldsm2(uint32_t* r, uint32_t a) {
    asm volatile("ldmatrix.sync.aligned.m8n8.x2.shared.b16 {%0,%1}, [%2];\n"
        : "=r"(r[0]), "=r"(r[1]) : "r"(a));
}

__device__ __forceinline__ void mma_f16(float c[4], const uint32_t a[4], const uint32_t b[2])
{
    asm volatile(
        "mma.sync.aligned.m16n8k16.row.col.f32.f16.f16.f32 "
        "{%0,%1,%2,%3}, {%4,%5,%6,%7}, {%8,%9}, {%0,%1,%2,%3};\n"
        : "+f"(c[0]), "+f"(c[1]), "+f"(c[2]), "+f"(c[3])
        : "r"(a[0]), "r"(a[1]), "r"(a[2]), "r"(a[3]), "r"(b[0]), "r"(b[1]));
}

// A-side pair: hi = fp16(v), m = fp16(hi + 64*(v - hi))
__device__ __forceinline__ void store_A(float v, f16* hi, f16* m, size_t i)
{
    __half h = __float2half(v);
    float hf = __half2float(h);
    hi[i] = h;
    m[i] = __float2half(hf + 64.0f*(v - hf));
}
// B-side pair: hi = fp16(v), m = fp16(hi/64 + (v - hi))
__device__ __forceinline__ void store_B(float v, f16* hi, f16* m, size_t i)
{
    __half h = __float2half(v);
    float hf = __half2float(h);
    hi[i] = h;
    m[i] = __float2half(hf*(1.0f/64.0f) + (v - hf));
}

// ------------------------- split (7 tensors, one launch) --------------------
// z 0..5: plain fp16 (q,k,v,Wq,Wk,Wv). z 6: Wo B-side pair.
struct SplitArgs {
    const float* src[7];
    f16* hi[7];
    f16* lo[7];
};
#define NT (MTOK*D_)
#define NW (D_*D_)

__global__ __launch_bounds__(256) void split_all_kernel(SplitArgs a)
{
    int bid = blockIdx.x;
    int z, base;
    if (bid < 3 * (NT/256)) { z = bid / (NT/256); base = (bid % (NT/256)) * 256; }
    else { int r = bid - 3*(NT/256); z = 3 + r / (NW/256); base = (r % (NW/256)) * 256; }
    int i = base + threadIdx.x;
    float v = a.src[z][i];
    if (z < 6) a.hi[z][i] = __float2half(v);
    else       store_B(v, a.hi[z], a.lo[z], i);
}

// ------------------------- 1-pass QKV projection GEMM -----------------------
// C = A @ W^T + bias, plain fp16, 128x128 tile, BK=32 double-buffered.
// smem: 2 planes x 2 bufs x 128*BKP f16 = 40960 B
#define P1_SMEM (4*128*BKP*2)

__device__ __forceinline__ void stage1(f16* d, const f16* S, int r0, int kt, int srow, int sch)
{
    cp16(d +  srow      * BKP + sch, S + (size_t)(r0 + srow)      * D_ + kt + sch);
    cp16(d + (srow + 64) * BKP + sch, S + (size_t)(r0 + srow + 64) * D_ + kt + sch);
}

__global__ __launch_bounds__(256) void proj_qkv_kernel(
    const f16* __restrict__ A0, const f16* __restrict__ W0, const float* __restrict__ b0,
    const f16* __restrict__ A1, const f16* __restrict__ W1, const float* __restrict__ b1,
    const f16* __restrict__ A2, const f16* __restrict__ W2, const float* __restrict__ b2,
    f16* __restrict__ O0, f16* __restrict__ O1, f16* __restrict__ O2)
{
    extern __shared__ f16 sm[];
    #define UA(buf) (sm + (buf) * (128*BKP))
    #define UB(buf) (sm + (2 + (buf)) * (128*BKP))
    const int z = blockIdx.z;
    const f16* A = z == 0 ? A0 : (z == 1 ? A1 : A2);
    const f16* W = z == 0 ? W0 : (z == 1 ? W1 : W2);
    const float* bias = z == 0 ? b0 : (z == 1 ? b1 : b2);
    f16* Oh = z == 0 ? O0 : (z == 1 ? O1 : O2);
    const float scale = z == 0 ? 0.125f : 1.0f;

    const int tid = threadIdx.x, lane = tid & 31, wid = tid >> 5;
    const int g = lane >> 2, t = lane & 3;
    const int wm = (wid >> 2) * 64, wn = (wid & 3) * 32;
    const int m0 = blockIdx.y * 128, n0 = blockIdx.x * 128;
    const int srow = tid >> 2, sch = (tid & 3) * 8;
    const uint32_t aoff = (uint32_t)((lane & 15) * BKP * 2 + (lane >> 4) * 16);
    const uint32_t boff = (uint32_t)((lane & 7) * BKP * 2 + ((lane >> 3) & 1) * 16);

    float acc[4][4][4] = {};
    stage1(UA(0), A, m0, 0, srow, sch);
    stage1(UB(0), W, n0, 0, srow, sch);
    CP_COMMIT;

    for (int kt = 0; kt < D_; kt += 32) {
        const int cur = (kt >> 5) & 1;
        asm volatile("cp.async.wait_group 0;\n");
        __syncthreads();
        if (kt + 32 < D_) {
            stage1(UA(cur^1), A, m0, kt + 32, srow, sch);
            stage1(UB(cur^1), W, n0, kt + 32, srow, sch);
            CP_COMMIT;
        }
        const uint32_t ab = sptr(UA(cur)), bb = sptr(UB(cur));
        #pragma unroll
        for (int kk = 0; kk < 32; kk += 16) {
            uint32_t aH[4][4], bH[4][2];
            #pragma unroll
            for (int mt = 0; mt < 4; ++mt)
                ldsm4(aH[mt], ab + (uint32_t)(((wm + mt*16)*BKP + kk) * 2) + aoff);
            #pragma unroll
            for (int nt = 0; nt < 4; ++nt)
                ldsm2(bH[nt], bb + (uint32_t)(((wn + nt*8)*BKP + kk) * 2) + boff);
            #pragma unroll
            for (int mt = 0; mt < 4; ++mt)
                #pragma unroll
                for (int nt = 0; nt < 4; ++nt)
                    mma_f16(acc[mt][nt], aH[mt], bH[nt]);
        }
        __syncthreads();
    }

    #pragma unroll
    for (int mt = 0; mt < 4; ++mt) {
        int row0 = m0 + wm + mt*16 + g;
        #pragma unroll
        for (int nt = 0; nt < 4; ++nt) {
            int col = n0 + wn + nt*8 + 2*t;
            float v[4];
            v[0] = (acc[mt][nt][0] + bias[col])   * scale;
            v[1] = (acc[mt][nt][1] + bias[col+1]) * scale;
            v[2] = (acc[mt][nt][2] + bias[col])   * scale;
            v[3] = (acc[mt][nt][3] + bias[col+1]) * scale;
            if (z != 2) {
                size_t i0 = (size_t)row0 * D_ + col, i1 = (size_t)(row0+8) * D_ + col;
                __half2 a01 = __floats2half2_rn(v[0], v[1]);
                __half2 a23 = __floats2half2_rn(v[2], v[3]);
                *(uint32_t*)(Oh + i0) = *(uint32_t*)&a01;
                *(uint32_t*)(Oh + i1) = *(uint32_t*)&a23;
            } else {  // V transposed: [bh][d][s]
                #pragma unroll
                for (int e = 0; e < 4; ++e) {
                    int row = row0 + (e >> 1) * 8, c = col + (e & 1);
                    size_t i = (((size_t)(row >> 11) * 16 + (c >> 6)) * 64 + (c & 63)) * S_
                             + (row & (S_-1));
                    Oh[i] = __float2half(v[e]);
                }
            }
        }
    }
    #undef UA
    #undef UB
}

// ------------------------- 2-pass O projection ------------------------------
// smem: 4 planes x 2 bufs = 81920 B
#define GEMM_SMEM (8*128*BKP*2)

__device__ __forceinline__ void stage128(f16* dh, f16* dl,
    const f16* Sh, const f16* Sl, int r0, int kt, int srow, int sch)
{
    size_t a0 = (size_t)(r0 + srow)      * D_ + kt + sch;
    size_t a1 = (size_t)(r0 + srow + 64) * D_ + kt + sch;
    cp16(dh +  srow      * BKP + sch, Sh + a0);
    cp16(dh + (srow + 64) * BKP + sch, Sh + a1);
    cp16(dl +  srow      * BKP + sch, Sl + a0);
    cp16(dl + (srow + 64) * BKP + sch, Sl + a1);
}

__global__ __launch_bounds__(256) void proj_o_kernel(
    const f16* __restrict__ Ahi, const f16* __restrict__ Alo,
    const f16* __restrict__ Whi, const f16* __restrict__ Wlo,
    const float* __restrict__ bias, float* __restrict__ Of)
{
    extern __shared__ f16 sm[];
    #define TA(buf,hl) (sm + ((buf)*2 + (hl)) * (128*BKP))
    #define TB(buf,hl) (sm + (4 + (buf)*2 + (hl)) * (128*BKP))
    const int tid = threadIdx.x, lane = tid & 31, wid = tid >> 5;
    const int g = lane >> 2, t = lane & 3;
    const int wm = (wid >> 2) * 64, wn = (wid & 3) * 32;
    const int m0 = blockIdx.y * 128, n0 = blockIdx.x * 128;
    const int srow = tid >> 2, sch = (tid & 3) * 8;
    const uint32_t aoff = (uint32_t)((lane & 15) * BKP * 2 + (lane >> 4) * 16);
    const uint32_t boff = (uint32_t)((lane & 7) * BKP * 2 + ((lane >> 3) & 1) * 16);

    float acc[4][4][4] = {};
    stage128(TA(0,0), TA(0,1), Ahi, Alo, m0, 0, srow, sch);
    stage128(TB(0,0), TB(0,1), Whi, Wlo, n0, 0, srow, sch);
    CP_COMMIT;

    for (int kt = 0; kt < D_; kt += 32) {
        const int cur = (kt >> 5) & 1;
        asm volatile("cp.async.wait_group 0;\n");
        __syncthreads();
        if (kt + 32 < D_) {
            stage128(TA(cur^1,0), TA(cur^1,1), Ahi, Alo, m0, kt + 32, srow, sch);
            stage128(TB(cur^1,0), TB(cur^1,1), Whi, Wlo, n0, kt + 32, srow, sch);
            CP_COMMIT;
        }
        const uint32_t ah = sptr(TA(cur,0)), am = sptr(TA(cur,1));
        const uint32_t bh = sptr(TB(cur,0)), bm = sptr(TB(cur,1));
        #pragma unroll
        for (int kk = 0; kk < 32; kk += 16) {
            uint32_t aH[4][4], aM[4][4], bH[4][2], bM[4][2];
            #pragma unroll
            for (int mt = 0; mt < 4; ++mt) {
                uint32_t base = (uint32_t)(((wm + mt*16)*BKP + kk) * 2);
                ldsm4(aH[mt], ah + base + aoff);
                ldsm4(aM[mt], am + base + aoff);
            }
            #pragma unroll
            for (int nt = 0; nt < 4; ++nt) {
                uint32_t base = (uint32_t)(((wn + nt*8)*BKP + kk) * 2);
                ldsm2(bH[nt], bh + base + boff);
                ldsm2(bM[nt], bm + base + boff);
            }
            #pragma unroll
            for (int mt = 0; mt < 4; ++mt)
                #pragma unroll
                for (int nt = 0; nt < 4; ++nt) {
                    mma_f16(acc[mt][nt], aH[mt], bH[nt]);
                    mma_f16(acc[mt][nt], aM[mt], bM[nt]);
                }
        }
        __syncthreads();
    }

    #pragma unroll
    for (int mt = 0; mt < 4; ++mt) {
        int row0 = m0 + wm + mt*16 + g;
        #pragma unroll
        for (int nt = 0; nt < 4; ++nt) {
            int col = n0 + wn + nt*8 + 2*t;
            size_t i0 = (size_t)row0 * D_ + col, i1 = (size_t)(row0+8) * D_ + col;
            Of[i0]   = acc[mt][nt][0]*CORRF + bias[col];
            Of[i0+1] = acc[mt][nt][1]*CORRF + bias[col+1];
            Of[i1]   = acc[mt][nt][2]*CORRF + bias[col];
            Of[i1+1] = acc[mt][nt][3]*CORRF + bias[col+1];
        }
    }
    #undef TA
    #undef TB
}

// ------------------------- flash attention (2 CTAs/SM, 1-pass QK+PV) --------
// smem: Qs 9216 | Ks 18432 | Vs 18432 | Ms 8192 = 54272 bytes
#define KCH  64
#define KPL  (64*72)
#define FLASH_SMEM 54272

__global__ __launch_bounds__(256, 2) void flash_kernel(const int* __restrict__ mask)
{
    extern __shared__ char smc[];
    f16* Qs = (f16*)smc;                   // [64][72]
    f16* Ks = (f16*)(smc + 9216);          // [buf][64][72]
    f16* Vs = (f16*)(smc + 27648);         // [buf][64][72]
    int* Ms = (int*)(smc + 46080);         // [2048]
    float* red   = (float*)smc;            // [64][68] (post-loop reuse)
    float* lpart = (float*)(smc + 18432);  // [64]

    const int bh = blockIdx.y, b = bh >> 4, h = bh & 15;
    const int q0 = blockIdx.x * 64;
    const int tid = threadIdx.x, lane = tid & 31, wid = tid >> 5;
    const int g = lane >> 2, t = lane & 3;
    const int mg = wid >> 1;
    const int j  = wid & 1;
    const int wn = j * 32;

    const int kr = tid >> 2, kc = (tid & 3) * 16;

    const uint32_t aoff72 = (uint32_t)((lane & 15) * 144 + (lane >> 4) * 16);
    const uint32_t boff72 = (uint32_t)((lane & 7) * 144 + ((lane >> 3) & 1) * 16);
    const uint32_t qs_base = sptr(Qs);

    {
        size_t gq = ((size_t)(b*S_ + q0 + kr))*D_ + h*64 + kc;
        cp16(Qs + kr*72 + kc,     g_q + gq);
        cp16(Qs + kr*72 + kc + 8, g_q + gq + 8);
        size_t gk = ((size_t)(b*S_ + kr))*D_ + h*64 + kc;
        cp16(Ks + kr*72 + kc,     g_k + gk);
        cp16(Ks + kr*72 + kc + 8, g_k + gk + 8);
        size_t gv = ((size_t)(bh*64 + kr))*S_ + kc;
        cp16(Vs + kr*72 + kc,     g_vt + gv);
        cp16(Vs + kr*72 + kc + 8, g_vt + gv + 8);
        cp16(Ms + tid*8,     mask + b*S_ + tid*8);
        cp16(Ms + tid*8 + 4, mask + b*S_ + tid*8 + 4);
        CP_COMMIT;
    }

    float acc_o[8][4] = {};
    float ls[2] = {};

    for (int it = 0; it < 32; ++it) {
        const int cur = it & 1;
        if (it < 31) {
            size_t gk = ((size_t)(b*S_ + (it+1)*KCH + kr))*D_ + h*64 + kc;
            f16* dk = Ks + (cur^1)*KPL + kr*72 + kc;
            cp16(dk,     g_k + gk);
            cp16(dk + 8, g_k + gk + 8);
            size_t gv = ((size_t)(bh*64 + kr))*S_ + (it+1)*KCH + kc;
            f16* dv = Vs + (cur^1)*KPL + kr*72 + kc;
            cp16(dv,     g_vt + gv);
            cp16(dv + 8, g_vt + gv + 8);
            CP_COMMIT;
            asm volatile("cp.async.wait_group 1;\n");
        } else {
            asm volatile("cp.async.wait_group 0;\n");
        }
        __syncthreads();

        // ---- scores: Q[16q x 64dk] . K_slice[32k x 64dk]^T ----
        float accs[4][4] = {};
        const uint32_t kb = sptr(Ks + cur*KPL);
        #pragma unroll
        for (int kk = 0; kk < 64; kk += 16) {
            uint32_t aH[4], bHf[4][2];
            uint32_t abase = (uint32_t)(((mg*16)*72 + kk) * 2);
            ldsm4(aH, qs_base + abase + aoff72);
            #pragma unroll
            for (int nt = 0; nt < 4; ++nt) {
                uint32_t base = (uint32_t)(((wn + nt*8)*72 + kk) * 2);
                ldsm2(bHf[nt], kb + base + boff72);
            }
            #pragma unroll
            for (int nt = 0; nt < 4; ++nt)
                mma_f16(accs[nt], aH, bHf[nt]);
        }

        // ---- mask + exp + pack P ----
        uint32_t pP[2][4];
        #pragma unroll
        for (int nt = 0; nt < 4; ++nt) {
            int c0 = it*KCH + wn + nt*8 + 2*t;
            bool m0 = Ms[c0] != 0, m1 = Ms[c0+1] != 0;
            float p0 = m0 ? __expf(accs[nt][0]) : 0.f;
            float p1 = m1 ? __expf(accs[nt][1]) : 0.f;
            float p2 = m0 ? __expf(accs[nt][2]) : 0.f;
            float p3 = m1 ? __expf(accs[nt][3]) : 0.f;
            ls[0] += p0 + p1;
            ls[1] += p2 + p3;
            int jj = nt >> 1, hf = (nt & 1) * 2;
            __half2 h01 = __floats2half2_rn(p0, p1);
            __half2 h23 = __floats2half2_rn(p2, p3);
            pP[jj][hf]   = *(uint32_t*)&h01;
            pP[jj][hf+1] = *(uint32_t*)&h23;
        }

        // ---- P_slice[16q x 32k] . V_slice[32k x 64d] ----
        const uint32_t vb = sptr(Vs + cur*KPL);
        #pragma unroll
        for (int jj = 0; jj < 2; ++jj) {
            uint32_t bHf[8][2];
            #pragma unroll
            for (int dt = 0; dt < 8; ++dt) {
                uint32_t base = (uint32_t)(((dt*8)*72 + wn + jj*16) * 2);
                ldsm2(bHf[dt], vb + base + boff72);
            }
            #pragma unroll
            for (int dt = 0; dt < 8; ++dt)
                mma_f16(acc_o[dt], pP[jj], bHf[dt]);
        }
        __syncthreads();
    }

    // ---- cross-slice reduction ----
    const int r0 = mg*16 + g;
    float s0 = ls[0], s1 = ls[1];
    s0 += __shfl_xor_sync(~0u, s0, 1);  s0 += __shfl_xor_sync(~0u, s0, 2);
    s1 += __shfl_xor_sync(~0u, s1, 1);  s1 += __shfl_xor_sync(~0u, s1, 2);

    #pragma unroll
    for (int round = 0; round < 2; ++round) {
        if (j == round) {
            #pragma unroll
            for (int dt = 0; dt < 8; ++dt) {
                int c = dt*8 + 2*t;
                if (round == 0) {
                    red[r0*68 + c]       = acc_o[dt][0];
                    red[r0*68 + c + 1]   = acc_o[dt][1];
                    red[(r0+8)*68 + c]   = acc_o[dt][2];
                    red[(r0+8)*68 + c+1] = acc_o[dt][3];
                } else {
                    red[r0*68 + c]       += acc_o[dt][0];
                    red[r0*68 + c + 1]   += acc_o[dt][1];
                    red[(r0+8)*68 + c]   += acc_o[dt][2];
                    red[(r0+8)*68 + c+1] += acc_o[dt][3];
                }
            }
            if (t == 0) {
                if (round == 0) { lpart[r0] = s0;  lpart[r0+8] = s1; }
                else            { lpart[r0] += s0; lpart[r0+8] += s1; }
            }
        }
        __syncthreads();
    }

    #pragma unroll
    for (int i = 0; i < 16; ++i) {
        int e = i*256 + tid;
        int row = e >> 6, col = e & 63;
        float v = red[row*68 + col] / lpart[row];
        size_t o = ((size_t)(b*S_ + q0 + row))*D_ + h*64 + col;
        store_A(v, g_c_hi, g_c_lo, o);
    }
}

// ------------------------- launch -------------------------
extern "C" void kernel_launch(void* const* d_in, const int* in_sizes, int n_in,
                              void* d_out, int out_size)
{
    const float* query = (const float*)d_in[0];
    const float* key   = (const float*)d_in[1];
    const float* value = (const float*)d_in[2];
    const int*   mask  = (const int*)d_in[3];
    const float* Wq = (const float*)d_in[4];  const float* bq = (const float*)d_in[5];
    const float* Wk = (const float*)d_in[6];  const float* bk = (const float*)d_in[7];
    const float* Wv = (const float*)d_in[8];  const float* bv = (const float*)d_in[9];
    const float* Wo = (const float*)d_in[10]; const float* bo = (const float*)d_in[11];
    float* out = (float*)d_out;

    cudaFuncSetAttribute(proj_qkv_kernel, cudaFuncAttributeMaxDynamicSharedMemorySize, P1_SMEM);
    cudaFuncSetAttribute(proj_o_kernel,   cudaFuncAttributeMaxDynamicSharedMemorySize, GEMM_SMEM);
    cudaFuncSetAttribute(flash_kernel,    cudaFuncAttributeMaxDynamicSharedMemorySize, FLASH_SMEM);

    f16 *tq,*tk,*tv,*wq,*wk,*wv,*woh,*wol,*qp,*kp,*vtp,*ch,*cl;
    cudaGetSymbolAddress((void**)&tq,  g_tq);
    cudaGetSymbolAddress((void**)&tk,  g_tk);
    cudaGetSymbolAddress((void**)&tv,  g_tv);
    cudaGetSymbolAddress((void**)&wq,  g_wq);
    cudaGetSymbolAddress((void**)&wk,  g_wk);
    cudaGetSymbolAddress((void**)&wv,  g_wv);
    cudaGetSymbolAddress((void**)&woh, g_wo_hi);
    cudaGetSymbolAddress((void**)&wol, g_wo_lo);
    cudaGetSymbolAddress((void**)&qp,  g_q);
    cudaGetSymbolAddress((void**)&kp,  g_k);
    cudaGetSymbolAddress((void**)&vtp, g_vt);
    cudaGetSymbolAddress((void**)&ch,  g_c_hi);
    cudaGetSymbolAddress((void**)&cl,  g_c_lo);

    SplitArgs sa;
    sa.src[0] = query; sa.hi[0] = tq;  sa.lo[0] = nullptr;
    sa.src[1] = key;   sa.hi[1] = tk;  sa.lo[1] = nullptr;
    sa.src[2] = value; sa.hi[2] = tv;  sa.lo[2] = nullptr;
    sa.src[3] = Wq;    sa.hi[3] = wq;  sa.lo[3] = nullptr;
    sa.src[4] = Wk;    sa.hi[4] = wk;  sa.lo[4] = nullptr;
    sa.src[5] = Wv;    sa.hi[5] = wv;  sa.lo[5] = nullptr;
    sa.src[6] = Wo;    sa.hi[6] = woh; sa.lo[6] = wol;
    split_all_kernel<<<3*(NT/256) + 4*(NW/256), 256>>>(sa);

    proj_qkv_kernel<<<dim3(D_/128, MTOK/128, 3), 256, P1_SMEM>>>(
        tq, wq, bq, tk, wk, bk, tv, wv, bv, qp, kp, vtp);

    flash_kernel<<<dim3(S_/64, BH_), 256, FLASH_SMEM>>>(mask);

    proj_o_kernel<<<dim3(D_/128, MTOK/128), 256, GEMM_SMEM>>>(ch, cl, woh, wol, bo, out);
}